// round 4
// baseline (speedup 1.0000x reference)
#include <cuda_runtime.h>
#include <cuda_bf16.h>
#include <math.h>

// ---------------------------------------------------------------------------
// T6Attention — fp32 pipeline, round 2
// B=2, S=2048, D_MODEL=1024, HEADS=16, DK=64, Q_RANK=6, RANK=2
// ---------------------------------------------------------------------------

#define BATCH     2
#define SEQ       2048
#define DMODEL    1024
#define HEADS     16
#define DK        64
#define QRANK     6
#define RANK      2
#define NTOK      (BATCH*SEQ)        // 4096
#define BH        (BATCH*HEADS)      // 32

// scratch offsets (floats)
#define OFF_AQ   0
#define SZ_AQ    (NTOK*HEADS*QRANK)
#define OFF_AK   (OFF_AQ+SZ_AQ)
#define SZ_AK    (NTOK*HEADS*RANK)
#define OFF_AV   (OFF_AK+SZ_AK)
#define SZ_AV    SZ_AK
#define OFF_BQ   (OFF_AV+SZ_AV)
#define SZ_BQ    (NTOK*QRANK*DK)
#define OFF_BK   (OFF_BQ+SZ_BQ)
#define SZ_BK    (NTOK*RANK*DK)
#define OFF_BV   (OFF_BK+SZ_BK)
#define SZ_BV    SZ_BK
#define OFF_QH   (OFF_BV+SZ_BV)
#define SZ_QH    (BH*SEQ*DK)
#define OFF_KH   (OFF_QH+SZ_QH)
#define OFF_VH   (OFF_KH+SZ_QH)
#define OFF_OA   (OFF_VH+SZ_QH)
#define SCRATCH_TOTAL (OFF_OA+SZ_QH)

__device__ float g_scratch[SCRATCH_TOTAL];

// ---------------------------------------------------------------------------
// Tiled SGEMM: C[M,N] = A[M,K] @ W[K,N], row-major. M%128==0, K%16==0, N%4==0.
// BM=128, BN template (128 or 64), BK=16, 256 threads, thread tile 8 x TN.
// ---------------------------------------------------------------------------
template<int BN, int TN>
__global__ __launch_bounds__(256) void gemm_kernel(
    const float* __restrict__ A, const float* __restrict__ W,
    float* __restrict__ C, int M, int N, int K)
{
    __shared__ float As[16][132];     // padded; row start stays 16B-aligned
    __shared__ float Ws[16][BN];

    const int tid = threadIdx.x;
    const int tm = (tid & 15) * 8;
    const int tn = (tid >> 4) * TN;
    const int m0 = blockIdx.y * 128;
    const int n0 = blockIdx.x * BN;

    float acc[8][TN];
#pragma unroll
    for (int i = 0; i < 8; i++)
#pragma unroll
        for (int j = 0; j < TN; j++) acc[i][j] = 0.f;

    for (int k0 = 0; k0 < K; k0 += 16) {
        // A tile: 128 rows x 16 cols = 512 float4, 2 per thread (transpose to k-major)
#pragma unroll
        for (int i = 0; i < 2; i++) {
            int idx = tid + i * 256;
            int r  = idx >> 2;
            int c4 = (idx & 3) * 4;
            float4 a = *reinterpret_cast<const float4*>(
                A + (size_t)(m0 + r) * K + k0 + c4);
            As[c4 + 0][r] = a.x;
            As[c4 + 1][r] = a.y;
            As[c4 + 2][r] = a.z;
            As[c4 + 3][r] = a.w;
        }
        // W tile: 16 rows x BN cols
#pragma unroll
        for (int i = 0; i < (16 * BN / 4) / 256; i++) {
            int idx = tid + i * 256;
            int r  = idx / (BN / 4);
            int c4 = (idx % (BN / 4)) * 4;
            int gn = n0 + c4;
            float4 w = (gn < N)
                ? *reinterpret_cast<const float4*>(W + (size_t)(k0 + r) * N + gn)
                : make_float4(0.f, 0.f, 0.f, 0.f);
            *reinterpret_cast<float4*>(&Ws[r][c4]) = w;
        }
        __syncthreads();

#pragma unroll
        for (int kk = 0; kk < 16; kk++) {
            float af[8], bf[TN];
            *reinterpret_cast<float4*>(&af[0]) = *reinterpret_cast<float4*>(&As[kk][tm]);
            *reinterpret_cast<float4*>(&af[4]) = *reinterpret_cast<float4*>(&As[kk][tm + 4]);
#pragma unroll
            for (int j4 = 0; j4 < TN / 4; j4++)
                *reinterpret_cast<float4*>(&bf[j4 * 4]) =
                    *reinterpret_cast<float4*>(&Ws[kk][tn + j4 * 4]);
#pragma unroll
            for (int i = 0; i < 8; i++)
#pragma unroll
                for (int j = 0; j < TN; j++) acc[i][j] += af[i] * bf[j];
        }
        __syncthreads();
    }

#pragma unroll
    for (int i = 0; i < 8; i++) {
        int gm = m0 + tm + i;
#pragma unroll
        for (int j4 = 0; j4 < TN / 4; j4++) {
            int gn = n0 + tn + j4 * 4;
            if (gn < N) {
                *reinterpret_cast<float4*>(&C[(size_t)gm * N + gn]) =
                    make_float4(acc[i][j4 * 4], acc[i][j4 * 4 + 1],
                                acc[i][j4 * 4 + 2], acc[i][j4 * 4 + 3]);
            }
        }
    }
}

// ---------------------------------------------------------------------------
// RoPE in-place on X[NTOK][R][DK]
// ---------------------------------------------------------------------------
__global__ void rope_kernel(float* __restrict__ X, int R, int total)
{
    int idx = blockIdx.x * blockDim.x + threadIdx.x;
    if (idx >= total) return;
    int i = idx & 31;
    int r = (idx >> 5) % R;
    int t = idx / (32 * R);
    int s = t & (SEQ - 1);

    float inv_freq = powf(10000.0f, -(float)(2 * i) / 64.0f);
    float fr = (float)s * inv_freq;
    float sn, cs;
    sincosf(fr, &sn, &cs);

    float* base = X + ((size_t)t * R + r) * DK;
    float x1 = base[i];
    float x2 = base[32 + i];
    base[i]      = x1 * cs + x2 * sn;
    base[32 + i] = -x1 * sn + x2 * cs;
}

// ---------------------------------------------------------------------------
// Rank contraction: out[(b*H+h)][s][d] = scale * sum_r A[t][h*R+r]*Bm[t][r*DK+d]
// ---------------------------------------------------------------------------
__global__ void contract_kernel(const float* __restrict__ Am,
                                const float* __restrict__ Bm,
                                float* __restrict__ out, int R, float scale)
{
    int idx = blockIdx.x * blockDim.x + threadIdx.x;
    if (idx >= NTOK * HEADS * DK) return;
    int d = idx & (DK - 1);
    int h = (idx >> 6) & (HEADS - 1);
    int t = idx >> 10;

    const float* a = Am + (size_t)t * (HEADS * R) + h * R;
    const float* b = Bm + (size_t)t * R * DK + d;
    float s = 0.f;
#pragma unroll 6
    for (int r = 0; r < R; r++) s += a[r] * b[r * DK];

    int bb = t >> 11;
    int ss = t & (SEQ - 1);
    out[(((size_t)(bb * HEADS + h)) * SEQ + ss) * DK + d] = s * scale;
}

// ---------------------------------------------------------------------------
// Causal flash attention, pair-split queries.
// grid (SEQ/64, BH), 128 threads. Thread pair (2q, 2q+1) owns query qt*64+q;
// thread handles 32 of the 64 head dims; dot halves combined via shfl_xor(1).
// ---------------------------------------------------------------------------
__global__ __launch_bounds__(128) void flash_kernel(
    const float* __restrict__ Qh, const float* __restrict__ Kh,
    const float* __restrict__ Vh, float* __restrict__ O)
{
    const int bh = blockIdx.y;
    const int qt = blockIdx.x;
    const int tid = threadIdx.x;
    const int q = tid >> 1;
    const int half = tid & 1;
    const int qrow = qt * 64 + q;

    __shared__ float4 Ks4[64][16];
    __shared__ float4 Vs4[64][16];

    float qreg[32];
    {
        const float4* qp4 = reinterpret_cast<const float4*>(
            Qh + ((size_t)bh * SEQ + qrow) * DK) + half * 8;
        const float inv_dk = 1.0f / (float)DK;
#pragma unroll
        for (int d4 = 0; d4 < 8; d4++) {
            float4 qq = qp4[d4];
            qreg[4 * d4 + 0] = qq.x * inv_dk;
            qreg[4 * d4 + 1] = qq.y * inv_dk;
            qreg[4 * d4 + 2] = qq.z * inv_dk;
            qreg[4 * d4 + 3] = qq.w * inv_dk;
        }
    }

    float4 acc4[8];
#pragma unroll
    for (int d4 = 0; d4 < 8; d4++) acc4[d4] = make_float4(0.f, 0.f, 0.f, 0.f);
    float m = -INFINITY, l = 0.f;

    for (int kt = 0; kt <= qt; kt++) {
        __syncthreads();
        const float4* kb4 = reinterpret_cast<const float4*>(
            Kh + ((size_t)bh * SEQ + kt * 64) * DK);
        const float4* vb4 = reinterpret_cast<const float4*>(
            Vh + ((size_t)bh * SEQ + kt * 64) * DK);
#pragma unroll
        for (int i = 0; i < 8; i++) {
            int idx = i * 128 + tid;
            Ks4[idx >> 4][idx & 15] = kb4[idx];
            Vs4[idx >> 4][idx & 15] = vb4[idx];
        }
        __syncthreads();

        const int kg0 = kt * 64;
#pragma unroll
        for (int c = 0; c < 4; c++) {
            float p[16];
            float mloc = -INFINITY;
#pragma unroll
            for (int j = 0; j < 16; j++) {
                const int jj = c * 16 + j;
                const float4* kp = &Ks4[jj][half * 8];
                float a0 = 0.f, a1 = 0.f, a2 = 0.f, a3 = 0.f;
#pragma unroll
                for (int d4 = 0; d4 < 8; d4++) {
                    float4 kk4 = kp[d4];
                    a0 += qreg[4 * d4 + 0] * kk4.x;
                    a1 += qreg[4 * d4 + 1] * kk4.y;
                    a2 += qreg[4 * d4 + 2] * kk4.z;
                    a3 += qreg[4 * d4 + 3] * kk4.w;
                }
                float s = (a0 + a1) + (a2 + a3);
                s += __shfl_xor_sync(0xffffffffu, s, 1);   // combine halves
                if (kg0 + jj > qrow) s = -INFINITY;
                p[j] = s;
                mloc = fmaxf(mloc, s);
            }
            float m_new = fmaxf(m, mloc);
            float factor = __expf(m - m_new);
            float psum = 0.f;
#pragma unroll
            for (int j = 0; j < 16; j++) {
                p[j] = __expf(p[j] - m_new);
                psum += p[j];
            }
            l = l * factor + psum;
            m = m_new;
#pragma unroll
            for (int d4 = 0; d4 < 8; d4++) {
                acc4[d4].x *= factor; acc4[d4].y *= factor;
                acc4[d4].z *= factor; acc4[d4].w *= factor;
            }
#pragma unroll
            for (int j = 0; j < 16; j++) {
                const float pj = p[j];
                const float4* vp = &Vs4[c * 16 + j][half * 8];
#pragma unroll
                for (int d4 = 0; d4 < 8; d4++) {
                    float4 vv = vp[d4];
                    acc4[d4].x += pj * vv.x;
                    acc4[d4].y += pj * vv.y;
                    acc4[d4].z += pj * vv.z;
                    acc4[d4].w += pj * vv.w;
                }
            }
        }
    }

    const int b = bh >> 4;
    const int h = bh & 15;
    const float inv_l = 1.0f / l;
    float4* op4 = reinterpret_cast<float4*>(
        O + ((size_t)(b * SEQ) + qrow) * DMODEL + h * DK + half * 32);
#pragma unroll
    for (int d4 = 0; d4 < 8; d4++) {
        float4 a = acc4[d4];
        op4[d4] = make_float4(a.x * inv_l, a.y * inv_l, a.z * inv_l, a.w * inv_l);
    }
}

// ---------------------------------------------------------------------------
extern "C" void kernel_launch(void* const* d_in, const int* in_sizes, int n_in,
                              void* d_out, int out_size)
{
    const float* q    = (const float*)d_in[0];
    const float* k    = (const float*)d_in[1];
    const float* v    = (const float*)d_in[2];
    const float* W_Aq = (const float*)d_in[4];
    const float* W_Ak = (const float*)d_in[5];
    const float* W_Av = (const float*)d_in[6];
    const float* W_Bq = (const float*)d_in[7];
    const float* W_Bk = (const float*)d_in[8];
    const float* W_Bv = (const float*)d_in[9];
    const float* Wo   = (const float*)d_in[10];
    float* out = (float*)d_out;

    float* scratch = nullptr;
    cudaGetSymbolAddress((void**)&scratch, g_scratch);
    float* sAq = scratch + OFF_AQ;
    float* sAk = scratch + OFF_AK;
    float* sAv = scratch + OFF_AV;
    float* sBq = scratch + OFF_BQ;
    float* sBk = scratch + OFF_BK;
    float* sBv = scratch + OFF_BV;
    float* sQh = scratch + OFF_QH;
    float* sKh = scratch + OFF_KH;
    float* sVh = scratch + OFF_VH;
    float* sOa = scratch + OFF_OA;

    const int MY = NTOK / 128;   // 32 row-blocks

    // 1) projections
    gemm_kernel<64, 4><<<dim3(2, MY), 256>>>(q, W_Aq, sAq, NTOK, 96, DMODEL);
    gemm_kernel<64, 4><<<dim3(1, MY), 256>>>(k, W_Ak, sAk, NTOK, 32, DMODEL);
    gemm_kernel<64, 4><<<dim3(1, MY), 256>>>(v, W_Av, sAv, NTOK, 32, DMODEL);
    gemm_kernel<128, 8><<<dim3(3, MY), 256>>>(q, W_Bq, sBq, NTOK, 384, DMODEL);
    gemm_kernel<128, 8><<<dim3(1, MY), 256>>>(k, W_Bk, sBk, NTOK, 128, DMODEL);
    gemm_kernel<128, 8><<<dim3(1, MY), 256>>>(v, W_Bv, sBv, NTOK, 128, DMODEL);

    // 2) RoPE
    {
        int total_q = NTOK * QRANK * 32;
        int total_k = NTOK * RANK * 32;
        rope_kernel<<<(total_q + 255) / 256, 256>>>(sBq, QRANK, total_q);
        rope_kernel<<<(total_k + 255) / 256, 256>>>(sBk, RANK, total_k);
    }

    // 3) rank contractions
    {
        int total = NTOK * HEADS * DK;
        contract_kernel<<<(total + 255) / 256, 256>>>(sAq, sBq, sQh, QRANK, 1.0f / QRANK);
        contract_kernel<<<(total + 255) / 256, 256>>>(sAk, sBk, sKh, RANK, 1.0f / RANK);
        contract_kernel<<<(total + 255) / 256, 256>>>(sAv, sBv, sVh, RANK, 1.0f / RANK);
    }

    // 4) causal flash attention
    flash_kernel<<<dim3(SEQ / 64, BH), 128>>>(sQh, sKh, sVh, sOa);

    // 5) output projection
    gemm_kernel<128, 8><<<dim3(DMODEL / 128, MY), 256>>>(sOa, Wo, out, NTOK, DMODEL, DMODEL);
}

// round 5
// speedup vs baseline: 1.0296x; 1.0296x over previous
#include <cuda_runtime.h>
#include <cuda_bf16.h>
#include <math.h>

// ---------------------------------------------------------------------------
// T6Attention — fp32 pipeline, round 3
// B=2, S=2048, D_MODEL=1024, HEADS=16, DK=64, Q_RANK=6, RANK=2
// ---------------------------------------------------------------------------

#define BATCH     2
#define SEQ       2048
#define DMODEL    1024
#define HEADS     16
#define DK        64
#define QRANK     6
#define RANK      2
#define NTOK      (BATCH*SEQ)        // 4096
#define BH        (BATCH*HEADS)      // 32

// scratch offsets (floats)
#define OFF_AQ   0
#define SZ_AQ    (NTOK*HEADS*QRANK)
#define OFF_AK   (OFF_AQ+SZ_AQ)
#define SZ_AK    (NTOK*HEADS*RANK)
#define OFF_AV   (OFF_AK+SZ_AK)
#define SZ_AV    SZ_AK
#define OFF_BQ   (OFF_AV+SZ_AV)
#define SZ_BQ    (NTOK*QRANK*DK)
#define OFF_BK   (OFF_BQ+SZ_BQ)
#define SZ_BK    (NTOK*RANK*DK)
#define OFF_BV   (OFF_BK+SZ_BK)
#define SZ_BV    SZ_BK
#define OFF_QH   (OFF_BV+SZ_BV)
#define SZ_QH    (BH*SEQ*DK)
#define OFF_KH   (OFF_QH+SZ_QH)
#define OFF_VH   (OFF_KH+SZ_QH)
#define OFF_OA   (OFF_VH+SZ_QH)
#define SCRATCH_TOTAL (OFF_OA+SZ_QH)

__device__ float g_scratch[SCRATCH_TOTAL];

// ---------------------------------------------------------------------------
// Tiled SGEMM with register double-buffering.
// C[M,N] = A[M,K] @ W[K,N], row-major. M%128==0, K%16==0, N%4==0.
// BM=128, BN in {64,128}, BK=16, 256 threads, thread tile 8 x TN.
// BATCH3: if nonzero, blockIdx.z in {0,1,2} selects (A,W,C,N) from arrays.
// ---------------------------------------------------------------------------
template<int BN, int TN, int BATCH3>
__global__ __launch_bounds__(256) void gemm_kernel(
    const float* __restrict__ A0, const float* __restrict__ W0, float* __restrict__ C0, int N0,
    const float* __restrict__ A1, const float* __restrict__ W1, float* __restrict__ C1, int N1,
    const float* __restrict__ A2, const float* __restrict__ W2, float* __restrict__ C2, int N2,
    int M, int K)
{
    const float* A = A0; const float* W = W0; float* C = C0; int N = N0;
    if (BATCH3) {
        int z = blockIdx.z;
        if (z == 1) { A = A1; W = W1; C = C1; N = N1; }
        else if (z == 2) { A = A2; W = W2; C = C2; N = N2; }
    }

    __shared__ float As[16][132];     // k-major, padded
    __shared__ float Ws[16][BN];

    const int tid = threadIdx.x;
    const int tm = (tid & 15) * 8;
    const int tn = (tid >> 4) * TN;
    const int m0 = blockIdx.y * 128;
    const int n0 = blockIdx.x * BN;
    if (n0 >= N) return;              // batched variant: skip unused tiles

    constexpr int WLOAD = (16 * BN / 4) / 256;   // float4 W loads per thread

    // A-load indices (fixed per thread)
    const int ar0 = (tid)       >> 2, ac0 = ((tid)       & 3) * 4;
    const int ar1 = (tid + 256) >> 2, ac1 = ((tid + 256) & 3) * 4;

    float4 pa[2];
    float4 pw[WLOAD];

    // prologue: load tile k0=0 into registers
    {
        pa[0] = *reinterpret_cast<const float4*>(A + (size_t)(m0 + ar0) * K + ac0);
        pa[1] = *reinterpret_cast<const float4*>(A + (size_t)(m0 + ar1) * K + ac1);
#pragma unroll
        for (int i = 0; i < WLOAD; i++) {
            int idx = tid + i * 256;
            int r  = idx / (BN / 4);
            int c4 = (idx % (BN / 4)) * 4;
            int gn = n0 + c4;
            pw[i] = (gn < N)
                ? *reinterpret_cast<const float4*>(W + (size_t)r * N + gn)
                : make_float4(0.f, 0.f, 0.f, 0.f);
        }
    }

    float acc[8][TN];
#pragma unroll
    for (int i = 0; i < 8; i++)
#pragma unroll
        for (int j = 0; j < TN; j++) acc[i][j] = 0.f;

    for (int k0 = 0; k0 < K; k0 += 16) {
        // store prefetched tile to smem
        As[ac0 + 0][ar0] = pa[0].x;
        As[ac0 + 1][ar0] = pa[0].y;
        As[ac0 + 2][ar0] = pa[0].z;
        As[ac0 + 3][ar0] = pa[0].w;
        As[ac1 + 0][ar1] = pa[1].x;
        As[ac1 + 1][ar1] = pa[1].y;
        As[ac1 + 2][ar1] = pa[1].z;
        As[ac1 + 3][ar1] = pa[1].w;
#pragma unroll
        for (int i = 0; i < WLOAD; i++) {
            int idx = tid + i * 256;
            int r  = idx / (BN / 4);
            int c4 = (idx % (BN / 4)) * 4;
            *reinterpret_cast<float4*>(&Ws[r][c4]) = pw[i];
        }
        __syncthreads();

        // prefetch next tile into registers (overlaps with compute below)
        if (k0 + 16 < K) {
            int kn = k0 + 16;
            pa[0] = *reinterpret_cast<const float4*>(A + (size_t)(m0 + ar0) * K + kn + ac0);
            pa[1] = *reinterpret_cast<const float4*>(A + (size_t)(m0 + ar1) * K + kn + ac1);
#pragma unroll
            for (int i = 0; i < WLOAD; i++) {
                int idx = tid + i * 256;
                int r  = idx / (BN / 4);
                int c4 = (idx % (BN / 4)) * 4;
                int gn = n0 + c4;
                pw[i] = (gn < N)
                    ? *reinterpret_cast<const float4*>(W + (size_t)(kn + r) * N + gn)
                    : make_float4(0.f, 0.f, 0.f, 0.f);
            }
        }

#pragma unroll
        for (int kk = 0; kk < 16; kk++) {
            float af[8], bf[TN];
            *reinterpret_cast<float4*>(&af[0]) = *reinterpret_cast<float4*>(&As[kk][tm]);
            *reinterpret_cast<float4*>(&af[4]) = *reinterpret_cast<float4*>(&As[kk][tm + 4]);
#pragma unroll
            for (int j4 = 0; j4 < TN / 4; j4++)
                *reinterpret_cast<float4*>(&bf[j4 * 4]) =
                    *reinterpret_cast<float4*>(&Ws[kk][tn + j4 * 4]);
#pragma unroll
            for (int i = 0; i < 8; i++)
#pragma unroll
                for (int j = 0; j < TN; j++) acc[i][j] += af[i] * bf[j];
        }
        __syncthreads();
    }

#pragma unroll
    for (int i = 0; i < 8; i++) {
        int gm = m0 + tm + i;
#pragma unroll
        for (int j4 = 0; j4 < TN / 4; j4++) {
            int gn = n0 + tn + j4 * 4;
            if (gn < N) {
                *reinterpret_cast<float4*>(&C[(size_t)gm * N + gn]) =
                    make_float4(acc[i][j4 * 4], acc[i][j4 * 4 + 1],
                                acc[i][j4 * 4 + 2], acc[i][j4 * 4 + 3]);
            }
        }
    }
}

// ---------------------------------------------------------------------------
// RoPE in-place on X[NTOK][R][DK]
// ---------------------------------------------------------------------------
__global__ void rope_kernel(float* __restrict__ X, int R, int total)
{
    int idx = blockIdx.x * blockDim.x + threadIdx.x;
    if (idx >= total) return;
    int i = idx & 31;
    int r = (idx >> 5) % R;
    int t = idx / (32 * R);
    int s = t & (SEQ - 1);

    float inv_freq = powf(10000.0f, -(float)(2 * i) / 64.0f);
    float fr = (float)s * inv_freq;
    float sn, cs;
    sincosf(fr, &sn, &cs);

    float* base = X + ((size_t)t * R + r) * DK;
    float x1 = base[i];
    float x2 = base[32 + i];
    base[i]      = x1 * cs + x2 * sn;
    base[32 + i] = -x1 * sn + x2 * cs;
}

// ---------------------------------------------------------------------------
// Rank contraction: out[(b*H+h)][s][d] = scale * sum_r A[t][h*R+r]*Bm[t][r*DK+d]
// ---------------------------------------------------------------------------
__global__ void contract_kernel(const float* __restrict__ Am,
                                const float* __restrict__ Bm,
                                float* __restrict__ out, int R, float scale)
{
    int idx = blockIdx.x * blockDim.x + threadIdx.x;
    if (idx >= NTOK * HEADS * DK) return;
    int d = idx & (DK - 1);
    int h = (idx >> 6) & (HEADS - 1);
    int t = idx >> 10;

    const float* a = Am + (size_t)t * (HEADS * R) + h * R;
    const float* b = Bm + (size_t)t * R * DK + d;
    float s = 0.f;
#pragma unroll 6
    for (int r = 0; r < R; r++) s += a[r] * b[r * DK];

    int bb = t >> 11;
    int ss = t & (SEQ - 1);
    out[(((size_t)(bb * HEADS + h)) * SEQ + ss) * DK + d] = s * scale;
}

// ---------------------------------------------------------------------------
// Causal flash attention v3.
// grid (SEQ/128, BH), 128 threads. Thread t owns query row qb*128+t, full
// 64-dim q in registers. 64-key tiles staged in smem. 2 blocks/SM.
// qb is reversed so the heaviest blocks launch first.
// ---------------------------------------------------------------------------
#define FQ 128
#define FK 64

__global__ __launch_bounds__(128, 2) void flash_kernel(
    const float* __restrict__ Qh, const float* __restrict__ Kh,
    const float* __restrict__ Vh, float* __restrict__ O)
{
    const int bh = blockIdx.y;
    const int qb = (gridDim.x - 1) - blockIdx.x;   // heaviest first
    const int t = threadIdx.x;
    const int qrow = qb * FQ + t;

    __shared__ float4 Ks4[FK][16];
    __shared__ float4 Vs4[FK][16];

    float qreg[64];
    {
        const float4* qp4 = reinterpret_cast<const float4*>(
            Qh + ((size_t)bh * SEQ + qrow) * DK);
        const float inv_dk = 1.0f / (float)DK;
#pragma unroll
        for (int d4 = 0; d4 < 16; d4++) {
            float4 qq = qp4[d4];
            qreg[4 * d4 + 0] = qq.x * inv_dk;
            qreg[4 * d4 + 1] = qq.y * inv_dk;
            qreg[4 * d4 + 2] = qq.z * inv_dk;
            qreg[4 * d4 + 3] = qq.w * inv_dk;
        }
    }

    float4 acc4[16];
#pragma unroll
    for (int d4 = 0; d4 < 16; d4++) acc4[d4] = make_float4(0.f, 0.f, 0.f, 0.f);
    float m = -INFINITY, l = 0.f;

    const int ktmax = (qb * FQ + FQ - 1) / FK;     // inclusive
    for (int kt = 0; kt <= ktmax; kt++) {
        __syncthreads();
        const float4* kb4 = reinterpret_cast<const float4*>(
            Kh + ((size_t)bh * SEQ + kt * FK) * DK);
        const float4* vb4 = reinterpret_cast<const float4*>(
            Vh + ((size_t)bh * SEQ + kt * FK) * DK);
#pragma unroll
        for (int i = 0; i < 8; i++) {
            int idx = i * 128 + t;
            Ks4[idx >> 4][idx & 15] = kb4[idx];
            Vs4[idx >> 4][idx & 15] = vb4[idx];
        }
        __syncthreads();

        const int kg0 = kt * FK;
#pragma unroll
        for (int c = 0; c < 4; c++) {
            float p[16];
            float mloc = -INFINITY;
#pragma unroll
            for (int j = 0; j < 16; j++) {
                const int jj = c * 16 + j;
                float a0 = 0.f, a1 = 0.f, a2 = 0.f, a3 = 0.f;
#pragma unroll
                for (int d4 = 0; d4 < 16; d4++) {
                    float4 kk4 = Ks4[jj][d4];
                    a0 += qreg[4 * d4 + 0] * kk4.x;
                    a1 += qreg[4 * d4 + 1] * kk4.y;
                    a2 += qreg[4 * d4 + 2] * kk4.z;
                    a3 += qreg[4 * d4 + 3] * kk4.w;
                }
                float sv = (a0 + a1) + (a2 + a3);
                if (kg0 + jj > qrow) sv = -INFINITY;
                p[j] = sv;
                mloc = fmaxf(mloc, sv);
            }
            float m_new = fmaxf(m, mloc);
            float factor = __expf(m - m_new);
            float psum = 0.f;
#pragma unroll
            for (int j = 0; j < 16; j++) {
                p[j] = __expf(p[j] - m_new);
                psum += p[j];
            }
            l = l * factor + psum;
            m = m_new;
#pragma unroll
            for (int d4 = 0; d4 < 16; d4++) {
                acc4[d4].x *= factor; acc4[d4].y *= factor;
                acc4[d4].z *= factor; acc4[d4].w *= factor;
            }
#pragma unroll
            for (int j = 0; j < 16; j++) {
                const float pj = p[j];
#pragma unroll
                for (int d4 = 0; d4 < 16; d4++) {
                    float4 vv = Vs4[c * 16 + j][d4];
                    acc4[d4].x += pj * vv.x;
                    acc4[d4].y += pj * vv.y;
                    acc4[d4].z += pj * vv.z;
                    acc4[d4].w += pj * vv.w;
                }
            }
        }
    }

    const int b = bh >> 4;
    const int h = bh & 15;
    const float inv_l = 1.0f / l;
    float4* op4 = reinterpret_cast<float4*>(
        O + ((size_t)(b * SEQ) + qrow) * DMODEL + h * DK);
#pragma unroll
    for (int d4 = 0; d4 < 16; d4++) {
        float4 a = acc4[d4];
        op4[d4] = make_float4(a.x * inv_l, a.y * inv_l, a.z * inv_l, a.w * inv_l);
    }
}

// ---------------------------------------------------------------------------
extern "C" void kernel_launch(void* const* d_in, const int* in_sizes, int n_in,
                              void* d_out, int out_size)
{
    const float* q    = (const float*)d_in[0];
    const float* k    = (const float*)d_in[1];
    const float* v    = (const float*)d_in[2];
    const float* W_Aq = (const float*)d_in[4];
    const float* W_Ak = (const float*)d_in[5];
    const float* W_Av = (const float*)d_in[6];
    const float* W_Bq = (const float*)d_in[7];
    const float* W_Bk = (const float*)d_in[8];
    const float* W_Bv = (const float*)d_in[9];
    const float* Wo   = (const float*)d_in[10];
    float* out = (float*)d_out;

    float* scratch = nullptr;
    cudaGetSymbolAddress((void**)&scratch, g_scratch);
    float* sAq = scratch + OFF_AQ;
    float* sAk = scratch + OFF_AK;
    float* sAv = scratch + OFF_AV;
    float* sBq = scratch + OFF_BQ;
    float* sBk = scratch + OFF_BK;
    float* sBv = scratch + OFF_BV;
    float* sQh = scratch + OFF_QH;
    float* sKh = scratch + OFF_KH;
    float* sVh = scratch + OFF_VH;
    float* sOa = scratch + OFF_OA;

    const int MY = NTOK / 128;   // 32 row-blocks

    // 1) projections — batched: A-projections (N<=96, BN=64), B-projections (N<=384, BN=128)
    gemm_kernel<64, 4, 1><<<dim3(2, MY, 3), 256>>>(
        q, W_Aq, sAq, 96,
        k, W_Ak, sAk, 32,
        v, W_Av, sAv, 32,
        NTOK, DMODEL);
    gemm_kernel<128, 8, 1><<<dim3(3, MY, 3), 256>>>(
        q, W_Bq, sBq, 384,
        k, W_Bk, sBk, 128,
        v, W_Bv, sBv, 128,
        NTOK, DMODEL);

    // 2) RoPE
    {
        int total_q = NTOK * QRANK * 32;
        int total_k = NTOK * RANK * 32;
        rope_kernel<<<(total_q + 255) / 256, 256>>>(sBq, QRANK, total_q);
        rope_kernel<<<(total_k + 255) / 256, 256>>>(sBk, RANK, total_k);
    }

    // 3) rank contractions
    {
        int total = NTOK * HEADS * DK;
        contract_kernel<<<(total + 255) / 256, 256>>>(sAq, sBq, sQh, QRANK, 1.0f / QRANK);
        contract_kernel<<<(total + 255) / 256, 256>>>(sAk, sBk, sKh, RANK, 1.0f / RANK);
        contract_kernel<<<(total + 255) / 256, 256>>>(sAv, sBv, sVh, RANK, 1.0f / RANK);
    }

    // 4) causal flash attention
    flash_kernel<<<dim3(SEQ / FQ, BH), 128>>>(sQh, sKh, sVh, sOa);

    // 5) output projection
    gemm_kernel<128, 8, 0><<<dim3(DMODEL / 128, MY), 256>>>(
        sOa, Wo, out, DMODEL,
        nullptr, nullptr, nullptr, 0,
        nullptr, nullptr, nullptr, 0,
        NTOK, DMODEL);
}

// round 7
// speedup vs baseline: 1.6641x; 1.6163x over previous
#include <cuda_runtime.h>
#include <cuda_bf16.h>
#include <math.h>
#include <stdint.h>

// ---------------------------------------------------------------------------
// T6Attention — round 7: mma.sync (HMMA) bf16 hi/lo GEMMs + fp32 flash
// B=2, S=2048, D_MODEL=1024, HEADS=16, DK=64, Q_RANK=6, RANK=2
// (tcgen05 unavailable: harness PTX targets sm_103 base, not sm_103a)
// ---------------------------------------------------------------------------

#define BATCH     2
#define SEQ       2048
#define DMODEL    1024
#define HEADS     16
#define DK        64
#define QRANK     6
#define RANK      2
#define NTOK      (BATCH*SEQ)        // 4096
#define BH        (BATCH*HEADS)      // 32

// fp32 scratch offsets
#define OFF_AQ   0
#define SZ_AQ    (NTOK*HEADS*QRANK)
#define OFF_AK   (OFF_AQ+SZ_AQ)
#define SZ_AK    (NTOK*HEADS*RANK)
#define OFF_AV   (OFF_AK+SZ_AK)
#define SZ_AV    SZ_AK
#define OFF_BQ   (OFF_AV+SZ_AV)
#define SZ_BQ    (NTOK*QRANK*DK)
#define OFF_BK   (OFF_BQ+SZ_BQ)
#define SZ_BK    (NTOK*RANK*DK)
#define OFF_BV   (OFF_BK+SZ_BK)
#define SZ_BV    SZ_BK
#define OFF_QH   (OFF_BV+SZ_BV)
#define SZ_QH    (BH*SEQ*DK)
#define OFF_KH   (OFF_QH+SZ_QH)
#define OFF_VH   (OFF_KH+SZ_QH)
#define OFF_OA   (OFF_VH+SZ_QH)
#define SCRATCH_TOTAL (OFF_OA+SZ_QH)

__device__ float g_scratch[SCRATCH_TOTAL];

// bf16 scratch offsets (elements)
#define TOKD          (NTOK*DMODEL)
#define BOFF_QHI      0
#define BOFF_QLO      (BOFF_QHI + TOKD)
#define BOFF_KHI      (BOFF_QLO + TOKD)
#define BOFF_KLO      (BOFF_KHI + TOKD)
#define BOFF_VHI      (BOFF_KLO + TOKD)
#define BOFF_VLO      (BOFF_VHI + TOKD)
#define BOFF_OAHI     (BOFF_VLO + TOKD)
#define BOFF_OALO     (BOFF_OAHI + TOKD)
#define BOFF_WBQ_HI   (BOFF_OALO + TOKD)
#define BOFF_WBQ_LO   (BOFF_WBQ_HI + 384*1024)
#define BOFF_WBK_HI   (BOFF_WBQ_LO + 384*1024)
#define BOFF_WBK_LO   (BOFF_WBK_HI + 128*1024)
#define BOFF_WBV_HI   (BOFF_WBK_LO + 128*1024)
#define BOFF_WBV_LO   (BOFF_WBV_HI + 128*1024)
#define BOFF_WO_HI    (BOFF_WBV_LO + 128*1024)
#define BOFF_WO_LO    (BOFF_WO_HI + 1024*1024)
#define BF_TOTAL      (BOFF_WO_LO + 1024*1024)

__device__ __nv_bfloat16 g_bf[BF_TOTAL];

// ---------------------------------------------------------------------------
// mma.sync m16n8k16 bf16 (row.col) with fp32 accumulate
// ---------------------------------------------------------------------------
__device__ __forceinline__ void mma16816(float* d,
                                         uint32_t a0, uint32_t a1, uint32_t a2, uint32_t a3,
                                         uint32_t b0, uint32_t b1)
{
    asm volatile(
        "mma.sync.aligned.m16n8k16.row.col.f32.bf16.bf16.f32 "
        "{%0,%1,%2,%3}, {%4,%5,%6,%7}, {%8,%9}, {%0,%1,%2,%3};"
        : "+f"(d[0]), "+f"(d[1]), "+f"(d[2]), "+f"(d[3])
        : "r"(a0), "r"(a1), "r"(a2), "r"(a3), "r"(b0), "r"(b1));
}

// ---------------------------------------------------------------------------
// hi/lo split: hi=bf16(x), lo=bf16(x-hi)
// ---------------------------------------------------------------------------
__global__ void split_kernel(const float* __restrict__ x,
                             __nv_bfloat16* __restrict__ hi,
                             __nv_bfloat16* __restrict__ lo, int n)
{
    int i = blockIdx.x * blockDim.x + threadIdx.x;
    if (i >= n) return;
    float v = x[i];
    __nv_bfloat16 h = __float2bfloat16(v);
    hi[i] = h;
    lo[i] = __float2bfloat16(v - __bfloat162float(h));
}

// ---------------------------------------------------------------------------
// transpose + split: W[K,N] fp32 -> hi/lo [N,K] bf16.  K%32==0, N%32==0.
// block (32,8), grid (N/32, K/32)
// ---------------------------------------------------------------------------
__global__ void tsplit_kernel(const float* __restrict__ W,
                              __nv_bfloat16* __restrict__ hi,
                              __nv_bfloat16* __restrict__ lo, int K, int N)
{
    __shared__ float t[32][33];
    const int n0 = blockIdx.x * 32, k0 = blockIdx.y * 32;
    const int tx = threadIdx.x, ty = threadIdx.y;
#pragma unroll
    for (int i = 0; i < 4; i++)
        t[ty + i * 8][tx] = W[(size_t)(k0 + ty + i * 8) * N + n0 + tx];
    __syncthreads();
#pragma unroll
    for (int i = 0; i < 4; i++) {
        float v = t[tx][ty + i * 8];
        __nv_bfloat16 h = __float2bfloat16(v);
        size_t o = (size_t)(n0 + ty + i * 8) * K + k0 + tx;
        hi[o] = h;
        lo[o] = __float2bfloat16(v - __bfloat162float(h));
    }
}

// ---------------------------------------------------------------------------
// HMMA GEMM: C[M,N] fp32 = A @ W via bf16 hi/lo (hihi + hilo + lohi).
// A: (Ahi,Alo)[M,1024] bf16 row-major. B: (Bhi,Blo)[N,1024] bf16 row-major
// (pre-transposed W). CTA: 128x128 tile, 256 thr = 8 warps (4 along M x 2
// along N), warp tile 32x64, mma m16n8k16. K chunk = 64, smem padded to
// 72 bf16/row (conflict-free b32 fragment loads).
// ---------------------------------------------------------------------------
#define KPAD   72
#define KTILE  64
#define TILEB  (128 * KPAD * 2)        // bytes per smem operand tile (18432)

__global__ __launch_bounds__(256) void tc_gemm_kernel(
    const __nv_bfloat16* __restrict__ Ahi, const __nv_bfloat16* __restrict__ Alo,
    const __nv_bfloat16* __restrict__ Bhi, const __nv_bfloat16* __restrict__ Blo,
    float* __restrict__ C, int N)
{
    extern __shared__ char smem[];
    __nv_bfloat16* sAhi = reinterpret_cast<__nv_bfloat16*>(smem);
    __nv_bfloat16* sAlo = reinterpret_cast<__nv_bfloat16*>(smem + TILEB);
    __nv_bfloat16* sBhi = reinterpret_cast<__nv_bfloat16*>(smem + 2 * TILEB);
    __nv_bfloat16* sBlo = reinterpret_cast<__nv_bfloat16*>(smem + 3 * TILEB);
    const uint32_t* uAhi = reinterpret_cast<const uint32_t*>(sAhi);
    const uint32_t* uAlo = reinterpret_cast<const uint32_t*>(sAlo);
    const uint32_t* uBhi = reinterpret_cast<const uint32_t*>(sBhi);
    const uint32_t* uBlo = reinterpret_cast<const uint32_t*>(sBlo);

    const int tid = threadIdx.x;
    const int wid = tid >> 5;
    const int lid = tid & 31;
    const int m0 = blockIdx.y * 128;
    const int n0 = blockIdx.x * 128;
    const int wm = (wid & 3) * 32;      // warp m offset in tile
    const int wn = (wid >> 2) * 64;     // warp n offset in tile

    const int gr = lid >> 2;            // 0..7
    const int gc = (lid & 3) * 2;       // 0,2,4,6

    const uint4* gAhi = reinterpret_cast<const uint4*>(Ahi);  // row = 128 uint4
    const uint4* gAlo = reinterpret_cast<const uint4*>(Alo);
    const uint4* gBhi = reinterpret_cast<const uint4*>(Bhi);
    const uint4* gBlo = reinterpret_cast<const uint4*>(Blo);

    float acc[2][8][4];
#pragma unroll
    for (int mf = 0; mf < 2; mf++)
#pragma unroll
        for (int nf = 0; nf < 8; nf++)
#pragma unroll
            for (int e = 0; e < 4; e++) acc[mf][nf][e] = 0.f;

    for (int kc = 0; kc < 1024 / KTILE; kc++) {
        // G2S: each tile 128 rows x 64 bf16 = 1024 uint4, 4 per thread per array
#pragma unroll
        for (int i = 0; i < 4; i++) {
            int idx = tid + i * 256;
            int r = idx >> 3, c = idx & 7;
            size_t g = (size_t)(m0 + r) * 128 + kc * 8 + c;
            size_t s = ((size_t)r * KPAD + c * 8) / 8;   // uint4 index (KPAD%8==0)
            reinterpret_cast<uint4*>(sAhi)[s] = gAhi[g];
            reinterpret_cast<uint4*>(sAlo)[s] = gAlo[g];
            size_t gb = (size_t)(n0 + r) * 128 + kc * 8 + c;
            reinterpret_cast<uint4*>(sBhi)[s] = gBhi[gb];
            reinterpret_cast<uint4*>(sBlo)[s] = gBlo[gb];
        }
        __syncthreads();

#pragma unroll
        for (int ks = 0; ks < 4; ks++) {
            const int k0 = ks * 16;
            // A fragments (hi & lo): 2 m-frags x 4 regs
            uint32_t ah[2][4], al[2][4];
#pragma unroll
            for (int mf = 0; mf < 2; mf++) {
                int r0 = wm + mf * 16 + gr;
                int base0 = (r0 * KPAD + k0 + gc) >> 1;
                int base1 = ((r0 + 8) * KPAD + k0 + gc) >> 1;
                ah[mf][0] = uAhi[base0];     al[mf][0] = uAlo[base0];
                ah[mf][1] = uAhi[base1];     al[mf][1] = uAlo[base1];
                ah[mf][2] = uAhi[base0 + 4]; al[mf][2] = uAlo[base0 + 4];
                ah[mf][3] = uAhi[base1 + 4]; al[mf][3] = uAlo[base1 + 4];
            }
            // B fragments: 8 n-frags x 2 regs
            uint32_t bh[8][2], bl[8][2];
#pragma unroll
            for (int nf = 0; nf < 8; nf++) {
                int r = wn + nf * 8 + gr;
                int base = (r * KPAD + k0 + gc) >> 1;
                bh[nf][0] = uBhi[base];     bl[nf][0] = uBlo[base];
                bh[nf][1] = uBhi[base + 4]; bl[nf][1] = uBlo[base + 4];
            }
#pragma unroll
            for (int mf = 0; mf < 2; mf++)
#pragma unroll
                for (int nf = 0; nf < 8; nf++) {
                    mma16816(acc[mf][nf], ah[mf][0], ah[mf][1], ah[mf][2], ah[mf][3],
                             bh[nf][0], bh[nf][1]);
                    mma16816(acc[mf][nf], ah[mf][0], ah[mf][1], ah[mf][2], ah[mf][3],
                             bl[nf][0], bl[nf][1]);
                    mma16816(acc[mf][nf], al[mf][0], al[mf][1], al[mf][2], al[mf][3],
                             bh[nf][0], bh[nf][1]);
                }
        }
        __syncthreads();
    }

    // epilogue: direct global stores (float2, 8B aligned)
#pragma unroll
    for (int mf = 0; mf < 2; mf++) {
        int r0 = m0 + wm + mf * 16 + gr;
        int r1 = r0 + 8;
#pragma unroll
        for (int nf = 0; nf < 8; nf++) {
            int col = n0 + wn + nf * 8 + gc;
            *reinterpret_cast<float2*>(&C[(size_t)r0 * N + col]) =
                make_float2(acc[mf][nf][0], acc[mf][nf][1]);
            *reinterpret_cast<float2*>(&C[(size_t)r1 * N + col]) =
                make_float2(acc[mf][nf][2], acc[mf][nf][3]);
        }
    }
}

// ---------------------------------------------------------------------------
// fp32 tiled SGEMM (A-projections only). BM=128, BN=64, BK=16, 256 thr, 8x4.
// blockIdx.z selects (A,W,C,N).
// ---------------------------------------------------------------------------
__global__ __launch_bounds__(256) void gemm_a_kernel(
    const float* __restrict__ A0, const float* __restrict__ W0, float* __restrict__ C0, int N0,
    const float* __restrict__ A1, const float* __restrict__ W1, float* __restrict__ C1, int N1,
    const float* __restrict__ A2, const float* __restrict__ W2, float* __restrict__ C2, int N2,
    int M, int K)
{
    const float* A = A0; const float* W = W0; float* C = C0; int N = N0;
    {
        int z = blockIdx.z;
        if (z == 1) { A = A1; W = W1; C = C1; N = N1; }
        else if (z == 2) { A = A2; W = W2; C = C2; N = N2; }
    }

    __shared__ float As[16][132];
    __shared__ float Ws[16][64];

    const int tid = threadIdx.x;
    const int tm = (tid & 15) * 8;
    const int tn = (tid >> 4) * 4;
    const int m0 = blockIdx.y * 128;
    const int n0 = blockIdx.x * 64;
    if (n0 >= N) return;

    float acc[8][4];
#pragma unroll
    for (int i = 0; i < 8; i++)
#pragma unroll
        for (int j = 0; j < 4; j++) acc[i][j] = 0.f;

    for (int k0 = 0; k0 < K; k0 += 16) {
#pragma unroll
        for (int i = 0; i < 2; i++) {
            int idx = tid + i * 256;
            int r = idx >> 2, c4 = (idx & 3) * 4;
            float4 a = *reinterpret_cast<const float4*>(A + (size_t)(m0 + r) * K + k0 + c4);
            As[c4 + 0][r] = a.x; As[c4 + 1][r] = a.y;
            As[c4 + 2][r] = a.z; As[c4 + 3][r] = a.w;
        }
        {
            int idx = tid;
            int r = idx >> 4, c4 = (idx & 15) * 4;
            int gn = n0 + c4;
            float4 w = (gn < N)
                ? *reinterpret_cast<const float4*>(W + (size_t)(k0 + r) * N + gn)
                : make_float4(0.f, 0.f, 0.f, 0.f);
            *reinterpret_cast<float4*>(&Ws[r][c4]) = w;
        }
        __syncthreads();

#pragma unroll
        for (int kk = 0; kk < 16; kk++) {
            float af[8], bf[4];
            *reinterpret_cast<float4*>(&af[0]) = *reinterpret_cast<float4*>(&As[kk][tm]);
            *reinterpret_cast<float4*>(&af[4]) = *reinterpret_cast<float4*>(&As[kk][tm + 4]);
            *reinterpret_cast<float4*>(&bf[0]) = *reinterpret_cast<float4*>(&Ws[kk][tn]);
#pragma unroll
            for (int i = 0; i < 8; i++)
#pragma unroll
                for (int j = 0; j < 4; j++) acc[i][j] += af[i] * bf[j];
        }
        __syncthreads();
    }

#pragma unroll
    for (int i = 0; i < 8; i++) {
        int gm = m0 + tm + i;
        int gn = n0 + tn;
        if (gn < N) {
            *reinterpret_cast<float4*>(&C[(size_t)gm * N + gn]) =
                make_float4(acc[i][0], acc[i][1], acc[i][2], acc[i][3]);
        }
    }
}

// ---------------------------------------------------------------------------
// RoPE in-place on X[NTOK][R][DK]
// ---------------------------------------------------------------------------
__global__ void rope_kernel(float* __restrict__ X, int R, int total)
{
    int idx = blockIdx.x * blockDim.x + threadIdx.x;
    if (idx >= total) return;
    int i = idx & 31;
    int r = (idx >> 5) % R;
    int t = idx / (32 * R);
    int s = t & (SEQ - 1);

    float inv_freq = powf(10000.0f, -(float)(2 * i) / 64.0f);
    float fr = (float)s * inv_freq;
    float sn, cs;
    sincosf(fr, &sn, &cs);

    float* base = X + ((size_t)t * R + r) * DK;
    float x1 = base[i];
    float x2 = base[32 + i];
    base[i]      = x1 * cs + x2 * sn;
    base[32 + i] = -x1 * sn + x2 * cs;
}

// ---------------------------------------------------------------------------
// Rank contraction
// ---------------------------------------------------------------------------
__global__ void contract_kernel(const float* __restrict__ Am,
                                const float* __restrict__ Bm,
                                float* __restrict__ out, int R, float scale)
{
    int idx = blockIdx.x * blockDim.x + threadIdx.x;
    if (idx >= NTOK * HEADS * DK) return;
    int d = idx & (DK - 1);
    int h = (idx >> 6) & (HEADS - 1);
    int t = idx >> 10;

    const float* a = Am + (size_t)t * (HEADS * R) + h * R;
    const float* b = Bm + (size_t)t * R * DK + d;
    float s = 0.f;
#pragma unroll 6
    for (int r = 0; r < R; r++) s += a[r] * b[r * DK];

    int bb = t >> 11;
    int ss = t & (SEQ - 1);
    out[(((size_t)(bb * HEADS + h)) * SEQ + ss) * DK + d] = s * scale;
}

// ---------------------------------------------------------------------------
// Causal flash attention (R1 measured-best structure + diagonal-only masking).
// grid (SEQ/64, BH), 64 threads. Thread t owns query qt*64+t.
// ---------------------------------------------------------------------------
__global__ __launch_bounds__(64) void flash_kernel(
    const float* __restrict__ Qh, const float* __restrict__ Kh,
    const float* __restrict__ Vh, float* __restrict__ O)
{
    const int bh = blockIdx.y;
    const int qt = blockIdx.x;
    const int t = threadIdx.x;
    const int qrow = qt * 64 + t;

    __shared__ float4 Ks4[64][16];
    __shared__ float4 Vs4[64][16];

    float qreg[64];
    {
        const float4* qp4 = reinterpret_cast<const float4*>(
            Qh + ((size_t)bh * SEQ + qrow) * DK);
        const float inv_dk = 1.0f / (float)DK;
#pragma unroll
        for (int d4 = 0; d4 < 16; d4++) {
            float4 qq = qp4[d4];
            qreg[4 * d4 + 0] = qq.x * inv_dk;
            qreg[4 * d4 + 1] = qq.y * inv_dk;
            qreg[4 * d4 + 2] = qq.z * inv_dk;
            qreg[4 * d4 + 3] = qq.w * inv_dk;
        }
    }

    float4 acc4[16];
#pragma unroll
    for (int d4 = 0; d4 < 16; d4++) acc4[d4] = make_float4(0.f, 0.f, 0.f, 0.f);
    float m = -INFINITY, l = 0.f;

    for (int kt = 0; kt <= qt; kt++) {
        __syncthreads();
        const float4* kb4 = reinterpret_cast<const float4*>(
            Kh + ((size_t)bh * SEQ + kt * 64) * DK);
        const float4* vb4 = reinterpret_cast<const float4*>(
            Vh + ((size_t)bh * SEQ + kt * 64) * DK);
#pragma unroll
        for (int i = 0; i < 16; i++) {
            int idx = i * 64 + t;
            Ks4[idx >> 4][idx & 15] = kb4[idx];
            Vs4[idx >> 4][idx & 15] = vb4[idx];
        }
        __syncthreads();

        const bool diag = (kt == qt);
        const int kg0 = kt * 64;
        for (int c = 0; c < 4; c++) {
            float p[16];
            float mloc = -INFINITY;
#pragma unroll
            for (int j = 0; j < 16; j++) {
                const int jj = c * 16 + j;
                float a0 = 0.f, a1 = 0.f, a2 = 0.f, a3 = 0.f;
#pragma unroll
                for (int d4 = 0; d4 < 16; d4++) {
                    float4 kk4 = Ks4[jj][d4];
                    a0 += qreg[4 * d4 + 0] * kk4.x;
                    a1 += qreg[4 * d4 + 1] * kk4.y;
                    a2 += qreg[4 * d4 + 2] * kk4.z;
                    a3 += qreg[4 * d4 + 3] * kk4.w;
                }
                float sv = (a0 + a1) + (a2 + a3);
                if (diag && (kg0 + jj > qrow)) sv = -INFINITY;
                p[j] = sv;
                mloc = fmaxf(mloc, sv);
            }
            float m_new = fmaxf(m, mloc);
            float factor = __expf(m - m_new);
            float psum = 0.f;
#pragma unroll
            for (int j = 0; j < 16; j++) {
                p[j] = __expf(p[j] - m_new);
                psum += p[j];
            }
            l = l * factor + psum;
            m = m_new;
#pragma unroll
            for (int d4 = 0; d4 < 16; d4++) {
                acc4[d4].x *= factor; acc4[d4].y *= factor;
                acc4[d4].z *= factor; acc4[d4].w *= factor;
            }
#pragma unroll
            for (int j = 0; j < 16; j++) {
                const float pj = p[j];
#pragma unroll
                for (int d4 = 0; d4 < 16; d4++) {
                    float4 vv = Vs4[c * 16 + j][d4];
                    acc4[d4].x += pj * vv.x;
                    acc4[d4].y += pj * vv.y;
                    acc4[d4].z += pj * vv.z;
                    acc4[d4].w += pj * vv.w;
                }
            }
        }
    }

    const int b = bh >> 4;
    const int h = bh & 15;
    const float inv_l = 1.0f / l;
    float4* op4 = reinterpret_cast<float4*>(
        O + ((size_t)(b * SEQ) + qrow) * DMODEL + h * DK);
#pragma unroll
    for (int d4 = 0; d4 < 16; d4++) {
        float4 a = acc4[d4];
        op4[d4] = make_float4(a.x * inv_l, a.y * inv_l, a.z * inv_l, a.w * inv_l);
    }
}

// ---------------------------------------------------------------------------
extern "C" void kernel_launch(void* const* d_in, const int* in_sizes, int n_in,
                              void* d_out, int out_size)
{
    const float* q    = (const float*)d_in[0];
    const float* k    = (const float*)d_in[1];
    const float* v    = (const float*)d_in[2];
    const float* W_Aq = (const float*)d_in[4];
    const float* W_Ak = (const float*)d_in[5];
    const float* W_Av = (const float*)d_in[6];
    const float* W_Bq = (const float*)d_in[7];
    const float* W_Bk = (const float*)d_in[8];
    const float* W_Bv = (const float*)d_in[9];
    const float* Wo   = (const float*)d_in[10];
    float* out = (float*)d_out;

    float* scratch = nullptr;
    cudaGetSymbolAddress((void**)&scratch, g_scratch);
    __nv_bfloat16* bscratch = nullptr;
    cudaGetSymbolAddress((void**)&bscratch, g_bf);

    float* sAq = scratch + OFF_AQ;
    float* sAk = scratch + OFF_AK;
    float* sAv = scratch + OFF_AV;
    float* sBq = scratch + OFF_BQ;
    float* sBk = scratch + OFF_BK;
    float* sBv = scratch + OFF_BV;
    float* sQh = scratch + OFF_QH;
    float* sKh = scratch + OFF_KH;
    float* sVh = scratch + OFF_VH;
    float* sOa = scratch + OFF_OA;

    __nv_bfloat16* bQhi = bscratch + BOFF_QHI;
    __nv_bfloat16* bQlo = bscratch + BOFF_QLO;
    __nv_bfloat16* bKhi = bscratch + BOFF_KHI;
    __nv_bfloat16* bKlo = bscratch + BOFF_KLO;
    __nv_bfloat16* bVhi = bscratch + BOFF_VHI;
    __nv_bfloat16* bVlo = bscratch + BOFF_VLO;
    __nv_bfloat16* bOhi = bscratch + BOFF_OAHI;
    __nv_bfloat16* bOlo = bscratch + BOFF_OALO;
    __nv_bfloat16* wBqHi = bscratch + BOFF_WBQ_HI;
    __nv_bfloat16* wBqLo = bscratch + BOFF_WBQ_LO;
    __nv_bfloat16* wBkHi = bscratch + BOFF_WBK_HI;
    __nv_bfloat16* wBkLo = bscratch + BOFF_WBK_LO;
    __nv_bfloat16* wBvHi = bscratch + BOFF_WBV_HI;
    __nv_bfloat16* wBvLo = bscratch + BOFF_WBV_LO;
    __nv_bfloat16* wOHi  = bscratch + BOFF_WO_HI;
    __nv_bfloat16* wOLo  = bscratch + BOFF_WO_LO;

    const int TCSMEM = 4 * TILEB;   // 73728 bytes
    cudaFuncSetAttribute(tc_gemm_kernel,
                         cudaFuncAttributeMaxDynamicSharedMemorySize, TCSMEM);

    const int MY = NTOK / 128;   // 32

    // 0) precision prep: splits and weight transposes
    split_kernel<<<(TOKD + 255) / 256, 256>>>(q, bQhi, bQlo, TOKD);
    split_kernel<<<(TOKD + 255) / 256, 256>>>(k, bKhi, bKlo, TOKD);
    split_kernel<<<(TOKD + 255) / 256, 256>>>(v, bVhi, bVlo, TOKD);
    tsplit_kernel<<<dim3(384 / 32, 1024 / 32), dim3(32, 8)>>>(W_Bq, wBqHi, wBqLo, 1024, 384);
    tsplit_kernel<<<dim3(128 / 32, 1024 / 32), dim3(32, 8)>>>(W_Bk, wBkHi, wBkLo, 1024, 128);
    tsplit_kernel<<<dim3(128 / 32, 1024 / 32), dim3(32, 8)>>>(W_Bv, wBvHi, wBvLo, 1024, 128);
    tsplit_kernel<<<dim3(1024 / 32, 1024 / 32), dim3(32, 8)>>>(Wo, wOHi, wOLo, 1024, 1024);

    // 1) A-projections (fp32, batched)
    gemm_a_kernel<<<dim3(2, MY, 3), 256>>>(
        q, W_Aq, sAq, 96,
        k, W_Ak, sAk, 32,
        v, W_Av, sAv, 32,
        NTOK, DMODEL);

    // 2) B-projections (HMMA)
    tc_gemm_kernel<<<dim3(384 / 128, MY), 256, TCSMEM>>>(bQhi, bQlo, wBqHi, wBqLo, sBq, 384);
    tc_gemm_kernel<<<dim3(128 / 128, MY), 256, TCSMEM>>>(bKhi, bKlo, wBkHi, wBkLo, sBk, 128);
    tc_gemm_kernel<<<dim3(128 / 128, MY), 256, TCSMEM>>>(bVhi, bVlo, wBvHi, wBvLo, sBv, 128);

    // 3) RoPE
    {
        int total_q = NTOK * QRANK * 32;
        int total_k = NTOK * RANK * 32;
        rope_kernel<<<(total_q + 255) / 256, 256>>>(sBq, QRANK, total_q);
        rope_kernel<<<(total_k + 255) / 256, 256>>>(sBk, RANK, total_k);
    }

    // 4) rank contractions
    {
        int total = NTOK * HEADS * DK;
        contract_kernel<<<(total + 255) / 256, 256>>>(sAq, sBq, sQh, QRANK, 1.0f / QRANK);
        contract_kernel<<<(total + 255) / 256, 256>>>(sAk, sBk, sKh, RANK, 1.0f / RANK);
        contract_kernel<<<(total + 255) / 256, 256>>>(sAv, sBv, sVh, RANK, 1.0f / RANK);
    }

    // 5) causal flash attention
    flash_kernel<<<dim3(SEQ / 64, BH), 64>>>(sQh, sKh, sVh, sOa);

    // 6) output projection (HMMA)
    split_kernel<<<(TOKD + 255) / 256, 256>>>(sOa, bOhi, bOlo, TOKD);
    tc_gemm_kernel<<<dim3(1024 / 128, MY), 256, TCSMEM>>>(bOhi, bOlo, wOHi, wOLo, out, 1024);
}

// round 8
// speedup vs baseline: 3.1654x; 1.9022x over previous
#include <cuda_runtime.h>
#include <cuda_bf16.h>
#include <math.h>
#include <stdint.h>

// ---------------------------------------------------------------------------
// T6Attention — round 8: HMMA everywhere (GEMMs + flash attention)
// B=2, S=2048, D_MODEL=1024, HEADS=16, DK=64, Q_RANK=6, RANK=2
// ---------------------------------------------------------------------------

#define BATCH     2
#define SEQ       2048
#define DMODEL    1024
#define HEADS     16
#define DK        64
#define QRANK     6
#define RANK      2
#define NTOK      (BATCH*SEQ)        // 4096
#define BH        (BATCH*HEADS)      // 32

// fp32 scratch offsets
#define OFF_AQ   0
#define SZ_AQ    (NTOK*HEADS*QRANK)
#define OFF_AK   (OFF_AQ+SZ_AQ)
#define SZ_AK    (NTOK*HEADS*RANK)
#define OFF_AV   (OFF_AK+SZ_AK)
#define SZ_AV    SZ_AK
#define OFF_BQ   (OFF_AV+SZ_AV)
#define SZ_BQ    (NTOK*QRANK*DK)
#define OFF_BK   (OFF_BQ+SZ_BQ)
#define SZ_BK    (NTOK*RANK*DK)
#define OFF_BV   (OFF_BK+SZ_BK)
#define SZ_BV    SZ_BK
#define OFF_VH   (OFF_BV+SZ_BV)
#define SZ_VH    (BH*SEQ*DK)
#define OFF_OA   (OFF_VH+SZ_VH)
#define SCRATCH_TOTAL (OFF_OA+SZ_VH)

__device__ float g_scratch[SCRATCH_TOTAL];

// bf16 scratch offsets (elements);  TOKD == BH*SEQ*DK == 4194304
#define TOKD          (NTOK*DMODEL)
#define BOFF_QHI      0
#define BOFF_QLO      (BOFF_QHI + TOKD)
#define BOFF_KHI      (BOFF_QLO + TOKD)
#define BOFF_KLO      (BOFF_KHI + TOKD)
#define BOFF_VHI      (BOFF_KLO + TOKD)
#define BOFF_VLO      (BOFF_VHI + TOKD)
#define BOFF_OAHI     (BOFF_VLO + TOKD)
#define BOFF_OALO     (BOFF_OAHI + TOKD)
#define BOFF_WBQ_HI   (BOFF_OALO + TOKD)
#define BOFF_WBQ_LO   (BOFF_WBQ_HI + 384*1024)
#define BOFF_WBK_HI   (BOFF_WBQ_LO + 384*1024)
#define BOFF_WBK_LO   (BOFF_WBK_HI + 128*1024)
#define BOFF_WBV_HI   (BOFF_WBK_LO + 128*1024)
#define BOFF_WBV_LO   (BOFF_WBV_HI + 128*1024)
#define BOFF_WO_HI    (BOFF_WBV_LO + 128*1024)
#define BOFF_WO_LO    (BOFF_WO_HI + 1024*1024)
#define BOFF_FQHI     (BOFF_WO_LO + 1024*1024)
#define BOFF_FQLO     (BOFF_FQHI + TOKD)
#define BOFF_FKHI     (BOFF_FQLO + TOKD)
#define BOFF_FKLO     (BOFF_FKHI + TOKD)
#define BOFF_FVTHI    (BOFF_FKLO + TOKD)
#define BOFF_FVTLO    (BOFF_FVTHI + TOKD)
#define BF_TOTAL      (BOFF_FVTLO + TOKD)

__device__ __nv_bfloat16 g_bf[BF_TOTAL];

// ---------------------------------------------------------------------------
// mma.sync m16n8k16 bf16 (row.col) fp32 accumulate
// ---------------------------------------------------------------------------
__device__ __forceinline__ void mma16816(float* d,
                                         uint32_t a0, uint32_t a1, uint32_t a2, uint32_t a3,
                                         uint32_t b0, uint32_t b1)
{
    asm volatile(
        "mma.sync.aligned.m16n8k16.row.col.f32.bf16.bf16.f32 "
        "{%0,%1,%2,%3}, {%4,%5,%6,%7}, {%8,%9}, {%0,%1,%2,%3};"
        : "+f"(d[0]), "+f"(d[1]), "+f"(d[2]), "+f"(d[3])
        : "r"(a0), "r"(a1), "r"(a2), "r"(a3), "r"(b0), "r"(b1));
}

__device__ __forceinline__ uint32_t packbf2(float a, float b) {
    __nv_bfloat162 t = __floats2bfloat162_rn(a, b);
    return *reinterpret_cast<uint32_t*>(&t);
}

// ---------------------------------------------------------------------------
// hi/lo split
// ---------------------------------------------------------------------------
__global__ void split_kernel(const float* __restrict__ x,
                             __nv_bfloat16* __restrict__ hi,
                             __nv_bfloat16* __restrict__ lo, int n)
{
    int i = blockIdx.x * blockDim.x + threadIdx.x;
    if (i >= n) return;
    float v = x[i];
    __nv_bfloat16 h = __float2bfloat16(v);
    hi[i] = h;
    lo[i] = __float2bfloat16(v - __bfloat162float(h));
}

// ---------------------------------------------------------------------------
// transpose + split: W[K,N] fp32 -> hi/lo [N,K] bf16
// ---------------------------------------------------------------------------
__global__ void tsplit_kernel(const float* __restrict__ W,
                              __nv_bfloat16* __restrict__ hi,
                              __nv_bfloat16* __restrict__ lo, int K, int N)
{
    __shared__ float t[32][33];
    const int n0 = blockIdx.x * 32, k0 = blockIdx.y * 32;
    const int tx = threadIdx.x, ty = threadIdx.y;
#pragma unroll
    for (int i = 0; i < 4; i++)
        t[ty + i * 8][tx] = W[(size_t)(k0 + ty + i * 8) * N + n0 + tx];
    __syncthreads();
#pragma unroll
    for (int i = 0; i < 4; i++) {
        float v = t[tx][ty + i * 8];
        __nv_bfloat16 h = __float2bfloat16(v);
        size_t o = (size_t)(n0 + ty + i * 8) * K + k0 + tx;
        hi[o] = h;
        lo[o] = __float2bfloat16(v - __bfloat162float(h));
    }
}

// ---------------------------------------------------------------------------
// batched transpose + split for V: vh[bh][S][64] fp32 -> [bh][64][S] bf16 hi/lo
// grid (SEQ/32, DK/32, BH), block (32,8)
// ---------------------------------------------------------------------------
__global__ void vtsplit_kernel(const float* __restrict__ Vsrc,
                               __nv_bfloat16* __restrict__ hi,
                               __nv_bfloat16* __restrict__ lo)
{
    __shared__ float t[32][33];
    const int s0 = blockIdx.x * 32, d0 = blockIdx.y * 32;
    const int bh = blockIdx.z;
    const int tx = threadIdx.x, ty = threadIdx.y;
#pragma unroll
    for (int i = 0; i < 4; i++)
        t[ty + i * 8][tx] = Vsrc[((size_t)bh * SEQ + s0 + ty + i * 8) * DK + d0 + tx];
    __syncthreads();
#pragma unroll
    for (int i = 0; i < 4; i++) {
        float v = t[tx][ty + i * 8];
        __nv_bfloat16 h = __float2bfloat16(v);
        size_t o = ((size_t)bh * DK + d0 + ty + i * 8) * SEQ + s0 + tx;
        hi[o] = h;
        lo[o] = __float2bfloat16(v - __bfloat162float(h));
    }
}

// ---------------------------------------------------------------------------
// HMMA GEMM (unchanged from R7): C[M,N] fp32 = A @ W via bf16 hi/lo
// ---------------------------------------------------------------------------
#define KPAD   72
#define KTILE  64
#define TILEB  (128 * KPAD * 2)

__global__ __launch_bounds__(256) void tc_gemm_kernel(
    const __nv_bfloat16* __restrict__ Ahi, const __nv_bfloat16* __restrict__ Alo,
    const __nv_bfloat16* __restrict__ Bhi, const __nv_bfloat16* __restrict__ Blo,
    float* __restrict__ C, int N)
{
    extern __shared__ char smem[];
    __nv_bfloat16* sAhi = reinterpret_cast<__nv_bfloat16*>(smem);
    __nv_bfloat16* sAlo = reinterpret_cast<__nv_bfloat16*>(smem + TILEB);
    __nv_bfloat16* sBhi = reinterpret_cast<__nv_bfloat16*>(smem + 2 * TILEB);
    __nv_bfloat16* sBlo = reinterpret_cast<__nv_bfloat16*>(smem + 3 * TILEB);
    const uint32_t* uAhi = reinterpret_cast<const uint32_t*>(sAhi);
    const uint32_t* uAlo = reinterpret_cast<const uint32_t*>(sAlo);
    const uint32_t* uBhi = reinterpret_cast<const uint32_t*>(sBhi);
    const uint32_t* uBlo = reinterpret_cast<const uint32_t*>(sBlo);

    const int tid = threadIdx.x;
    const int wid = tid >> 5;
    const int lid = tid & 31;
    const int m0 = blockIdx.y * 128;
    const int n0 = blockIdx.x * 128;
    const int wm = (wid & 3) * 32;
    const int wn = (wid >> 2) * 64;
    const int gr = lid >> 2;
    const int gc = (lid & 3) * 2;

    const uint4* gAhi = reinterpret_cast<const uint4*>(Ahi);
    const uint4* gAlo = reinterpret_cast<const uint4*>(Alo);
    const uint4* gBhi = reinterpret_cast<const uint4*>(Bhi);
    const uint4* gBlo = reinterpret_cast<const uint4*>(Blo);

    float acc[2][8][4];
#pragma unroll
    for (int mf = 0; mf < 2; mf++)
#pragma unroll
        for (int nf = 0; nf < 8; nf++)
#pragma unroll
            for (int e = 0; e < 4; e++) acc[mf][nf][e] = 0.f;

    for (int kc = 0; kc < 1024 / KTILE; kc++) {
#pragma unroll
        for (int i = 0; i < 4; i++) {
            int idx = tid + i * 256;
            int r = idx >> 3, c = idx & 7;
            size_t g = (size_t)(m0 + r) * 128 + kc * 8 + c;
            size_t s = ((size_t)r * KPAD + c * 8) / 8;
            reinterpret_cast<uint4*>(sAhi)[s] = gAhi[g];
            reinterpret_cast<uint4*>(sAlo)[s] = gAlo[g];
            size_t gb = (size_t)(n0 + r) * 128 + kc * 8 + c;
            reinterpret_cast<uint4*>(sBhi)[s] = gBhi[gb];
            reinterpret_cast<uint4*>(sBlo)[s] = gBlo[gb];
        }
        __syncthreads();

#pragma unroll
        for (int ks = 0; ks < 4; ks++) {
            const int k0 = ks * 16;
            uint32_t ah[2][4], al[2][4];
#pragma unroll
            for (int mf = 0; mf < 2; mf++) {
                int r0 = wm + mf * 16 + gr;
                int base0 = (r0 * KPAD + k0 + gc) >> 1;
                int base1 = ((r0 + 8) * KPAD + k0 + gc) >> 1;
                ah[mf][0] = uAhi[base0];     al[mf][0] = uAlo[base0];
                ah[mf][1] = uAhi[base1];     al[mf][1] = uAlo[base1];
                ah[mf][2] = uAhi[base0 + 4]; al[mf][2] = uAlo[base0 + 4];
                ah[mf][3] = uAhi[base1 + 4]; al[mf][3] = uAlo[base1 + 4];
            }
            uint32_t bh[8][2], bl[8][2];
#pragma unroll
            for (int nf = 0; nf < 8; nf++) {
                int r = wn + nf * 8 + gr;
                int base = (r * KPAD + k0 + gc) >> 1;
                bh[nf][0] = uBhi[base];     bl[nf][0] = uBlo[base];
                bh[nf][1] = uBhi[base + 4]; bl[nf][1] = uBlo[base + 4];
            }
#pragma unroll
            for (int mf = 0; mf < 2; mf++)
#pragma unroll
                for (int nf = 0; nf < 8; nf++) {
                    mma16816(acc[mf][nf], ah[mf][0], ah[mf][1], ah[mf][2], ah[mf][3],
                             bh[nf][0], bh[nf][1]);
                    mma16816(acc[mf][nf], ah[mf][0], ah[mf][1], ah[mf][2], ah[mf][3],
                             bl[nf][0], bl[nf][1]);
                    mma16816(acc[mf][nf], al[mf][0], al[mf][1], al[mf][2], al[mf][3],
                             bh[nf][0], bh[nf][1]);
                }
        }
        __syncthreads();
    }

#pragma unroll
    for (int mf = 0; mf < 2; mf++) {
        int r0 = m0 + wm + mf * 16 + gr;
        int r1 = r0 + 8;
#pragma unroll
        for (int nf = 0; nf < 8; nf++) {
            int col = n0 + wn + nf * 8 + gc;
            *reinterpret_cast<float2*>(&C[(size_t)r0 * N + col]) =
                make_float2(acc[mf][nf][0], acc[mf][nf][1]);
            *reinterpret_cast<float2*>(&C[(size_t)r1 * N + col]) =
                make_float2(acc[mf][nf][2], acc[mf][nf][3]);
        }
    }
}

// ---------------------------------------------------------------------------
// fp32 tiled SGEMM (A-projections only)
// ---------------------------------------------------------------------------
__global__ __launch_bounds__(256) void gemm_a_kernel(
    const float* __restrict__ A0, const float* __restrict__ W0, float* __restrict__ C0, int N0,
    const float* __restrict__ A1, const float* __restrict__ W1, float* __restrict__ C1, int N1,
    const float* __restrict__ A2, const float* __restrict__ W2, float* __restrict__ C2, int N2,
    int M, int K)
{
    const float* A = A0; const float* W = W0; float* C = C0; int N = N0;
    {
        int z = blockIdx.z;
        if (z == 1) { A = A1; W = W1; C = C1; N = N1; }
        else if (z == 2) { A = A2; W = W2; C = C2; N = N2; }
    }

    __shared__ float As[16][132];
    __shared__ float Ws[16][64];

    const int tid = threadIdx.x;
    const int tm = (tid & 15) * 8;
    const int tn = (tid >> 4) * 4;
    const int m0 = blockIdx.y * 128;
    const int n0 = blockIdx.x * 64;
    if (n0 >= N) return;

    float acc[8][4];
#pragma unroll
    for (int i = 0; i < 8; i++)
#pragma unroll
        for (int j = 0; j < 4; j++) acc[i][j] = 0.f;

    for (int k0 = 0; k0 < K; k0 += 16) {
#pragma unroll
        for (int i = 0; i < 2; i++) {
            int idx = tid + i * 256;
            int r = idx >> 2, c4 = (idx & 3) * 4;
            float4 a = *reinterpret_cast<const float4*>(A + (size_t)(m0 + r) * K + k0 + c4);
            As[c4 + 0][r] = a.x; As[c4 + 1][r] = a.y;
            As[c4 + 2][r] = a.z; As[c4 + 3][r] = a.w;
        }
        {
            int r = tid >> 4, c4 = (tid & 15) * 4;
            int gn = n0 + c4;
            float4 w = (gn < N)
                ? *reinterpret_cast<const float4*>(W + (size_t)(k0 + r) * N + gn)
                : make_float4(0.f, 0.f, 0.f, 0.f);
            *reinterpret_cast<float4*>(&Ws[r][c4]) = w;
        }
        __syncthreads();

#pragma unroll
        for (int kk = 0; kk < 16; kk++) {
            float af[8], bf[4];
            *reinterpret_cast<float4*>(&af[0]) = *reinterpret_cast<float4*>(&As[kk][tm]);
            *reinterpret_cast<float4*>(&af[4]) = *reinterpret_cast<float4*>(&As[kk][tm + 4]);
            *reinterpret_cast<float4*>(&bf[0]) = *reinterpret_cast<float4*>(&Ws[kk][tn]);
#pragma unroll
            for (int i = 0; i < 8; i++)
#pragma unroll
                for (int j = 0; j < 4; j++) acc[i][j] += af[i] * bf[j];
        }
        __syncthreads();
    }

#pragma unroll
    for (int i = 0; i < 8; i++) {
        int gm = m0 + tm + i;
        int gn = n0 + tn;
        if (gn < N) {
            *reinterpret_cast<float4*>(&C[(size_t)gm * N + gn]) =
                make_float4(acc[i][0], acc[i][1], acc[i][2], acc[i][3]);
        }
    }
}

// ---------------------------------------------------------------------------
// RoPE in-place on X[NTOK][R][DK]
// ---------------------------------------------------------------------------
__global__ void rope_kernel(float* __restrict__ X, int R, int total)
{
    int idx = blockIdx.x * blockDim.x + threadIdx.x;
    if (idx >= total) return;
    int i = idx & 31;
    int r = (idx >> 5) % R;
    int t = idx / (32 * R);
    int s = t & (SEQ - 1);

    float inv_freq = powf(10000.0f, -(float)(2 * i) / 64.0f);
    float fr = (float)s * inv_freq;
    float sn, cs;
    sincosf(fr, &sn, &cs);

    float* base = X + ((size_t)t * R + r) * DK;
    float x1 = base[i];
    float x2 = base[32 + i];
    base[i]      = x1 * cs + x2 * sn;
    base[32 + i] = -x1 * sn + x2 * cs;
}

// ---------------------------------------------------------------------------
// Rank contractions.
// contract_qk: -> bf16 hi/lo at [bh][s][dk] (scale folded)
// contract_v:  -> fp32 at [bh][s][dk]
// ---------------------------------------------------------------------------
__global__ void contract_qk_kernel(const float* __restrict__ Am,
                                   const float* __restrict__ Bm,
                                   __nv_bfloat16* __restrict__ hi,
                                   __nv_bfloat16* __restrict__ lo,
                                   int R, float scale)
{
    int idx = blockIdx.x * blockDim.x + threadIdx.x;
    if (idx >= NTOK * HEADS * DK) return;
    int d = idx & (DK - 1);
    int h = (idx >> 6) & (HEADS - 1);
    int t = idx >> 10;

    const float* a = Am + (size_t)t * (HEADS * R) + h * R;
    const float* b = Bm + (size_t)t * R * DK + d;
    float s = 0.f;
#pragma unroll 6
    for (int r = 0; r < R; r++) s += a[r] * b[r * DK];
    s *= scale;

    int bb = t >> 11;
    int ss = t & (SEQ - 1);
    size_t o = (((size_t)(bb * HEADS + h)) * SEQ + ss) * DK + d;
    __nv_bfloat16 hv = __float2bfloat16(s);
    hi[o] = hv;
    lo[o] = __float2bfloat16(s - __bfloat162float(hv));
}

__global__ void contract_v_kernel(const float* __restrict__ Am,
                                  const float* __restrict__ Bm,
                                  float* __restrict__ out, int R, float scale)
{
    int idx = blockIdx.x * blockDim.x + threadIdx.x;
    if (idx >= NTOK * HEADS * DK) return;
    int d = idx & (DK - 1);
    int h = (idx >> 6) & (HEADS - 1);
    int t = idx >> 10;

    const float* a = Am + (size_t)t * (HEADS * R) + h * R;
    const float* b = Bm + (size_t)t * R * DK + d;
    float s = 0.f;
#pragma unroll 2
    for (int r = 0; r < R; r++) s += a[r] * b[r * DK];

    int bb = t >> 11;
    int ss = t & (SEQ - 1);
    out[(((size_t)(bb * HEADS + h)) * SEQ + ss) * DK + d] = s * scale;
}

// ---------------------------------------------------------------------------
// HMMA causal flash attention.
// grid (SEQ/64, BH), 128 threads = 4 warps; warp w owns q rows qt*64+w*16..+15.
// K tile 64 keys. Q/K bf16 hi/lo [bh][s][dk]; V^T hi/lo [bh][dk][S].
// 3-product hi/lo for both QK and PV; fp32 softmax state.
// ---------------------------------------------------------------------------
#define FPAD 72   // bf16 per smem row; uint32 stride 36

__global__ __launch_bounds__(128) void flash_mma_kernel(
    const __nv_bfloat16* __restrict__ Qhi, const __nv_bfloat16* __restrict__ Qlo,
    const __nv_bfloat16* __restrict__ Khi, const __nv_bfloat16* __restrict__ Klo,
    const __nv_bfloat16* __restrict__ Vthi, const __nv_bfloat16* __restrict__ Vtlo,
    float* __restrict__ O)
{
    __shared__ __nv_bfloat16 sKhi[64 * FPAD], sKlo[64 * FPAD];
    __shared__ __nv_bfloat16 sVhi[64 * FPAD], sVlo[64 * FPAD];
    const uint32_t* uKhi = reinterpret_cast<const uint32_t*>(sKhi);
    const uint32_t* uKlo = reinterpret_cast<const uint32_t*>(sKlo);
    const uint32_t* uVhi = reinterpret_cast<const uint32_t*>(sVhi);
    const uint32_t* uVlo = reinterpret_cast<const uint32_t*>(sVlo);

    const int bh = blockIdx.y;
    const int qt = (gridDim.x - 1) - blockIdx.x;    // heaviest first
    const int tid = threadIdx.x;
    const int wid = tid >> 5;
    const int lid = tid & 31;
    const int gr = lid >> 2;          // 0..7
    const int gc = lid & 3;           // 0..3 (pair units)
    const int q0 = qt * 64 + wid * 16;

    // Q fragments (hi & lo): 4 ksteps x 4 regs
    uint32_t qfh[4][4], qfl[4][4];
#pragma unroll
    for (int ks = 0; ks < 4; ks++)
#pragma unroll
        for (int i = 0; i < 4; i++) {
            int row = q0 + gr + (i & 1) * 8;
            int col = ks * 16 + gc * 2 + (i >> 1) * 8;
            size_t g = ((size_t)bh * SEQ + row) * DK + col;
            qfh[ks][i] = *reinterpret_cast<const uint32_t*>(&Qhi[g]);
            qfl[ks][i] = *reinterpret_cast<const uint32_t*>(&Qlo[g]);
        }

    float accO[8][4];
#pragma unroll
    for (int nf = 0; nf < 8; nf++)
#pragma unroll
        for (int e = 0; e < 4; e++) accO[nf][e] = 0.f;
    float m0 = -INFINITY, m1 = -INFINITY, l0 = 0.f, l1 = 0.f;

    const uint4* gKhi = reinterpret_cast<const uint4*>(Khi);
    const uint4* gKlo = reinterpret_cast<const uint4*>(Klo);
    const uint4* gVhi = reinterpret_cast<const uint4*>(Vthi);
    const uint4* gVlo = reinterpret_cast<const uint4*>(Vtlo);

    for (int kt = 0; kt <= qt; kt++) {
        // ---- G2S: K tile [64 keys][64 dk], V^T tile [64 dk][64 keys]
#pragma unroll
        for (int i = 0; i < 4; i++) {
            int idx = tid + i * 128;
            int r = idx >> 3, c = idx & 7;
            size_t so = ((size_t)r * FPAD + c * 8) / 8;
            size_t gk = ((size_t)bh * SEQ + kt * 64 + r) * (DK / 8) + c;
            reinterpret_cast<uint4*>(sKhi)[so] = gKhi[gk];
            reinterpret_cast<uint4*>(sKlo)[so] = gKlo[gk];
            size_t gv = ((size_t)bh * DK + r) * (SEQ / 8) + (kt * 64) / 8 + c;
            reinterpret_cast<uint4*>(sVhi)[so] = gVhi[gv];
            reinterpret_cast<uint4*>(sVlo)[so] = gVlo[gv];
        }
        __syncthreads();

        // ---- S = Q K^T (hi/lo 3-product)
        float sacc[8][4];
#pragma unroll
        for (int nf = 0; nf < 8; nf++)
#pragma unroll
            for (int e = 0; e < 4; e++) sacc[nf][e] = 0.f;

#pragma unroll
        for (int ks = 0; ks < 4; ks++) {
#pragma unroll
            for (int nf = 0; nf < 8; nf++) {
                int w = (nf * 8 + gr) * 36 + ks * 8 + gc;
                uint32_t bh0 = uKhi[w], bh1 = uKhi[w + 4];
                uint32_t bl0 = uKlo[w], bl1 = uKlo[w + 4];
                mma16816(sacc[nf], qfh[ks][0], qfh[ks][1], qfh[ks][2], qfh[ks][3], bh0, bh1);
                mma16816(sacc[nf], qfh[ks][0], qfh[ks][1], qfh[ks][2], qfh[ks][3], bl0, bl1);
                mma16816(sacc[nf], qfl[ks][0], qfl[ks][1], qfl[ks][2], qfl[ks][3], bh0, bh1);
            }
        }

        // ---- causal mask (diagonal tile only)
        if (kt == qt) {
            const int kg0 = kt * 64;
#pragma unroll
            for (int nf = 0; nf < 8; nf++) {
                int key = kg0 + nf * 8 + gc * 2;
                int r0 = q0 + gr, r1 = r0 + 8;
                if (key > r0)     sacc[nf][0] = -INFINITY;
                if (key + 1 > r0) sacc[nf][1] = -INFINITY;
                if (key > r1)     sacc[nf][2] = -INFINITY;
                if (key + 1 > r1) sacc[nf][3] = -INFINITY;
            }
        }

        // ---- online softmax (rows gr / gr+8; quad = lanes sharing gr)
        float mx0 = -INFINITY, mx1 = -INFINITY;
#pragma unroll
        for (int nf = 0; nf < 8; nf++) {
            mx0 = fmaxf(mx0, fmaxf(sacc[nf][0], sacc[nf][1]));
            mx1 = fmaxf(mx1, fmaxf(sacc[nf][2], sacc[nf][3]));
        }
        mx0 = fmaxf(mx0, __shfl_xor_sync(0xffffffffu, mx0, 1));
        mx0 = fmaxf(mx0, __shfl_xor_sync(0xffffffffu, mx0, 2));
        mx1 = fmaxf(mx1, __shfl_xor_sync(0xffffffffu, mx1, 1));
        mx1 = fmaxf(mx1, __shfl_xor_sync(0xffffffffu, mx1, 2));

        float mn0 = fmaxf(m0, mx0), mn1 = fmaxf(m1, mx1);
        float f0 = __expf(m0 - mn0), f1 = __expf(m1 - mn1);
        m0 = mn0; m1 = mn1;

        float sum0 = 0.f, sum1 = 0.f;
#pragma unroll
        for (int nf = 0; nf < 8; nf++) {
            sacc[nf][0] = __expf(sacc[nf][0] - mn0);
            sacc[nf][1] = __expf(sacc[nf][1] - mn0);
            sacc[nf][2] = __expf(sacc[nf][2] - mn1);
            sacc[nf][3] = __expf(sacc[nf][3] - mn1);
            sum0 += sacc[nf][0] + sacc[nf][1];
            sum1 += sacc[nf][2] + sacc[nf][3];
        }
        sum0 += __shfl_xor_sync(0xffffffffu, sum0, 1);
        sum0 += __shfl_xor_sync(0xffffffffu, sum0, 2);
        sum1 += __shfl_xor_sync(0xffffffffu, sum1, 1);
        sum1 += __shfl_xor_sync(0xffffffffu, sum1, 2);
        l0 = l0 * f0 + sum0;
        l1 = l1 * f1 + sum1;

#pragma unroll
        for (int nf = 0; nf < 8; nf++) {
            accO[nf][0] *= f0; accO[nf][1] *= f0;
            accO[nf][2] *= f1; accO[nf][3] *= f1;
        }

        // ---- pack P into bf16 hi/lo A-fragments (pair S-frags 2j, 2j+1)
        uint32_t pah[4][4], pal[4][4];
#pragma unroll
        for (int j = 0; j < 4; j++) {
            float p00 = sacc[2 * j][0],     p01 = sacc[2 * j][1];
            float p02 = sacc[2 * j][2],     p03 = sacc[2 * j][3];
            float p10 = sacc[2 * j + 1][0], p11 = sacc[2 * j + 1][1];
            float p12 = sacc[2 * j + 1][2], p13 = sacc[2 * j + 1][3];
            pah[j][0] = packbf2(p00, p01);
            pah[j][1] = packbf2(p02, p03);
            pah[j][2] = packbf2(p10, p11);
            pah[j][3] = packbf2(p12, p13);
            float r00 = p00 - __bfloat162float(__float2bfloat16(p00));
            float r01 = p01 - __bfloat162float(__float2bfloat16(p01));
            float r02 = p02 - __bfloat162float(__float2bfloat16(p02));
            float r03 = p03 - __bfloat162float(__float2bfloat16(p03));
            float r10 = p10 - __bfloat162float(__float2bfloat16(p10));
            float r11 = p11 - __bfloat162float(__float2bfloat16(p11));
            float r12 = p12 - __bfloat162float(__float2bfloat16(p12));
            float r13 = p13 - __bfloat162float(__float2bfloat16(p13));
            pal[j][0] = packbf2(r00, r01);
            pal[j][1] = packbf2(r02, r03);
            pal[j][2] = packbf2(r10, r11);
            pal[j][3] = packbf2(r12, r13);
        }

        // ---- O += P V  (hi/lo 3-product); B-frag from V^T [dk][key]
#pragma unroll
        for (int ks = 0; ks < 4; ks++) {
#pragma unroll
            for (int nf = 0; nf < 8; nf++) {
                int w = (nf * 8 + gr) * 36 + ks * 8 + gc;
                uint32_t vh0 = uVhi[w], vh1 = uVhi[w + 4];
                uint32_t vl0 = uVlo[w], vl1 = uVlo[w + 4];
                mma16816(accO[nf], pah[ks][0], pah[ks][1], pah[ks][2], pah[ks][3], vh0, vh1);
                mma16816(accO[nf], pah[ks][0], pah[ks][1], pah[ks][2], pah[ks][3], vl0, vl1);
                mma16816(accO[nf], pal[ks][0], pal[ks][1], pal[ks][2], pal[ks][3], vh0, vh1);
            }
        }
        __syncthreads();
    }

    // ---- epilogue
    const int b = bh >> 4;
    const int h = bh & 15;
    const float inv0 = 1.0f / l0, inv1 = 1.0f / l1;
    const int r0 = q0 + gr, r1 = r0 + 8;
#pragma unroll
    for (int nf = 0; nf < 8; nf++) {
        int col = h * DK + nf * 8 + gc * 2;
        *reinterpret_cast<float2*>(&O[((size_t)(b * SEQ) + r0) * DMODEL + col]) =
            make_float2(accO[nf][0] * inv0, accO[nf][1] * inv0);
        *reinterpret_cast<float2*>(&O[((size_t)(b * SEQ) + r1) * DMODEL + col]) =
            make_float2(accO[nf][2] * inv1, accO[nf][3] * inv1);
    }
}

// ---------------------------------------------------------------------------
extern "C" void kernel_launch(void* const* d_in, const int* in_sizes, int n_in,
                              void* d_out, int out_size)
{
    const float* q    = (const float*)d_in[0];
    const float* k    = (const float*)d_in[1];
    const float* v    = (const float*)d_in[2];
    const float* W_Aq = (const float*)d_in[4];
    const float* W_Ak = (const float*)d_in[5];
    const float* W_Av = (const float*)d_in[6];
    const float* W_Bq = (const float*)d_in[7];
    const float* W_Bk = (const float*)d_in[8];
    const float* W_Bv = (const float*)d_in[9];
    const float* Wo   = (const float*)d_in[10];
    float* out = (float*)d_out;

    float* scratch = nullptr;
    cudaGetSymbolAddress((void**)&scratch, g_scratch);
    __nv_bfloat16* bscratch = nullptr;
    cudaGetSymbolAddress((void**)&bscratch, g_bf);

    float* sAq = scratch + OFF_AQ;
    float* sAk = scratch + OFF_AK;
    float* sAv = scratch + OFF_AV;
    float* sBq = scratch + OFF_BQ;
    float* sBk = scratch + OFF_BK;
    float* sBv = scratch + OFF_BV;
    float* sVh = scratch + OFF_VH;
    float* sOa = scratch + OFF_OA;

    __nv_bfloat16* bQhi  = bscratch + BOFF_QHI;
    __nv_bfloat16* bQlo  = bscratch + BOFF_QLO;
    __nv_bfloat16* bKhi  = bscratch + BOFF_KHI;
    __nv_bfloat16* bKlo  = bscratch + BOFF_KLO;
    __nv_bfloat16* bVhi  = bscratch + BOFF_VHI;
    __nv_bfloat16* bVlo  = bscratch + BOFF_VLO;
    __nv_bfloat16* bOhi  = bscratch + BOFF_OAHI;
    __nv_bfloat16* bOlo  = bscratch + BOFF_OALO;
    __nv_bfloat16* wBqHi = bscratch + BOFF_WBQ_HI;
    __nv_bfloat16* wBqLo = bscratch + BOFF_WBQ_LO;
    __nv_bfloat16* wBkHi = bscratch + BOFF_WBK_HI;
    __nv_bfloat16* wBkLo = bscratch + BOFF_WBK_LO;
    __nv_bfloat16* wBvHi = bscratch + BOFF_WBV_HI;
    __nv_bfloat16* wBvLo = bscratch + BOFF_WBV_LO;
    __nv_bfloat16* wOHi  = bscratch + BOFF_WO_HI;
    __nv_bfloat16* wOLo  = bscratch + BOFF_WO_LO;
    __nv_bfloat16* fQhi  = bscratch + BOFF_FQHI;
    __nv_bfloat16* fQlo  = bscratch + BOFF_FQLO;
    __nv_bfloat16* fKhi  = bscratch + BOFF_FKHI;
    __nv_bfloat16* fKlo  = bscratch + BOFF_FKLO;
    __nv_bfloat16* fVthi = bscratch + BOFF_FVTHI;
    __nv_bfloat16* fVtlo = bscratch + BOFF_FVTLO;

    const int TCSMEM = 4 * TILEB;
    cudaFuncSetAttribute(tc_gemm_kernel,
                         cudaFuncAttributeMaxDynamicSharedMemorySize, TCSMEM);

    const int MY = NTOK / 128;   // 32

    // 0) precision prep
    split_kernel<<<(TOKD + 255) / 256, 256>>>(q, bQhi, bQlo, TOKD);
    split_kernel<<<(TOKD + 255) / 256, 256>>>(k, bKhi, bKlo, TOKD);
    split_kernel<<<(TOKD + 255) / 256, 256>>>(v, bVhi, bVlo, TOKD);
    tsplit_kernel<<<dim3(384 / 32, 1024 / 32), dim3(32, 8)>>>(W_Bq, wBqHi, wBqLo, 1024, 384);
    tsplit_kernel<<<dim3(128 / 32, 1024 / 32), dim3(32, 8)>>>(W_Bk, wBkHi, wBkLo, 1024, 128);
    tsplit_kernel<<<dim3(128 / 32, 1024 / 32), dim3(32, 8)>>>(W_Bv, wBvHi, wBvLo, 1024, 128);
    tsplit_kernel<<<dim3(1024 / 32, 1024 / 32), dim3(32, 8)>>>(Wo, wOHi, wOLo, 1024, 1024);

    // 1) A-projections (fp32, batched)
    gemm_a_kernel<<<dim3(2, MY, 3), 256>>>(
        q, W_Aq, sAq, 96,
        k, W_Ak, sAk, 32,
        v, W_Av, sAv, 32,
        NTOK, DMODEL);

    // 2) B-projections (HMMA)
    tc_gemm_kernel<<<dim3(3, MY), 256, TCSMEM>>>(bQhi, bQlo, wBqHi, wBqLo, sBq, 384);
    tc_gemm_kernel<<<dim3(1, MY), 256, TCSMEM>>>(bKhi, bKlo, wBkHi, wBkLo, sBk, 128);
    tc_gemm_kernel<<<dim3(1, MY), 256, TCSMEM>>>(bVhi, bVlo, wBvHi, wBvLo, sBv, 128);

    // 3) RoPE
    {
        int total_q = NTOK * QRANK * 32;
        int total_k = NTOK * RANK * 32;
        rope_kernel<<<(total_q + 255) / 256, 256>>>(sBq, QRANK, total_q);
        rope_kernel<<<(total_k + 255) / 256, 256>>>(sBk, RANK, total_k);
    }

    // 4) rank contractions (q/k -> bf16 hi/lo, scale folded; v -> fp32)
    {
        int total = NTOK * HEADS * DK;
        contract_qk_kernel<<<(total + 255) / 256, 256>>>(
            sAq, sBq, fQhi, fQlo, QRANK, 1.0f / (QRANK * DK));
        contract_qk_kernel<<<(total + 255) / 256, 256>>>(
            sAk, sBk, fKhi, fKlo, RANK, 1.0f / RANK);
        contract_v_kernel<<<(total + 255) / 256, 256>>>(
            sAv, sBv, sVh, RANK, 1.0f / RANK);
    }

    // 5) V transpose+split -> [bh][dk][S] hi/lo
    vtsplit_kernel<<<dim3(SEQ / 32, DK / 32, BH), dim3(32, 8)>>>(sVh, fVthi, fVtlo);

    // 6) HMMA causal flash attention
    flash_mma_kernel<<<dim3(SEQ / 64, BH), 128>>>(
        fQhi, fQlo, fKhi, fKlo, fVthi, fVtlo, sOa);

    // 7) output projection (HMMA)
    split_kernel<<<(TOKD + 255) / 256, 256>>>(sOa, bOhi, bOlo, TOKD);
    tc_gemm_kernel<<<dim3(8, MY), 256, TCSMEM>>>(bOhi, bOlo, wOHi, wOLo, out, 1024);
}

// round 9
// speedup vs baseline: 3.7459x; 1.1834x over previous
#include <cuda_runtime.h>
#include <cuda_bf16.h>
#include <math.h>
#include <stdint.h>

// ---------------------------------------------------------------------------
// T6Attention — round 9: cp.async-pipelined HMMA flash + fused prep
// B=2, S=2048, D_MODEL=1024, HEADS=16, DK=64, Q_RANK=6, RANK=2
// ---------------------------------------------------------------------------

#define BATCH     2
#define SEQ       2048
#define DMODEL    1024
#define HEADS     16
#define DK        64
#define QRANK     6
#define RANK      2
#define NTOK      (BATCH*SEQ)        // 4096
#define BH        (BATCH*HEADS)      // 32

// fp32 scratch offsets
#define OFF_AQ   0
#define SZ_AQ    (NTOK*HEADS*QRANK)
#define OFF_AK   (OFF_AQ+SZ_AQ)
#define SZ_AK    (NTOK*HEADS*RANK)
#define OFF_AV   (OFF_AK+SZ_AK)
#define SZ_AV    SZ_AK
#define OFF_BQ   (OFF_AV+SZ_AV)
#define SZ_BQ    (NTOK*QRANK*DK)
#define OFF_BK   (OFF_BQ+SZ_BQ)
#define SZ_BK    (NTOK*RANK*DK)
#define OFF_BV   (OFF_BK+SZ_BK)
#define SZ_BV    SZ_BK
#define SCRATCH_TOTAL (OFF_BV+SZ_BV)

__device__ float g_scratch[SCRATCH_TOTAL];

// bf16 scratch offsets (elements);  TOKD == 4194304
#define TOKD          (NTOK*DMODEL)
#define BOFF_QHI      0
#define BOFF_QLO      (BOFF_QHI + TOKD)
#define BOFF_KHI      (BOFF_QLO + TOKD)
#define BOFF_KLO      (BOFF_KHI + TOKD)
#define BOFF_VHI      (BOFF_KLO + TOKD)
#define BOFF_VLO      (BOFF_VHI + TOKD)
#define BOFF_OAHI     (BOFF_VLO + TOKD)
#define BOFF_OALO     (BOFF_OAHI + TOKD)
#define BOFF_WBQ_HI   (BOFF_OALO + TOKD)
#define BOFF_WBQ_LO   (BOFF_WBQ_HI + 384*1024)
#define BOFF_WBK_HI   (BOFF_WBQ_LO + 384*1024)
#define BOFF_WBK_LO   (BOFF_WBK_HI + 128*1024)
#define BOFF_WBV_HI   (BOFF_WBK_LO + 128*1024)
#define BOFF_WBV_LO   (BOFF_WBV_HI + 128*1024)
#define BOFF_WO_HI    (BOFF_WBV_LO + 128*1024)
#define BOFF_WO_LO    (BOFF_WO_HI + 1024*1024)
#define BOFF_FQHI     (BOFF_WO_LO + 1024*1024)
#define BOFF_FQLO     (BOFF_FQHI + TOKD)
#define BOFF_FKHI     (BOFF_FQLO + TOKD)
#define BOFF_FKLO     (BOFF_FKHI + TOKD)
#define BOFF_FVTHI    (BOFF_FKLO + TOKD)
#define BOFF_FVTLO    (BOFF_FVTHI + TOKD)
#define BF_TOTAL      (BOFF_FVTLO + TOKD)

__device__ __nv_bfloat16 g_bf[BF_TOTAL];

// ---------------------------------------------------------------------------
// helpers
// ---------------------------------------------------------------------------
__device__ __forceinline__ void mma16816(float* d,
                                         uint32_t a0, uint32_t a1, uint32_t a2, uint32_t a3,
                                         uint32_t b0, uint32_t b1)
{
    asm volatile(
        "mma.sync.aligned.m16n8k16.row.col.f32.bf16.bf16.f32 "
        "{%0,%1,%2,%3}, {%4,%5,%6,%7}, {%8,%9}, {%0,%1,%2,%3};"
        : "+f"(d[0]), "+f"(d[1]), "+f"(d[2]), "+f"(d[3])
        : "r"(a0), "r"(a1), "r"(a2), "r"(a3), "r"(b0), "r"(b1));
}

__device__ __forceinline__ uint32_t packbf2(float a, float b) {
    __nv_bfloat162 t = __floats2bfloat162_rn(a, b);
    return *reinterpret_cast<uint32_t*>(&t);
}

__device__ __forceinline__ uint32_t smem_u32(const void* p) {
    return (uint32_t)__cvta_generic_to_shared(p);
}

#define CP_ASYNC16(dst_u32, src_ptr) \
    asm volatile("cp.async.cg.shared.global [%0], [%1], 16;" \
        :: "r"(dst_u32), "l"(src_ptr) : "memory")
#define CP_COMMIT() asm volatile("cp.async.commit_group;" ::: "memory")
#define CP_WAIT0()  asm volatile("cp.async.wait_group 0;" ::: "memory")
#define CP_WAIT1()  asm volatile("cp.async.wait_group 1;" ::: "memory")

// ---------------------------------------------------------------------------
// batched hi/lo split for q,k,v (grid.z selects input)
// ---------------------------------------------------------------------------
__global__ void split3_kernel(const float* __restrict__ x0, const float* __restrict__ x1,
                              const float* __restrict__ x2,
                              __nv_bfloat16* __restrict__ h0, __nv_bfloat16* __restrict__ l0p,
                              __nv_bfloat16* __restrict__ h1, __nv_bfloat16* __restrict__ l1p,
                              __nv_bfloat16* __restrict__ h2, __nv_bfloat16* __restrict__ l2p,
                              int n)
{
    const float* x = x0; __nv_bfloat16* hi = h0; __nv_bfloat16* lo = l0p;
    if (blockIdx.z == 1) { x = x1; hi = h1; lo = l1p; }
    else if (blockIdx.z == 2) { x = x2; hi = h2; lo = l2p; }
    int i = blockIdx.x * blockDim.x + threadIdx.x;
    if (i >= n) return;
    float v = x[i];
    __nv_bfloat16 h = __float2bfloat16(v);
    hi[i] = h;
    lo[i] = __float2bfloat16(v - __bfloat162float(h));
}

// ---------------------------------------------------------------------------
// batched transpose + split: 4 weights W[1024,N] -> hi/lo [N,1024]
// grid (32, 32, 4) with skip when n0 >= N
// ---------------------------------------------------------------------------
__global__ void tsplit4_kernel(
    const float* __restrict__ W0, __nv_bfloat16* __restrict__ h0, __nv_bfloat16* __restrict__ l0p, int N0,
    const float* __restrict__ W1, __nv_bfloat16* __restrict__ h1, __nv_bfloat16* __restrict__ l1p, int N1,
    const float* __restrict__ W2, __nv_bfloat16* __restrict__ h2, __nv_bfloat16* __restrict__ l2p, int N2,
    const float* __restrict__ W3, __nv_bfloat16* __restrict__ h3, __nv_bfloat16* __restrict__ l3p, int N3)
{
    const float* W = W0; __nv_bfloat16* hi = h0; __nv_bfloat16* lo = l0p; int N = N0;
    int z = blockIdx.z;
    if (z == 1) { W = W1; hi = h1; lo = l1p; N = N1; }
    else if (z == 2) { W = W2; hi = h2; lo = l2p; N = N2; }
    else if (z == 3) { W = W3; hi = h3; lo = l3p; N = N3; }

    const int n0 = blockIdx.x * 32, k0 = blockIdx.y * 32;
    if (n0 >= N) return;

    __shared__ float t[32][33];
    const int tx = threadIdx.x, ty = threadIdx.y;
#pragma unroll
    for (int i = 0; i < 4; i++)
        t[ty + i * 8][tx] = W[(size_t)(k0 + ty + i * 8) * N + n0 + tx];
    __syncthreads();
#pragma unroll
    for (int i = 0; i < 4; i++) {
        float v = t[tx][ty + i * 8];
        __nv_bfloat16 h = __float2bfloat16(v);
        size_t o = (size_t)(n0 + ty + i * 8) * 1024 + k0 + tx;
        hi[o] = h;
        lo[o] = __float2bfloat16(v - __bfloat162float(h));
    }
}

// ---------------------------------------------------------------------------
// HMMA GEMM, 3-way batched (z selects config; n0>=N blocks skip)
// ---------------------------------------------------------------------------
#define KPAD   72
#define KTILE  64
#define TILEB  (128 * KPAD * 2)

template<int BATCH3>
__global__ __launch_bounds__(256) void tc_gemm_kernel(
    const __nv_bfloat16* __restrict__ Ahi0, const __nv_bfloat16* __restrict__ Alo0,
    const __nv_bfloat16* __restrict__ Bhi0, const __nv_bfloat16* __restrict__ Blo0,
    float* __restrict__ C0, int N0,
    const __nv_bfloat16* __restrict__ Ahi1, const __nv_bfloat16* __restrict__ Alo1,
    const __nv_bfloat16* __restrict__ Bhi1, const __nv_bfloat16* __restrict__ Blo1,
    float* __restrict__ C1, int N1,
    const __nv_bfloat16* __restrict__ Ahi2, const __nv_bfloat16* __restrict__ Alo2,
    const __nv_bfloat16* __restrict__ Bhi2, const __nv_bfloat16* __restrict__ Blo2,
    float* __restrict__ C2, int N2)
{
    const __nv_bfloat16* Ahi = Ahi0; const __nv_bfloat16* Alo = Alo0;
    const __nv_bfloat16* Bhi = Bhi0; const __nv_bfloat16* Blo = Blo0;
    float* C = C0; int N = N0;
    if (BATCH3) {
        int z = blockIdx.z;
        if (z == 1) { Ahi = Ahi1; Alo = Alo1; Bhi = Bhi1; Blo = Blo1; C = C1; N = N1; }
        else if (z == 2) { Ahi = Ahi2; Alo = Alo2; Bhi = Bhi2; Blo = Blo2; C = C2; N = N2; }
    }

    const int n0 = blockIdx.x * 128;
    if (n0 >= N) return;

    extern __shared__ char smem[];
    __nv_bfloat16* sAhi = reinterpret_cast<__nv_bfloat16*>(smem);
    __nv_bfloat16* sAlo = reinterpret_cast<__nv_bfloat16*>(smem + TILEB);
    __nv_bfloat16* sBhi = reinterpret_cast<__nv_bfloat16*>(smem + 2 * TILEB);
    __nv_bfloat16* sBlo = reinterpret_cast<__nv_bfloat16*>(smem + 3 * TILEB);
    const uint32_t* uAhi = reinterpret_cast<const uint32_t*>(sAhi);
    const uint32_t* uAlo = reinterpret_cast<const uint32_t*>(sAlo);
    const uint32_t* uBhi = reinterpret_cast<const uint32_t*>(sBhi);
    const uint32_t* uBlo = reinterpret_cast<const uint32_t*>(sBlo);

    const int tid = threadIdx.x;
    const int wid = tid >> 5;
    const int lid = tid & 31;
    const int m0 = blockIdx.y * 128;
    const int wm = (wid & 3) * 32;
    const int wn = (wid >> 2) * 64;
    const int gr = lid >> 2;
    const int gc = (lid & 3) * 2;

    const uint4* gAhi = reinterpret_cast<const uint4*>(Ahi);
    const uint4* gAlo = reinterpret_cast<const uint4*>(Alo);
    const uint4* gBhi = reinterpret_cast<const uint4*>(Bhi);
    const uint4* gBlo = reinterpret_cast<const uint4*>(Blo);

    float acc[2][8][4];
#pragma unroll
    for (int mf = 0; mf < 2; mf++)
#pragma unroll
        for (int nf = 0; nf < 8; nf++)
#pragma unroll
            for (int e = 0; e < 4; e++) acc[mf][nf][e] = 0.f;

    for (int kc = 0; kc < 1024 / KTILE; kc++) {
#pragma unroll
        for (int i = 0; i < 4; i++) {
            int idx = tid + i * 256;
            int r = idx >> 3, c = idx & 7;
            size_t g = (size_t)(m0 + r) * 128 + kc * 8 + c;
            size_t s = ((size_t)r * KPAD + c * 8) / 8;
            reinterpret_cast<uint4*>(sAhi)[s] = gAhi[g];
            reinterpret_cast<uint4*>(sAlo)[s] = gAlo[g];
            size_t gb = (size_t)(n0 + r) * 128 + kc * 8 + c;
            reinterpret_cast<uint4*>(sBhi)[s] = gBhi[gb];
            reinterpret_cast<uint4*>(sBlo)[s] = gBlo[gb];
        }
        __syncthreads();

#pragma unroll
        for (int ks = 0; ks < 4; ks++) {
            const int k0 = ks * 16;
            uint32_t ah[2][4], al[2][4];
#pragma unroll
            for (int mf = 0; mf < 2; mf++) {
                int r0 = wm + mf * 16 + gr;
                int base0 = (r0 * KPAD + k0 + gc) >> 1;
                int base1 = ((r0 + 8) * KPAD + k0 + gc) >> 1;
                ah[mf][0] = uAhi[base0];     al[mf][0] = uAlo[base0];
                ah[mf][1] = uAhi[base1];     al[mf][1] = uAlo[base1];
                ah[mf][2] = uAhi[base0 + 4]; al[mf][2] = uAlo[base0 + 4];
                ah[mf][3] = uAhi[base1 + 4]; al[mf][3] = uAlo[base1 + 4];
            }
            uint32_t bhf[8][2], blf[8][2];
#pragma unroll
            for (int nf = 0; nf < 8; nf++) {
                int r = wn + nf * 8 + gr;
                int base = (r * KPAD + k0 + gc) >> 1;
                bhf[nf][0] = uBhi[base];     blf[nf][0] = uBlo[base];
                bhf[nf][1] = uBhi[base + 4]; blf[nf][1] = uBlo[base + 4];
            }
#pragma unroll
            for (int mf = 0; mf < 2; mf++)
#pragma unroll
                for (int nf = 0; nf < 8; nf++) {
                    mma16816(acc[mf][nf], ah[mf][0], ah[mf][1], ah[mf][2], ah[mf][3],
                             bhf[nf][0], bhf[nf][1]);
                    mma16816(acc[mf][nf], ah[mf][0], ah[mf][1], ah[mf][2], ah[mf][3],
                             blf[nf][0], blf[nf][1]);
                    mma16816(acc[mf][nf], al[mf][0], al[mf][1], al[mf][2], al[mf][3],
                             bhf[nf][0], bhf[nf][1]);
                }
        }
        __syncthreads();
    }

#pragma unroll
    for (int mf = 0; mf < 2; mf++) {
        int r0 = m0 + wm + mf * 16 + gr;
        int r1 = r0 + 8;
#pragma unroll
        for (int nf = 0; nf < 8; nf++) {
            int col = n0 + wn + nf * 8 + gc;
            *reinterpret_cast<float2*>(&C[(size_t)r0 * N + col]) =
                make_float2(acc[mf][nf][0], acc[mf][nf][1]);
            *reinterpret_cast<float2*>(&C[(size_t)r1 * N + col]) =
                make_float2(acc[mf][nf][2], acc[mf][nf][3]);
        }
    }
}

// ---------------------------------------------------------------------------
// fp32 tiled SGEMM (A-projections, batched)
// ---------------------------------------------------------------------------
__global__ __launch_bounds__(256) void gemm_a_kernel(
    const float* __restrict__ A0, const float* __restrict__ W0, float* __restrict__ C0, int N0,
    const float* __restrict__ A1, const float* __restrict__ W1, float* __restrict__ C1, int N1,
    const float* __restrict__ A2, const float* __restrict__ W2, float* __restrict__ C2, int N2,
    int M, int K)
{
    const float* A = A0; const float* W = W0; float* C = C0; int N = N0;
    {
        int z = blockIdx.z;
        if (z == 1) { A = A1; W = W1; C = C1; N = N1; }
        else if (z == 2) { A = A2; W = W2; C = C2; N = N2; }
    }

    __shared__ float As[16][132];
    __shared__ float Ws[16][64];

    const int tid = threadIdx.x;
    const int tm = (tid & 15) * 8;
    const int tn = (tid >> 4) * 4;
    const int m0 = blockIdx.y * 128;
    const int n0 = blockIdx.x * 64;
    if (n0 >= N) return;

    float acc[8][4];
#pragma unroll
    for (int i = 0; i < 8; i++)
#pragma unroll
        for (int j = 0; j < 4; j++) acc[i][j] = 0.f;

    for (int k0 = 0; k0 < K; k0 += 16) {
#pragma unroll
        for (int i = 0; i < 2; i++) {
            int idx = tid + i * 256;
            int r = idx >> 2, c4 = (idx & 3) * 4;
            float4 a = *reinterpret_cast<const float4*>(A + (size_t)(m0 + r) * K + k0 + c4);
            As[c4 + 0][r] = a.x; As[c4 + 1][r] = a.y;
            As[c4 + 2][r] = a.z; As[c4 + 3][r] = a.w;
        }
        {
            int r = tid >> 4, c4 = (tid & 15) * 4;
            int gn = n0 + c4;
            float4 w = (gn < N)
                ? *reinterpret_cast<const float4*>(W + (size_t)(k0 + r) * N + gn)
                : make_float4(0.f, 0.f, 0.f, 0.f);
            *reinterpret_cast<float4*>(&Ws[r][c4]) = w;
        }
        __syncthreads();

#pragma unroll
        for (int kk = 0; kk < 16; kk++) {
            float af[8], bf[4];
            *reinterpret_cast<float4*>(&af[0]) = *reinterpret_cast<float4*>(&As[kk][tm]);
            *reinterpret_cast<float4*>(&af[4]) = *reinterpret_cast<float4*>(&As[kk][tm + 4]);
            *reinterpret_cast<float4*>(&bf[0]) = *reinterpret_cast<float4*>(&Ws[kk][tn]);
#pragma unroll
            for (int i = 0; i < 8; i++)
#pragma unroll
                for (int j = 0; j < 4; j++) acc[i][j] += af[i] * bf[j];
        }
        __syncthreads();
    }

#pragma unroll
    for (int i = 0; i < 8; i++) {
        int gm = m0 + tm + i;
        int gn = n0 + tn;
        if (gn < N) {
            *reinterpret_cast<float4*>(&C[(size_t)gm * N + gn]) =
                make_float4(acc[i][0], acc[i][1], acc[i][2], acc[i][3]);
        }
    }
}

// ---------------------------------------------------------------------------
// fused RoPE + rank contraction for q/k: reads raw B (pre-RoPE), applies
// rotary inline, contracts with A, writes bf16 hi/lo [bh][s][dk].
// ---------------------------------------------------------------------------
__global__ void contract_rope_kernel(const float* __restrict__ Am,
                                     const float* __restrict__ Bm,
                                     __nv_bfloat16* __restrict__ hi,
                                     __nv_bfloat16* __restrict__ lo,
                                     int R, float scale)
{
    int idx = blockIdx.x * blockDim.x + threadIdx.x;
    if (idx >= NTOK * HEADS * DK) return;
    int d = idx & (DK - 1);
    int h = (idx >> 6) & (HEADS - 1);
    int t = idx >> 10;

    int i = d & 31;
    int s = t & (SEQ - 1);
    float inv_freq = powf(10000.0f, -(float)(2 * i) / 64.0f);
    float fr = (float)s * inv_freq;
    float sn, cs;
    sincosf(fr, &sn, &cs);

    const float* a = Am + (size_t)t * (HEADS * R) + h * R;
    const float* b = Bm + (size_t)t * R * DK;
    float sum = 0.f;
    const bool lohalf = (d < 32);
#pragma unroll 6
    for (int r = 0; r < R; r++) {
        float x1 = b[r * DK + i];
        float x2 = b[r * DK + 32 + i];
        float rv = lohalf ? (x1 * cs + x2 * sn) : (-x1 * sn + x2 * cs);
        sum += a[r] * rv;
    }
    sum *= scale;

    int bb = t >> 11;
    size_t o = (((size_t)(bb * HEADS + h)) * SEQ + s) * DK + d;
    __nv_bfloat16 hv = __float2bfloat16(sum);
    hi[o] = hv;
    lo[o] = __float2bfloat16(sum - __bfloat162float(hv));
}

// ---------------------------------------------------------------------------
// fused V contraction + transpose + split: -> V^T hi/lo [bh][dk][S]
// grid (SEQ/32, DK/32, BH), block (32,8)
// ---------------------------------------------------------------------------
__global__ void fvt_kernel(const float* __restrict__ Am,
                           const float* __restrict__ Bm,
                           __nv_bfloat16* __restrict__ hi,
                           __nv_bfloat16* __restrict__ lo)
{
    __shared__ float vt[32][33];
    const int s0 = blockIdx.x * 32, d0 = blockIdx.y * 32;
    const int bh = blockIdx.z;
    const int b = bh >> 4, h = bh & 15;
    const int tx = threadIdx.x, ty = threadIdx.y;

    // phase 1: compute contraction; vt[d_off][s_off]
#pragma unroll
    for (int i = 0; i < 4; i++) {
        int ss = ty + i * 8;
        int t = b * SEQ + s0 + ss;
        const float* a = Am + (size_t)t * (HEADS * RANK) + h * RANK;
        const float* bp = Bm + (size_t)t * RANK * DK + d0 + tx;
        vt[tx][ss] = (a[0] * bp[0] + a[1] * bp[DK]) * 0.5f;
    }
    __syncthreads();

    // phase 2: write transposed hi/lo, rows = dk, cols = s
#pragma unroll
    for (int i = 0; i < 4; i++) {
        int dd = ty + i * 8;
        float v = vt[dd][tx];
        __nv_bfloat16 hv = __float2bfloat16(v);
        size_t o = ((size_t)bh * DK + d0 + dd) * SEQ + s0 + tx;
        hi[o] = hv;
        lo[o] = __float2bfloat16(v - __bfloat162float(hv));
    }
}

// ---------------------------------------------------------------------------
// HMMA causal flash attention, cp.async 2-stage pipelined.
// grid (SEQ/64, BH), 128 threads = 4 warps; warp owns 16 q rows.
// Epilogue writes bf16 hi/lo directly to [NTOK][DMODEL].
// ---------------------------------------------------------------------------
#define FPAD   72                       // bf16 per smem row (144B)
#define FARR   (64 * FPAD * 2)          // bytes per array   (9216)
#define FSTAGE (4 * FARR)               // Khi,Klo,Vhi,Vlo   (36864)

__global__ __launch_bounds__(128) void flash_mma_kernel(
    const __nv_bfloat16* __restrict__ Qhi, const __nv_bfloat16* __restrict__ Qlo,
    const __nv_bfloat16* __restrict__ Khi, const __nv_bfloat16* __restrict__ Klo,
    const __nv_bfloat16* __restrict__ Vthi, const __nv_bfloat16* __restrict__ Vtlo,
    __nv_bfloat16* __restrict__ Ohi, __nv_bfloat16* __restrict__ Olo)
{
    extern __shared__ char smem[];
    const uint32_t smem_base = smem_u32(smem);

    const int bh = blockIdx.y;
    const int qt = (gridDim.x - 1) - blockIdx.x;    // heaviest first
    const int tid = threadIdx.x;
    const int wid = tid >> 5;
    const int lid = tid & 31;
    const int gr = lid >> 2;
    const int gc = lid & 3;
    const int q0 = qt * 64 + wid * 16;

    // per-thread cp.async source/dest geometry (4 chunks per array)
    int cr[4], cc[4];
    uint32_t sdst[4];
#pragma unroll
    for (int i = 0; i < 4; i++) {
        int idx = tid + i * 128;
        cr[i] = idx >> 3;
        cc[i] = idx & 7;
        sdst[i] = (uint32_t)(cr[i] * FPAD * 2 + cc[i] * 16);
    }

    // Q fragments
    uint32_t qfh[4][4], qfl[4][4];
#pragma unroll
    for (int ks = 0; ks < 4; ks++)
#pragma unroll
        for (int i = 0; i < 4; i++) {
            int row = q0 + gr + (i & 1) * 8;
            int col = ks * 16 + gc * 2 + (i >> 1) * 8;
            size_t g = ((size_t)bh * SEQ + row) * DK + col;
            qfh[ks][i] = *reinterpret_cast<const uint32_t*>(&Qhi[g]);
            qfl[ks][i] = *reinterpret_cast<const uint32_t*>(&Qlo[g]);
        }

    float accO[8][4];
#pragma unroll
    for (int nf = 0; nf < 8; nf++)
#pragma unroll
        for (int e = 0; e < 4; e++) accO[nf][e] = 0.f;
    float m0 = -INFINITY, m1 = -INFINITY, l0 = 0.f, l1 = 0.f;

    const char* pKhi = reinterpret_cast<const char*>(Khi);
    const char* pKlo = reinterpret_cast<const char*>(Klo);
    const char* pVhi = reinterpret_cast<const char*>(Vthi);
    const char* pVlo = reinterpret_cast<const char*>(Vtlo);

    // issue tile kt into stage st
    auto issue = [&](int kt, int st) {
        uint32_t s0a = smem_base + st * FSTAGE;
#pragma unroll
        for (int i = 0; i < 4; i++) {
            size_t gk = 2 * (((size_t)bh * SEQ + kt * 64 + cr[i]) * DK + cc[i] * 8);
            CP_ASYNC16(s0a + sdst[i],            pKhi + gk);
            CP_ASYNC16(s0a + FARR + sdst[i],     pKlo + gk);
            size_t gv = 2 * (((size_t)bh * DK + cr[i]) * SEQ + kt * 64 + cc[i] * 8);
            CP_ASYNC16(s0a + 2 * FARR + sdst[i], pVhi + gv);
            CP_ASYNC16(s0a + 3 * FARR + sdst[i], pVlo + gv);
        }
        CP_COMMIT();
    };

    issue(0, 0);

    for (int kt = 0; kt <= qt; kt++) {
        const int st = kt & 1;
        if (kt < qt) { issue(kt + 1, st ^ 1); CP_WAIT1(); }
        else         { CP_WAIT0(); }
        __syncthreads();

        const uint32_t* uKhi = reinterpret_cast<const uint32_t*>(smem + st * FSTAGE);
        const uint32_t* uKlo = reinterpret_cast<const uint32_t*>(smem + st * FSTAGE + FARR);
        const uint32_t* uVhi = reinterpret_cast<const uint32_t*>(smem + st * FSTAGE + 2 * FARR);
        const uint32_t* uVlo = reinterpret_cast<const uint32_t*>(smem + st * FSTAGE + 3 * FARR);

        // ---- S = Q K^T
        float sacc[8][4];
#pragma unroll
        for (int nf = 0; nf < 8; nf++)
#pragma unroll
            for (int e = 0; e < 4; e++) sacc[nf][e] = 0.f;

#pragma unroll
        for (int ks = 0; ks < 4; ks++) {
#pragma unroll
            for (int nf = 0; nf < 8; nf++) {
                int w = (nf * 8 + gr) * 36 + ks * 8 + gc;
                uint32_t b0 = uKhi[w], b1 = uKhi[w + 4];
                uint32_t c0 = uKlo[w], c1 = uKlo[w + 4];
                mma16816(sacc[nf], qfh[ks][0], qfh[ks][1], qfh[ks][2], qfh[ks][3], b0, b1);
                mma16816(sacc[nf], qfh[ks][0], qfh[ks][1], qfh[ks][2], qfh[ks][3], c0, c1);
                mma16816(sacc[nf], qfl[ks][0], qfl[ks][1], qfl[ks][2], qfl[ks][3], b0, b1);
            }
        }

        // ---- causal mask (diagonal tile only)
        if (kt == qt) {
            const int kg0 = kt * 64;
#pragma unroll
            for (int nf = 0; nf < 8; nf++) {
                int key = kg0 + nf * 8 + gc * 2;
                int r0 = q0 + gr, r1 = r0 + 8;
                if (key > r0)     sacc[nf][0] = -INFINITY;
                if (key + 1 > r0) sacc[nf][1] = -INFINITY;
                if (key > r1)     sacc[nf][2] = -INFINITY;
                if (key + 1 > r1) sacc[nf][3] = -INFINITY;
            }
        }

        // ---- online softmax
        float mx0 = -INFINITY, mx1 = -INFINITY;
#pragma unroll
        for (int nf = 0; nf < 8; nf++) {
            mx0 = fmaxf(mx0, fmaxf(sacc[nf][0], sacc[nf][1]));
            mx1 = fmaxf(mx1, fmaxf(sacc[nf][2], sacc[nf][3]));
        }
        mx0 = fmaxf(mx0, __shfl_xor_sync(0xffffffffu, mx0, 1));
        mx0 = fmaxf(mx0, __shfl_xor_sync(0xffffffffu, mx0, 2));
        mx1 = fmaxf(mx1, __shfl_xor_sync(0xffffffffu, mx1, 1));
        mx1 = fmaxf(mx1, __shfl_xor_sync(0xffffffffu, mx1, 2));

        float mn0 = fmaxf(m0, mx0), mn1 = fmaxf(m1, mx1);
        float f0 = __expf(m0 - mn0), f1 = __expf(m1 - mn1);
        m0 = mn0; m1 = mn1;

        float sum0 = 0.f, sum1 = 0.f;
#pragma unroll
        for (int nf = 0; nf < 8; nf++) {
            sacc[nf][0] = __expf(sacc[nf][0] - mn0);
            sacc[nf][1] = __expf(sacc[nf][1] - mn0);
            sacc[nf][2] = __expf(sacc[nf][2] - mn1);
            sacc[nf][3] = __expf(sacc[nf][3] - mn1);
            sum0 += sacc[nf][0] + sacc[nf][1];
            sum1 += sacc[nf][2] + sacc[nf][3];
        }
        sum0 += __shfl_xor_sync(0xffffffffu, sum0, 1);
        sum0 += __shfl_xor_sync(0xffffffffu, sum0, 2);
        sum1 += __shfl_xor_sync(0xffffffffu, sum1, 1);
        sum1 += __shfl_xor_sync(0xffffffffu, sum1, 2);
        l0 = l0 * f0 + sum0;
        l1 = l1 * f1 + sum1;

#pragma unroll
        for (int nf = 0; nf < 8; nf++) {
            accO[nf][0] *= f0; accO[nf][1] *= f0;
            accO[nf][2] *= f1; accO[nf][3] *= f1;
        }

        // ---- pack P hi/lo
        uint32_t pah[4][4], pal[4][4];
#pragma unroll
        for (int j = 0; j < 4; j++) {
            float p00 = sacc[2 * j][0],     p01 = sacc[2 * j][1];
            float p02 = sacc[2 * j][2],     p03 = sacc[2 * j][3];
            float p10 = sacc[2 * j + 1][0], p11 = sacc[2 * j + 1][1];
            float p12 = sacc[2 * j + 1][2], p13 = sacc[2 * j + 1][3];
            pah[j][0] = packbf2(p00, p01);
            pah[j][1] = packbf2(p02, p03);
            pah[j][2] = packbf2(p10, p11);
            pah[j][3] = packbf2(p12, p13);
            pal[j][0] = packbf2(p00 - __bfloat162float(__float2bfloat16(p00)),
                                p01 - __bfloat162float(__float2bfloat16(p01)));
            pal[j][1] = packbf2(p02 - __bfloat162float(__float2bfloat16(p02)),
                                p03 - __bfloat162float(__float2bfloat16(p03)));
            pal[j][2] = packbf2(p10 - __bfloat162float(__float2bfloat16(p10)),
                                p11 - __bfloat162float(__float2bfloat16(p11)));
            pal[j][3] = packbf2(p12 - __bfloat162float(__float2bfloat16(p12)),
                                p13 - __bfloat162float(__float2bfloat16(p13)));
        }

        // ---- O += P V
#pragma unroll
        for (int ks = 0; ks < 4; ks++) {
#pragma unroll
            for (int nf = 0; nf < 8; nf++) {
                int w = (nf * 8 + gr) * 36 + ks * 8 + gc;
                uint32_t v0 = uVhi[w], v1 = uVhi[w + 4];
                uint32_t u0 = uVlo[w], u1 = uVlo[w + 4];
                mma16816(accO[nf], pah[ks][0], pah[ks][1], pah[ks][2], pah[ks][3], v0, v1);
                mma16816(accO[nf], pah[ks][0], pah[ks][1], pah[ks][2], pah[ks][3], u0, u1);
                mma16816(accO[nf], pal[ks][0], pal[ks][1], pal[ks][2], pal[ks][3], v0, v1);
            }
        }
        __syncthreads();
    }

    // ---- epilogue: write bf16 hi/lo directly
    const int b = bh >> 4;
    const int h = bh & 15;
    const float inv0 = 1.0f / l0, inv1 = 1.0f / l1;
    const int r0 = q0 + gr, r1 = r0 + 8;
#pragma unroll
    for (int nf = 0; nf < 8; nf++) {
        int col = h * DK + nf * 8 + gc * 2;
        size_t o0 = ((size_t)(b * SEQ) + r0) * DMODEL + col;
        size_t o1 = ((size_t)(b * SEQ) + r1) * DMODEL + col;
        float v00 = accO[nf][0] * inv0, v01 = accO[nf][1] * inv0;
        float v10 = accO[nf][2] * inv1, v11 = accO[nf][3] * inv1;
        *reinterpret_cast<uint32_t*>(&Ohi[o0]) = packbf2(v00, v01);
        *reinterpret_cast<uint32_t*>(&Ohi[o1]) = packbf2(v10, v11);
        *reinterpret_cast<uint32_t*>(&Olo[o0]) =
            packbf2(v00 - __bfloat162float(__float2bfloat16(v00)),
                    v01 - __bfloat162float(__float2bfloat16(v01)));
        *reinterpret_cast<uint32_t*>(&Olo[o1]) =
            packbf2(v10 - __bfloat162float(__float2bfloat16(v10)),
                    v11 - __bfloat162float(__float2bfloat16(v11)));
    }
}

// ---------------------------------------------------------------------------
extern "C" void kernel_launch(void* const* d_in, const int* in_sizes, int n_in,
                              void* d_out, int out_size)
{
    const float* q    = (const float*)d_in[0];
    const float* k    = (const float*)d_in[1];
    const float* v    = (const float*)d_in[2];
    const float* W_Aq = (const float*)d_in[4];
    const float* W_Ak = (const float*)d_in[5];
    const float* W_Av = (const float*)d_in[6];
    const float* W_Bq = (const float*)d_in[7];
    const float* W_Bk = (const float*)d_in[8];
    const float* W_Bv = (const float*)d_in[9];
    const float* Wo   = (const float*)d_in[10];
    float* out = (float*)d_out;

    float* scratch = nullptr;
    cudaGetSymbolAddress((void**)&scratch, g_scratch);
    __nv_bfloat16* bscratch = nullptr;
    cudaGetSymbolAddress((void**)&bscratch, g_bf);

    float* sAq = scratch + OFF_AQ;
    float* sAk = scratch + OFF_AK;
    float* sAv = scratch + OFF_AV;
    float* sBq = scratch + OFF_BQ;
    float* sBk = scratch + OFF_BK;
    float* sBv = scratch + OFF_BV;

    __nv_bfloat16* bQhi  = bscratch + BOFF_QHI;
    __nv_bfloat16* bQlo  = bscratch + BOFF_QLO;
    __nv_bfloat16* bKhi  = bscratch + BOFF_KHI;
    __nv_bfloat16* bKlo  = bscratch + BOFF_KLO;
    __nv_bfloat16* bVhi  = bscratch + BOFF_VHI;
    __nv_bfloat16* bVlo  = bscratch + BOFF_VLO;
    __nv_bfloat16* bOhi  = bscratch + BOFF_OAHI;
    __nv_bfloat16* bOlo  = bscratch + BOFF_OALO;
    __nv_bfloat16* wBqHi = bscratch + BOFF_WBQ_HI;
    __nv_bfloat16* wBqLo = bscratch + BOFF_WBQ_LO;
    __nv_bfloat16* wBkHi = bscratch + BOFF_WBK_HI;
    __nv_bfloat16* wBkLo = bscratch + BOFF_WBK_LO;
    __nv_bfloat16* wBvHi = bscratch + BOFF_WBV_HI;
    __nv_bfloat16* wBvLo = bscratch + BOFF_WBV_LO;
    __nv_bfloat16* wOHi  = bscratch + BOFF_WO_HI;
    __nv_bfloat16* wOLo  = bscratch + BOFF_WO_LO;
    __nv_bfloat16* fQhi  = bscratch + BOFF_FQHI;
    __nv_bfloat16* fQlo  = bscratch + BOFF_FQLO;
    __nv_bfloat16* fKhi  = bscratch + BOFF_FKHI;
    __nv_bfloat16* fKlo  = bscratch + BOFF_FKLO;
    __nv_bfloat16* fVthi = bscratch + BOFF_FVTHI;
    __nv_bfloat16* fVtlo = bscratch + BOFF_FVTLO;

    const int TCSMEM = 4 * TILEB;           // 73728
    const int FLSMEM = 2 * FSTAGE;          // 73728
    cudaFuncSetAttribute(tc_gemm_kernel<0>,
                         cudaFuncAttributeMaxDynamicSharedMemorySize, TCSMEM);
    cudaFuncSetAttribute(tc_gemm_kernel<1>,
                         cudaFuncAttributeMaxDynamicSharedMemorySize, TCSMEM);
    cudaFuncSetAttribute(flash_mma_kernel,
                         cudaFuncAttributeMaxDynamicSharedMemorySize, FLSMEM);

    const int MY = NTOK / 128;   // 32

    // 0) input splits (one launch) + weight transpose-splits (one launch)
    split3_kernel<<<dim3((TOKD + 255) / 256, 1, 3), 256>>>(
        q, k, v, bQhi, bQlo, bKhi, bKlo, bVhi, bVlo, TOKD);
    tsplit4_kernel<<<dim3(32, 32, 4), dim3(32, 8)>>>(
        W_Bq, wBqHi, wBqLo, 384,
        W_Bk, wBkHi, wBkLo, 128,
        W_Bv, wBvHi, wBvLo, 128,
        Wo,   wOHi,  wOLo,  1024);

    // 1) A-projections (fp32, batched)
    gemm_a_kernel<<<dim3(2, MY, 3), 256>>>(
        q, W_Aq, sAq, 96,
        k, W_Ak, sAk, 32,
        v, W_Av, sAv, 32,
        NTOK, DMODEL);

    // 2) B-projections (HMMA, one batched launch)
    tc_gemm_kernel<1><<<dim3(3, MY, 3), 256, TCSMEM>>>(
        bQhi, bQlo, wBqHi, wBqLo, sBq, 384,
        bKhi, bKlo, wBkHi, wBkLo, sBk, 128,
        bVhi, bVlo, wBvHi, wBvLo, sBv, 128);

    // 3) fused RoPE + contraction (q, k) and fused V contraction+transpose
    {
        int total = NTOK * HEADS * DK;
        contract_rope_kernel<<<(total + 255) / 256, 256>>>(
            sAq, sBq, fQhi, fQlo, QRANK, 1.0f / (QRANK * DK));
        contract_rope_kernel<<<(total + 255) / 256, 256>>>(
            sAk, sBk, fKhi, fKlo, RANK, 1.0f / RANK);
        fvt_kernel<<<dim3(SEQ / 32, DK / 32, BH), dim3(32, 8)>>>(
            sAv, sBv, fVthi, fVtlo);
    }

    // 4) HMMA causal flash attention (cp.async pipelined), bf16 epilogue
    flash_mma_kernel<<<dim3(SEQ / 64, BH), 128, FLSMEM>>>(
        fQhi, fQlo, fKhi, fKlo, fVthi, fVtlo, bOhi, bOlo);

    // 5) output projection (HMMA)
    tc_gemm_kernel<0><<<dim3(8, MY), 256, TCSMEM>>>(
        bOhi, bOlo, wOHi, wOLo, out, 1024,
        nullptr, nullptr, nullptr, nullptr, nullptr, 0,
        nullptr, nullptr, nullptr, nullptr, nullptr, 0);
}

// round 10
// speedup vs baseline: 4.6825x; 1.2500x over previous
#include <cuda_runtime.h>
#include <cuda_bf16.h>
#include <math.h>
#include <stdint.h>

// ---------------------------------------------------------------------------
// T6Attention — round 10: pipelined HMMA GEMM (all projections), FQ=128 flash
// B=2, S=2048, D_MODEL=1024, HEADS=16, DK=64, Q_RANK=6, RANK=2
// ---------------------------------------------------------------------------

#define BATCH     2
#define SEQ       2048
#define DMODEL    1024
#define HEADS     16
#define DK        64
#define QRANK     6
#define RANK      2
#define NTOK      (BATCH*SEQ)        // 4096
#define BH        (BATCH*HEADS)      // 32

// fp32 scratch offsets
#define OFF_AQ   0
#define SZ_AQ    (NTOK*HEADS*QRANK)
#define OFF_AK   (OFF_AQ+SZ_AQ)
#define SZ_AK    (NTOK*HEADS*RANK)
#define OFF_AV   (OFF_AK+SZ_AK)
#define SZ_AV    SZ_AK
#define OFF_BQ   (OFF_AV+SZ_AV)
#define SZ_BQ    (NTOK*QRANK*DK)
#define OFF_BK   (OFF_BQ+SZ_BQ)
#define SZ_BK    (NTOK*RANK*DK)
#define OFF_BV   (OFF_BK+SZ_BK)
#define SZ_BV    SZ_BK
#define SCRATCH_TOTAL (OFF_BV+SZ_BV)

__device__ float g_scratch[SCRATCH_TOTAL];

// bf16 scratch offsets (elements)
#define TOKD          (NTOK*DMODEL)
#define BOFF_QHI      0
#define BOFF_QLO      (BOFF_QHI + TOKD)
#define BOFF_KHI      (BOFF_QLO + TOKD)
#define BOFF_KLO      (BOFF_KHI + TOKD)
#define BOFF_VHI      (BOFF_KLO + TOKD)
#define BOFF_VLO      (BOFF_VHI + TOKD)
#define BOFF_OAHI     (BOFF_VLO + TOKD)
#define BOFF_OALO     (BOFF_OAHI + TOKD)
#define BOFF_WBQ_HI   (BOFF_OALO + TOKD)
#define BOFF_WBQ_LO   (BOFF_WBQ_HI + 384*1024)
#define BOFF_WBK_HI   (BOFF_WBQ_LO + 384*1024)
#define BOFF_WBK_LO   (BOFF_WBK_HI + 128*1024)
#define BOFF_WBV_HI   (BOFF_WBK_LO + 128*1024)
#define BOFF_WBV_LO   (BOFF_WBV_HI + 128*1024)
#define BOFF_WO_HI    (BOFF_WBV_LO + 128*1024)
#define BOFF_WO_LO    (BOFF_WO_HI + 1024*1024)
#define BOFF_WAQ_HI   (BOFF_WO_LO + 1024*1024)
#define BOFF_WAQ_LO   (BOFF_WAQ_HI + 128*1024)
#define BOFF_WAK_HI   (BOFF_WAQ_LO + 128*1024)
#define BOFF_WAK_LO   (BOFF_WAK_HI + 128*1024)
#define BOFF_WAV_HI   (BOFF_WAK_LO + 128*1024)
#define BOFF_WAV_LO   (BOFF_WAV_HI + 128*1024)
#define BOFF_FQHI     (BOFF_WAV_LO + 128*1024)
#define BOFF_FQLO     (BOFF_FQHI + TOKD)
#define BOFF_FKHI     (BOFF_FQLO + TOKD)
#define BOFF_FKLO     (BOFF_FKHI + TOKD)
#define BOFF_FVTHI    (BOFF_FKLO + TOKD)
#define BOFF_FVTLO    (BOFF_FVTHI + TOKD)
#define BF_TOTAL      (BOFF_FVTLO + TOKD)

__device__ __nv_bfloat16 g_bf[BF_TOTAL];

// ---------------------------------------------------------------------------
// helpers
// ---------------------------------------------------------------------------
__device__ __forceinline__ void mma16816(float* d,
                                         uint32_t a0, uint32_t a1, uint32_t a2, uint32_t a3,
                                         uint32_t b0, uint32_t b1)
{
    asm volatile(
        "mma.sync.aligned.m16n8k16.row.col.f32.bf16.bf16.f32 "
        "{%0,%1,%2,%3}, {%4,%5,%6,%7}, {%8,%9}, {%0,%1,%2,%3};"
        : "+f"(d[0]), "+f"(d[1]), "+f"(d[2]), "+f"(d[3])
        : "r"(a0), "r"(a1), "r"(a2), "r"(a3), "r"(b0), "r"(b1));
}

__device__ __forceinline__ uint32_t packbf2(float a, float b) {
    __nv_bfloat162 t = __floats2bfloat162_rn(a, b);
    return *reinterpret_cast<uint32_t*>(&t);
}

__device__ __forceinline__ uint32_t smem_u32(const void* p) {
    return (uint32_t)__cvta_generic_to_shared(p);
}

#define CP_ASYNC16(dst_u32, src_ptr) \
    asm volatile("cp.async.cg.shared.global [%0], [%1], 16;" \
        :: "r"(dst_u32), "l"(src_ptr) : "memory")
#define CP_COMMIT() asm volatile("cp.async.commit_group;" ::: "memory")
#define CP_WAIT0()  asm volatile("cp.async.wait_group 0;" ::: "memory")
#define CP_WAIT1()  asm volatile("cp.async.wait_group 1;" ::: "memory")

// ---------------------------------------------------------------------------
// batched hi/lo split for q,k,v
// ---------------------------------------------------------------------------
__global__ void split3_kernel(const float* __restrict__ x0, const float* __restrict__ x1,
                              const float* __restrict__ x2,
                              __nv_bfloat16* __restrict__ h0, __nv_bfloat16* __restrict__ l0p,
                              __nv_bfloat16* __restrict__ h1, __nv_bfloat16* __restrict__ l1p,
                              __nv_bfloat16* __restrict__ h2, __nv_bfloat16* __restrict__ l2p,
                              int n)
{
    const float* x = x0; __nv_bfloat16* hi = h0; __nv_bfloat16* lo = l0p;
    if (blockIdx.z == 1) { x = x1; hi = h1; lo = l1p; }
    else if (blockIdx.z == 2) { x = x2; hi = h2; lo = l2p; }
    int i = blockIdx.x * blockDim.x + threadIdx.x;
    if (i >= n) return;
    float v = x[i];
    __nv_bfloat16 h = __float2bfloat16(v);
    hi[i] = h;
    lo[i] = __float2bfloat16(v - __bfloat162float(h));
}

// ---------------------------------------------------------------------------
// batched transpose + split with zero padding: W[1024,N] -> hi/lo [Npad,1024]
// ---------------------------------------------------------------------------
struct TsCfg {
    const float* W;
    __nv_bfloat16* hi;
    __nv_bfloat16* lo;
    int N;
    int Npad;
};
struct TsCfg7 { TsCfg c[7]; };

__global__ void tsplit7_kernel(TsCfg7 p)
{
    TsCfg cfg = p.c[blockIdx.z];
    const int n0 = blockIdx.x * 32, k0 = blockIdx.y * 32;
    if (n0 >= cfg.Npad) return;
    const int tx = threadIdx.x, ty = threadIdx.y;

    if (n0 >= cfg.N) {
        // zero padding rows
#pragma unroll
        for (int i = 0; i < 4; i++) {
            size_t o = (size_t)(n0 + ty + i * 8) * 1024 + k0 + tx;
            cfg.hi[o] = __float2bfloat16(0.f);
            cfg.lo[o] = __float2bfloat16(0.f);
        }
        return;
    }

    __shared__ float t[32][33];
#pragma unroll
    for (int i = 0; i < 4; i++)
        t[ty + i * 8][tx] = cfg.W[(size_t)(k0 + ty + i * 8) * cfg.N + n0 + tx];
    __syncthreads();
#pragma unroll
    for (int i = 0; i < 4; i++) {
        float v = t[tx][ty + i * 8];
        __nv_bfloat16 h = __float2bfloat16(v);
        size_t o = (size_t)(n0 + ty + i * 8) * 1024 + k0 + tx;
        cfg.hi[o] = h;
        cfg.lo[o] = __float2bfloat16(v - __bfloat162float(h));
    }
}

// ---------------------------------------------------------------------------
// HMMA GEMM, cp.async 2-stage pipelined, up to 6 batched configs.
// C[M,N] fp32 = A @ W via bf16 hi/lo (hihi+hilo+lohi). B pre-transposed
// [Npad,1024], Npad multiple of 128, stores guarded by col<N.
// CTA 128x128, 256 thr, 8 warps (4M x 2N), warp 32x64.
// ---------------------------------------------------------------------------
#define KPAD   72
#define GARR   (128 * KPAD * 2)           // bytes per smem array (18432)
#define GSTAGE (4 * GARR)                 // Ahi,Alo,Bhi,Blo      (73728)

struct GemmCfg {
    const __nv_bfloat16 *Ahi, *Alo, *Bhi, *Blo;
    float* C;
    int N;
    int Npad;
};
struct GemmCfg6 { GemmCfg c[6]; };

__global__ __launch_bounds__(256) void tc_gemm_kernel(GemmCfg6 p)
{
    GemmCfg cfg = p.c[blockIdx.z];
    const int n0 = blockIdx.x * 128;
    if (n0 >= cfg.Npad) return;

    extern __shared__ char smem[];
    const uint32_t smem_base = smem_u32(smem);

    const int tid = threadIdx.x;
    const int wid = tid >> 5;
    const int lid = tid & 31;
    const int m0 = blockIdx.y * 128;
    const int wm = (wid & 3) * 32;
    const int wn = (wid >> 2) * 64;
    const int gr = lid >> 2;
    const int gc = (lid & 3) * 2;

    const char* pAhi = reinterpret_cast<const char*>(cfg.Ahi);
    const char* pAlo = reinterpret_cast<const char*>(cfg.Alo);
    const char* pBhi = reinterpret_cast<const char*>(cfg.Bhi);
    const char* pBlo = reinterpret_cast<const char*>(cfg.Blo);

    // per-thread G2S geometry: 4 chunks per array
    int cr[4], cc[4];
    uint32_t sdst[4];
#pragma unroll
    for (int i = 0; i < 4; i++) {
        int idx = tid + i * 256;
        cr[i] = idx >> 3;
        cc[i] = idx & 7;
        sdst[i] = (uint32_t)(cr[i] * (KPAD * 2) + cc[i] * 16);
    }

    auto issue = [&](int kc, int st) {
        uint32_t s0a = smem_base + st * GSTAGE;
#pragma unroll
        for (int i = 0; i < 4; i++) {
            size_t ga = 2 * ((size_t)(m0 + cr[i]) * 1024 + kc * 64 + cc[i] * 8);
            CP_ASYNC16(s0a + sdst[i],            pAhi + ga);
            CP_ASYNC16(s0a + GARR + sdst[i],     pAlo + ga);
            size_t gb = 2 * ((size_t)(n0 + cr[i]) * 1024 + kc * 64 + cc[i] * 8);
            CP_ASYNC16(s0a + 2 * GARR + sdst[i], pBhi + gb);
            CP_ASYNC16(s0a + 3 * GARR + sdst[i], pBlo + gb);
        }
        CP_COMMIT();
    };

    float acc[2][8][4];
#pragma unroll
    for (int mf = 0; mf < 2; mf++)
#pragma unroll
        for (int nf = 0; nf < 8; nf++)
#pragma unroll
            for (int e = 0; e < 4; e++) acc[mf][nf][e] = 0.f;

    issue(0, 0);

    for (int kc = 0; kc < 16; kc++) {
        const int st = kc & 1;
        if (kc + 1 < 16) { issue(kc + 1, st ^ 1); CP_WAIT1(); }
        else             { CP_WAIT0(); }
        __syncthreads();

        const uint32_t* uAhi = reinterpret_cast<const uint32_t*>(smem + st * GSTAGE);
        const uint32_t* uAlo = reinterpret_cast<const uint32_t*>(smem + st * GSTAGE + GARR);
        const uint32_t* uBhi = reinterpret_cast<const uint32_t*>(smem + st * GSTAGE + 2 * GARR);
        const uint32_t* uBlo = reinterpret_cast<const uint32_t*>(smem + st * GSTAGE + 3 * GARR);

#pragma unroll
        for (int ks = 0; ks < 4; ks++) {
            const int k0 = ks * 16;
            uint32_t ah[2][4], al[2][4];
#pragma unroll
            for (int mf = 0; mf < 2; mf++) {
                int r0 = wm + mf * 16 + gr;
                int base0 = (r0 * KPAD + k0 + gc) >> 1;
                int base1 = ((r0 + 8) * KPAD + k0 + gc) >> 1;
                ah[mf][0] = uAhi[base0];     al[mf][0] = uAlo[base0];
                ah[mf][1] = uAhi[base1];     al[mf][1] = uAlo[base1];
                ah[mf][2] = uAhi[base0 + 4]; al[mf][2] = uAlo[base0 + 4];
                ah[mf][3] = uAhi[base1 + 4]; al[mf][3] = uAlo[base1 + 4];
            }
            uint32_t bhf[8][2], blf[8][2];
#pragma unroll
            for (int nf = 0; nf < 8; nf++) {
                int r = wn + nf * 8 + gr;
                int base = (r * KPAD + k0 + gc) >> 1;
                bhf[nf][0] = uBhi[base];     blf[nf][0] = uBlo[base];
                bhf[nf][1] = uBhi[base + 4]; blf[nf][1] = uBlo[base + 4];
            }
#pragma unroll
            for (int mf = 0; mf < 2; mf++)
#pragma unroll
                for (int nf = 0; nf < 8; nf++) {
                    mma16816(acc[mf][nf], ah[mf][0], ah[mf][1], ah[mf][2], ah[mf][3],
                             bhf[nf][0], bhf[nf][1]);
                    mma16816(acc[mf][nf], ah[mf][0], ah[mf][1], ah[mf][2], ah[mf][3],
                             blf[nf][0], blf[nf][1]);
                    mma16816(acc[mf][nf], al[mf][0], al[mf][1], al[mf][2], al[mf][3],
                             bhf[nf][0], bhf[nf][1]);
                }
        }
        __syncthreads();
    }

#pragma unroll
    for (int mf = 0; mf < 2; mf++) {
        int r0 = m0 + wm + mf * 16 + gr;
        int r1 = r0 + 8;
#pragma unroll
        for (int nf = 0; nf < 8; nf++) {
            int col = n0 + wn + nf * 8 + gc;
            if (col < cfg.N) {
                *reinterpret_cast<float2*>(&cfg.C[(size_t)r0 * cfg.N + col]) =
                    make_float2(acc[mf][nf][0], acc[mf][nf][1]);
                *reinterpret_cast<float2*>(&cfg.C[(size_t)r1 * cfg.N + col]) =
                    make_float2(acc[mf][nf][2], acc[mf][nf][3]);
            }
        }
    }
}

// ---------------------------------------------------------------------------
// fused RoPE + rank contraction for q/k -> bf16 hi/lo [bh][s][dk]
// ---------------------------------------------------------------------------
__global__ void contract_rope_kernel(const float* __restrict__ Am,
                                     const float* __restrict__ Bm,
                                     __nv_bfloat16* __restrict__ hi,
                                     __nv_bfloat16* __restrict__ lo,
                                     int R, float scale)
{
    int idx = blockIdx.x * blockDim.x + threadIdx.x;
    if (idx >= NTOK * HEADS * DK) return;
    int d = idx & (DK - 1);
    int h = (idx >> 6) & (HEADS - 1);
    int t = idx >> 10;

    int i = d & 31;
    int s = t & (SEQ - 1);
    float inv_freq = powf(10000.0f, -(float)(2 * i) / 64.0f);
    float fr = (float)s * inv_freq;
    float sn, cs;
    sincosf(fr, &sn, &cs);

    const float* a = Am + (size_t)t * (HEADS * R) + h * R;
    const float* b = Bm + (size_t)t * R * DK;
    float sum = 0.f;
    const bool lohalf = (d < 32);
#pragma unroll 6
    for (int r = 0; r < R; r++) {
        float x1 = b[r * DK + i];
        float x2 = b[r * DK + 32 + i];
        float rv = lohalf ? (x1 * cs + x2 * sn) : (-x1 * sn + x2 * cs);
        sum += a[r] * rv;
    }
    sum *= scale;

    int bb = t >> 11;
    size_t o = (((size_t)(bb * HEADS + h)) * SEQ + s) * DK + d;
    __nv_bfloat16 hv = __float2bfloat16(sum);
    hi[o] = hv;
    lo[o] = __float2bfloat16(sum - __bfloat162float(hv));
}

// ---------------------------------------------------------------------------
// fused V contraction + transpose + split -> V^T hi/lo [bh][dk][S]
// ---------------------------------------------------------------------------
__global__ void fvt_kernel(const float* __restrict__ Am,
                           const float* __restrict__ Bm,
                           __nv_bfloat16* __restrict__ hi,
                           __nv_bfloat16* __restrict__ lo)
{
    __shared__ float vt[32][33];
    const int s0 = blockIdx.x * 32, d0 = blockIdx.y * 32;
    const int bh = blockIdx.z;
    const int b = bh >> 4, h = bh & 15;
    const int tx = threadIdx.x, ty = threadIdx.y;

#pragma unroll
    for (int i = 0; i < 4; i++) {
        int ss = ty + i * 8;
        int t = b * SEQ + s0 + ss;
        const float* a = Am + (size_t)t * (HEADS * RANK) + h * RANK;
        const float* bp = Bm + (size_t)t * RANK * DK + d0 + tx;
        vt[tx][ss] = (a[0] * bp[0] + a[1] * bp[DK]) * 0.5f;
    }
    __syncthreads();

#pragma unroll
    for (int i = 0; i < 4; i++) {
        int dd = ty + i * 8;
        float v = vt[dd][tx];
        __nv_bfloat16 hv = __float2bfloat16(v);
        size_t o = ((size_t)bh * DK + d0 + dd) * SEQ + s0 + tx;
        hi[o] = hv;
        lo[o] = __float2bfloat16(v - __bfloat162float(hv));
    }
}

// ---------------------------------------------------------------------------
// HMMA causal flash attention, FQ=128 (8 warps), cp.async 2-stage.
// grid (SEQ/128, BH), 256 threads; warp owns 16 q rows.
// ---------------------------------------------------------------------------
#define FPAD   72
#define FARR   (64 * FPAD * 2)            // 9216
#define FSTAGE (4 * FARR)                 // 36864

__global__ __launch_bounds__(256) void flash_mma_kernel(
    const __nv_bfloat16* __restrict__ Qhi, const __nv_bfloat16* __restrict__ Qlo,
    const __nv_bfloat16* __restrict__ Khi, const __nv_bfloat16* __restrict__ Klo,
    const __nv_bfloat16* __restrict__ Vthi, const __nv_bfloat16* __restrict__ Vtlo,
    __nv_bfloat16* __restrict__ Ohi, __nv_bfloat16* __restrict__ Olo)
{
    extern __shared__ char smem[];
    const uint32_t smem_base = smem_u32(smem);

    const int bh = blockIdx.y;
    const int qb = (gridDim.x - 1) - blockIdx.x;    // heaviest first
    const int tid = threadIdx.x;
    const int wid = tid >> 5;
    const int lid = tid & 31;
    const int gr = lid >> 2;
    const int gc = lid & 3;
    const int q0 = qb * 128 + wid * 16;

    // G2S geometry: 2 chunks per array per thread
    int cr[2], cc[2];
    uint32_t sdst[2];
#pragma unroll
    for (int i = 0; i < 2; i++) {
        int idx = tid + i * 256;
        cr[i] = idx >> 3;
        cc[i] = idx & 7;
        sdst[i] = (uint32_t)(cr[i] * (FPAD * 2) + cc[i] * 16);
    }

    // Q fragments
    uint32_t qfh[4][4], qfl[4][4];
#pragma unroll
    for (int ks = 0; ks < 4; ks++)
#pragma unroll
        for (int i = 0; i < 4; i++) {
            int row = q0 + gr + (i & 1) * 8;
            int col = ks * 16 + gc * 2 + (i >> 1) * 8;
            size_t g = ((size_t)bh * SEQ + row) * DK + col;
            qfh[ks][i] = *reinterpret_cast<const uint32_t*>(&Qhi[g]);
            qfl[ks][i] = *reinterpret_cast<const uint32_t*>(&Qlo[g]);
        }

    float accO[8][4];
#pragma unroll
    for (int nf = 0; nf < 8; nf++)
#pragma unroll
        for (int e = 0; e < 4; e++) accO[nf][e] = 0.f;
    float m0 = -INFINITY, m1 = -INFINITY, l0 = 0.f, l1 = 0.f;

    const char* pKhi = reinterpret_cast<const char*>(Khi);
    const char* pKlo = reinterpret_cast<const char*>(Klo);
    const char* pVhi = reinterpret_cast<const char*>(Vthi);
    const char* pVlo = reinterpret_cast<const char*>(Vtlo);

    auto issue = [&](int kt, int st) {
        uint32_t s0a = smem_base + st * FSTAGE;
#pragma unroll
        for (int i = 0; i < 2; i++) {
            size_t gk = 2 * (((size_t)bh * SEQ + kt * 64 + cr[i]) * DK + cc[i] * 8);
            CP_ASYNC16(s0a + sdst[i],            pKhi + gk);
            CP_ASYNC16(s0a + FARR + sdst[i],     pKlo + gk);
            size_t gv = 2 * (((size_t)bh * DK + cr[i]) * SEQ + kt * 64 + cc[i] * 8);
            CP_ASYNC16(s0a + 2 * FARR + sdst[i], pVhi + gv);
            CP_ASYNC16(s0a + 3 * FARR + sdst[i], pVlo + gv);
        }
        CP_COMMIT();
    };

    const int ktmax = 2 * qb + 1;
    issue(0, 0);

    for (int kt = 0; kt <= ktmax; kt++) {
        const int st = kt & 1;
        if (kt < ktmax) { issue(kt + 1, st ^ 1); CP_WAIT1(); }
        else            { CP_WAIT0(); }
        __syncthreads();

        const int kg0 = kt * 64;
        if (kg0 <= q0 + 15) {   // not fully masked for this warp
            const uint32_t* uKhi = reinterpret_cast<const uint32_t*>(smem + st * FSTAGE);
            const uint32_t* uKlo = reinterpret_cast<const uint32_t*>(smem + st * FSTAGE + FARR);
            const uint32_t* uVhi = reinterpret_cast<const uint32_t*>(smem + st * FSTAGE + 2 * FARR);
            const uint32_t* uVlo = reinterpret_cast<const uint32_t*>(smem + st * FSTAGE + 3 * FARR);

            // ---- S = Q K^T
            float sacc[8][4];
#pragma unroll
            for (int nf = 0; nf < 8; nf++)
#pragma unroll
                for (int e = 0; e < 4; e++) sacc[nf][e] = 0.f;

#pragma unroll
            for (int ks = 0; ks < 4; ks++) {
#pragma unroll
                for (int nf = 0; nf < 8; nf++) {
                    int w = (nf * 8 + gr) * 36 + ks * 8 + gc;
                    uint32_t b0 = uKhi[w], b1 = uKhi[w + 4];
                    uint32_t c0 = uKlo[w], c1 = uKlo[w + 4];
                    mma16816(sacc[nf], qfh[ks][0], qfh[ks][1], qfh[ks][2], qfh[ks][3], b0, b1);
                    mma16816(sacc[nf], qfh[ks][0], qfh[ks][1], qfh[ks][2], qfh[ks][3], c0, c1);
                    mma16816(sacc[nf], qfl[ks][0], qfl[ks][1], qfl[ks][2], qfl[ks][3], b0, b1);
                }
            }

            // ---- causal mask (warp-diagonal tiles only)
            if (kg0 + 63 > q0) {
#pragma unroll
                for (int nf = 0; nf < 8; nf++) {
                    int key = kg0 + nf * 8 + gc * 2;
                    int r0 = q0 + gr, r1 = r0 + 8;
                    if (key > r0)     sacc[nf][0] = -INFINITY;
                    if (key + 1 > r0) sacc[nf][1] = -INFINITY;
                    if (key > r1)     sacc[nf][2] = -INFINITY;
                    if (key + 1 > r1) sacc[nf][3] = -INFINITY;
                }
            }

            // ---- online softmax
            float mx0 = -INFINITY, mx1 = -INFINITY;
#pragma unroll
            for (int nf = 0; nf < 8; nf++) {
                mx0 = fmaxf(mx0, fmaxf(sacc[nf][0], sacc[nf][1]));
                mx1 = fmaxf(mx1, fmaxf(sacc[nf][2], sacc[nf][3]));
            }
            mx0 = fmaxf(mx0, __shfl_xor_sync(0xffffffffu, mx0, 1));
            mx0 = fmaxf(mx0, __shfl_xor_sync(0xffffffffu, mx0, 2));
            mx1 = fmaxf(mx1, __shfl_xor_sync(0xffffffffu, mx1, 1));
            mx1 = fmaxf(mx1, __shfl_xor_sync(0xffffffffu, mx1, 2));

            float mn0 = fmaxf(m0, mx0), mn1 = fmaxf(m1, mx1);
            float f0 = __expf(m0 - mn0), f1 = __expf(m1 - mn1);
            m0 = mn0; m1 = mn1;

            float sum0 = 0.f, sum1 = 0.f;
#pragma unroll
            for (int nf = 0; nf < 8; nf++) {
                sacc[nf][0] = __expf(sacc[nf][0] - mn0);
                sacc[nf][1] = __expf(sacc[nf][1] - mn0);
                sacc[nf][2] = __expf(sacc[nf][2] - mn1);
                sacc[nf][3] = __expf(sacc[nf][3] - mn1);
                sum0 += sacc[nf][0] + sacc[nf][1];
                sum1 += sacc[nf][2] + sacc[nf][3];
            }
            sum0 += __shfl_xor_sync(0xffffffffu, sum0, 1);
            sum0 += __shfl_xor_sync(0xffffffffu, sum0, 2);
            sum1 += __shfl_xor_sync(0xffffffffu, sum1, 1);
            sum1 += __shfl_xor_sync(0xffffffffu, sum1, 2);
            l0 = l0 * f0 + sum0;
            l1 = l1 * f1 + sum1;

#pragma unroll
            for (int nf = 0; nf < 8; nf++) {
                accO[nf][0] *= f0; accO[nf][1] *= f0;
                accO[nf][2] *= f1; accO[nf][3] *= f1;
            }

            // ---- pack P hi/lo
            uint32_t pah[4][4], pal[4][4];
#pragma unroll
            for (int j = 0; j < 4; j++) {
                float p00 = sacc[2 * j][0],     p01 = sacc[2 * j][1];
                float p02 = sacc[2 * j][2],     p03 = sacc[2 * j][3];
                float p10 = sacc[2 * j + 1][0], p11 = sacc[2 * j + 1][1];
                float p12 = sacc[2 * j + 1][2], p13 = sacc[2 * j + 1][3];
                pah[j][0] = packbf2(p00, p01);
                pah[j][1] = packbf2(p02, p03);
                pah[j][2] = packbf2(p10, p11);
                pah[j][3] = packbf2(p12, p13);
                pal[j][0] = packbf2(p00 - __bfloat162float(__float2bfloat16(p00)),
                                    p01 - __bfloat162float(__float2bfloat16(p01)));
                pal[j][1] = packbf2(p02 - __bfloat162float(__float2bfloat16(p02)),
                                    p03 - __bfloat162float(__float2bfloat16(p03)));
                pal[j][2] = packbf2(p10 - __bfloat162float(__float2bfloat16(p10)),
                                    p11 - __bfloat162float(__float2bfloat16(p11)));
                pal[j][3] = packbf2(p12 - __bfloat162float(__float2bfloat16(p12)),
                                    p13 - __bfloat162float(__float2bfloat16(p13)));
            }

            // ---- O += P V
#pragma unroll
            for (int ks = 0; ks < 4; ks++) {
#pragma unroll
                for (int nf = 0; nf < 8; nf++) {
                    int w = (nf * 8 + gr) * 36 + ks * 8 + gc;
                    uint32_t v0 = uVhi[w], v1 = uVhi[w + 4];
                    uint32_t u0 = uVlo[w], u1 = uVlo[w + 4];
                    mma16816(accO[nf], pah[ks][0], pah[ks][1], pah[ks][2], pah[ks][3], v0, v1);
                    mma16816(accO[nf], pah[ks][0], pah[ks][1], pah[ks][2], pah[ks][3], u0, u1);
                    mma16816(accO[nf], pal[ks][0], pal[ks][1], pal[ks][2], pal[ks][3], v0, v1);
                }
            }
        }
        __syncthreads();
    }

    // ---- epilogue: bf16 hi/lo
    const int b = bh >> 4;
    const int h = bh & 15;
    const float inv0 = 1.0f / l0, inv1 = 1.0f / l1;
    const int r0 = q0 + gr, r1 = r0 + 8;
#pragma unroll
    for (int nf = 0; nf < 8; nf++) {
        int col = h * DK + nf * 8 + gc * 2;
        size_t o0 = ((size_t)(b * SEQ) + r0) * DMODEL + col;
        size_t o1 = ((size_t)(b * SEQ) + r1) * DMODEL + col;
        float v00 = accO[nf][0] * inv0, v01 = accO[nf][1] * inv0;
        float v10 = accO[nf][2] * inv1, v11 = accO[nf][3] * inv1;
        *reinterpret_cast<uint32_t*>(&Ohi[o0]) = packbf2(v00, v01);
        *reinterpret_cast<uint32_t*>(&Ohi[o1]) = packbf2(v10, v11);
        *reinterpret_cast<uint32_t*>(&Olo[o0]) =
            packbf2(v00 - __bfloat162float(__float2bfloat16(v00)),
                    v01 - __bfloat162float(__float2bfloat16(v01)));
        *reinterpret_cast<uint32_t*>(&Olo[o1]) =
            packbf2(v10 - __bfloat162float(__float2bfloat16(v10)),
                    v11 - __bfloat162float(__float2bfloat16(v11)));
    }
}

// ---------------------------------------------------------------------------
extern "C" void kernel_launch(void* const* d_in, const int* in_sizes, int n_in,
                              void* d_out, int out_size)
{
    const float* q    = (const float*)d_in[0];
    const float* k    = (const float*)d_in[1];
    const float* v    = (const float*)d_in[2];
    const float* W_Aq = (const float*)d_in[4];
    const float* W_Ak = (const float*)d_in[5];
    const float* W_Av = (const float*)d_in[6];
    const float* W_Bq = (const float*)d_in[7];
    const float* W_Bk = (const float*)d_in[8];
    const float* W_Bv = (const float*)d_in[9];
    const float* Wo   = (const float*)d_in[10];
    float* out = (float*)d_out;

    float* scratch = nullptr;
    cudaGetSymbolAddress((void**)&scratch, g_scratch);
    __nv_bfloat16* bs = nullptr;
    cudaGetSymbolAddress((void**)&bs, g_bf);

    float* sAq = scratch + OFF_AQ;
    float* sAk = scratch + OFF_AK;
    float* sAv = scratch + OFF_AV;
    float* sBq = scratch + OFF_BQ;
    float* sBk = scratch + OFF_BK;
    float* sBv = scratch + OFF_BV;

    const int GEMSMEM = 2 * GSTAGE;         // 147456
    const int FLSMEM  = 2 * FSTAGE;         // 73728
    cudaFuncSetAttribute(tc_gemm_kernel,
                         cudaFuncAttributeMaxDynamicSharedMemorySize, GEMSMEM);
    cudaFuncSetAttribute(flash_mma_kernel,
                         cudaFuncAttributeMaxDynamicSharedMemorySize, FLSMEM);

    const int MY = NTOK / 128;   // 32

    // 0) input splits + weight transpose-splits
    split3_kernel<<<dim3((TOKD + 255) / 256, 1, 3), 256>>>(
        q, k, v, bs + BOFF_QHI, bs + BOFF_QLO, bs + BOFF_KHI, bs + BOFF_KLO,
        bs + BOFF_VHI, bs + BOFF_VLO, TOKD);

    TsCfg7 ts;
    ts.c[0] = { W_Bq, bs + BOFF_WBQ_HI, bs + BOFF_WBQ_LO, 384, 384 };
    ts.c[1] = { W_Bk, bs + BOFF_WBK_HI, bs + BOFF_WBK_LO, 128, 128 };
    ts.c[2] = { W_Bv, bs + BOFF_WBV_HI, bs + BOFF_WBV_LO, 128, 128 };
    ts.c[3] = { Wo,   bs + BOFF_WO_HI,  bs + BOFF_WO_LO,  1024, 1024 };
    ts.c[4] = { W_Aq, bs + BOFF_WAQ_HI, bs + BOFF_WAQ_LO, 96, 128 };
    ts.c[5] = { W_Ak, bs + BOFF_WAK_HI, bs + BOFF_WAK_LO, 32, 128 };
    ts.c[6] = { W_Av, bs + BOFF_WAV_HI, bs + BOFF_WAV_LO, 32, 128 };
    tsplit7_kernel<<<dim3(32, 32, 7), dim3(32, 8)>>>(ts);

    // 1) all 6 projections in one pipelined HMMA launch
    GemmCfg6 gp;
    gp.c[0] = { bs + BOFF_QHI, bs + BOFF_QLO, bs + BOFF_WBQ_HI, bs + BOFF_WBQ_LO, sBq, 384, 384 };
    gp.c[1] = { bs + BOFF_KHI, bs + BOFF_KLO, bs + BOFF_WBK_HI, bs + BOFF_WBK_LO, sBk, 128, 128 };
    gp.c[2] = { bs + BOFF_VHI, bs + BOFF_VLO, bs + BOFF_WBV_HI, bs + BOFF_WBV_LO, sBv, 128, 128 };
    gp.c[3] = { bs + BOFF_QHI, bs + BOFF_QLO, bs + BOFF_WAQ_HI, bs + BOFF_WAQ_LO, sAq, 96, 128 };
    gp.c[4] = { bs + BOFF_KHI, bs + BOFF_KLO, bs + BOFF_WAK_HI, bs + BOFF_WAK_LO, sAk, 32, 128 };
    gp.c[5] = { bs + BOFF_VHI, bs + BOFF_VLO, bs + BOFF_WAV_HI, bs + BOFF_WAV_LO, sAv, 32, 128 };
    tc_gemm_kernel<<<dim3(3, MY, 6), 256, GEMSMEM>>>(gp);

    // 2) fused RoPE + contraction (q, k) and fused V contraction+transpose
    {
        int total = NTOK * HEADS * DK;
        contract_rope_kernel<<<(total + 255) / 256, 256>>>(
            sAq, sBq, bs + BOFF_FQHI, bs + BOFF_FQLO, QRANK, 1.0f / (QRANK * DK));
        contract_rope_kernel<<<(total + 255) / 256, 256>>>(
            sAk, sBk, bs + BOFF_FKHI, bs + BOFF_FKLO, RANK, 1.0f / RANK);
        fvt_kernel<<<dim3(SEQ / 32, DK / 32, BH), dim3(32, 8)>>>(
            sAv, sBv, bs + BOFF_FVTHI, bs + BOFF_FVTLO);
    }

    // 3) HMMA causal flash attention (FQ=128)
    flash_mma_kernel<<<dim3(SEQ / 128, BH), 256, FLSMEM>>>(
        bs + BOFF_FQHI, bs + BOFF_FQLO, bs + BOFF_FKHI, bs + BOFF_FKLO,
        bs + BOFF_FVTHI, bs + BOFF_FVTLO, bs + BOFF_OAHI, bs + BOFF_OALO);

    // 4) output projection
    GemmCfg6 go;
    go.c[0] = { bs + BOFF_OAHI, bs + BOFF_OALO, bs + BOFF_WO_HI, bs + BOFF_WO_LO, out, 1024, 1024 };
    go.c[1] = go.c[0]; go.c[2] = go.c[0]; go.c[3] = go.c[0]; go.c[4] = go.c[0]; go.c[5] = go.c[0];
    tc_gemm_kernel<<<dim3(8, MY, 1), 256, GEMSMEM>>>(go);
}

// round 12
// speedup vs baseline: 4.7736x; 1.0195x over previous
#include <cuda_runtime.h>
#include <cuda_bf16.h>
#include <math.h>
#include <stdint.h>

// ---------------------------------------------------------------------------
// T6Attention — round 12 (= round 11 resubmitted after infra failure):
// RoPE table + batched contractions
// B=2, S=2048, D_MODEL=1024, HEADS=16, DK=64, Q_RANK=6, RANK=2
// ---------------------------------------------------------------------------

#define BATCH     2
#define SEQ       2048
#define DMODEL    1024
#define HEADS     16
#define DK        64
#define QRANK     6
#define RANK      2
#define NTOK      (BATCH*SEQ)        // 4096
#define BH        (BATCH*HEADS)      // 32

// fp32 scratch offsets
#define OFF_AQ   0
#define SZ_AQ    (NTOK*HEADS*QRANK)
#define OFF_AK   (OFF_AQ+SZ_AQ)
#define SZ_AK    (NTOK*HEADS*RANK)
#define OFF_AV   (OFF_AK+SZ_AK)
#define SZ_AV    SZ_AK
#define OFF_BQ   (OFF_AV+SZ_AV)
#define SZ_BQ    (NTOK*QRANK*DK)
#define OFF_BK   (OFF_BQ+SZ_BQ)
#define SZ_BK    (NTOK*RANK*DK)
#define OFF_BV   (OFF_BK+SZ_BK)
#define SZ_BV    SZ_BK
#define SCRATCH_TOTAL (OFF_BV+SZ_BV)

__device__ float g_scratch[SCRATCH_TOTAL];
__device__ float2 g_rope[SEQ * 32];

// bf16 scratch offsets (elements)
#define TOKD          (NTOK*DMODEL)
#define BOFF_QHI      0
#define BOFF_QLO      (BOFF_QHI + TOKD)
#define BOFF_KHI      (BOFF_QLO + TOKD)
#define BOFF_KLO      (BOFF_KHI + TOKD)
#define BOFF_VHI      (BOFF_KLO + TOKD)
#define BOFF_VLO      (BOFF_VHI + TOKD)
#define BOFF_OAHI     (BOFF_VLO + TOKD)
#define BOFF_OALO     (BOFF_OAHI + TOKD)
#define BOFF_WBQ_HI   (BOFF_OALO + TOKD)
#define BOFF_WBQ_LO   (BOFF_WBQ_HI + 384*1024)
#define BOFF_WBK_HI   (BOFF_WBQ_LO + 384*1024)
#define BOFF_WBK_LO   (BOFF_WBK_HI + 128*1024)
#define BOFF_WBV_HI   (BOFF_WBK_LO + 128*1024)
#define BOFF_WBV_LO   (BOFF_WBV_HI + 128*1024)
#define BOFF_WO_HI    (BOFF_WBV_LO + 128*1024)
#define BOFF_WO_LO    (BOFF_WO_HI + 1024*1024)
#define BOFF_WAQ_HI   (BOFF_WO_LO + 1024*1024)
#define BOFF_WAQ_LO   (BOFF_WAQ_HI + 128*1024)
#define BOFF_WAK_HI   (BOFF_WAQ_LO + 128*1024)
#define BOFF_WAK_LO   (BOFF_WAK_HI + 128*1024)
#define BOFF_WAV_HI   (BOFF_WAK_LO + 128*1024)
#define BOFF_WAV_LO   (BOFF_WAV_HI + 128*1024)
#define BOFF_FQHI     (BOFF_WAV_LO + 128*1024)
#define BOFF_FQLO     (BOFF_FQHI + TOKD)
#define BOFF_FKHI     (BOFF_FQLO + TOKD)
#define BOFF_FKLO     (BOFF_FKHI + TOKD)
#define BOFF_FVTHI    (BOFF_FKLO + TOKD)
#define BOFF_FVTLO    (BOFF_FVTHI + TOKD)
#define BF_TOTAL      (BOFF_FVTLO + TOKD)

__device__ __nv_bfloat16 g_bf[BF_TOTAL];

// ---------------------------------------------------------------------------
// helpers
// ---------------------------------------------------------------------------
__device__ __forceinline__ void mma16816(float* d,
                                         uint32_t a0, uint32_t a1, uint32_t a2, uint32_t a3,
                                         uint32_t b0, uint32_t b1)
{
    asm volatile(
        "mma.sync.aligned.m16n8k16.row.col.f32.bf16.bf16.f32 "
        "{%0,%1,%2,%3}, {%4,%5,%6,%7}, {%8,%9}, {%0,%1,%2,%3};"
        : "+f"(d[0]), "+f"(d[1]), "+f"(d[2]), "+f"(d[3])
        : "r"(a0), "r"(a1), "r"(a2), "r"(a3), "r"(b0), "r"(b1));
}

__device__ __forceinline__ uint32_t packbf2(float a, float b) {
    __nv_bfloat162 t = __floats2bfloat162_rn(a, b);
    return *reinterpret_cast<uint32_t*>(&t);
}

__device__ __forceinline__ uint32_t smem_u32(const void* p) {
    return (uint32_t)__cvta_generic_to_shared(p);
}

#define CP_ASYNC16(dst_u32, src_ptr) \
    asm volatile("cp.async.cg.shared.global [%0], [%1], 16;" \
        :: "r"(dst_u32), "l"(src_ptr) : "memory")
#define CP_COMMIT() asm volatile("cp.async.commit_group;" ::: "memory")
#define CP_WAIT0()  asm volatile("cp.async.wait_group 0;" ::: "memory")
#define CP_WAIT1()  asm volatile("cp.async.wait_group 1;" ::: "memory")

// ---------------------------------------------------------------------------
// RoPE table: g_rope[s*32+i] = (cos, sin)(s * 10000^(-2i/64))
// ---------------------------------------------------------------------------
__global__ void rope_table_kernel()
{
    int idx = blockIdx.x * blockDim.x + threadIdx.x;
    if (idx >= SEQ * 32) return;
    int s = idx >> 5;
    int i = idx & 31;
    float inv_freq = powf(10000.0f, -(float)(2 * i) / 64.0f);
    float fr = (float)s * inv_freq;
    float sn, cs;
    sincosf(fr, &sn, &cs);
    g_rope[idx] = make_float2(cs, sn);
}

// ---------------------------------------------------------------------------
// batched hi/lo split for q,k,v
// ---------------------------------------------------------------------------
__global__ void split3_kernel(const float* __restrict__ x0, const float* __restrict__ x1,
                              const float* __restrict__ x2,
                              __nv_bfloat16* __restrict__ h0, __nv_bfloat16* __restrict__ l0p,
                              __nv_bfloat16* __restrict__ h1, __nv_bfloat16* __restrict__ l1p,
                              __nv_bfloat16* __restrict__ h2, __nv_bfloat16* __restrict__ l2p,
                              int n)
{
    const float* x = x0; __nv_bfloat16* hi = h0; __nv_bfloat16* lo = l0p;
    if (blockIdx.z == 1) { x = x1; hi = h1; lo = l1p; }
    else if (blockIdx.z == 2) { x = x2; hi = h2; lo = l2p; }
    int i = blockIdx.x * blockDim.x + threadIdx.x;
    if (i >= n) return;
    float v = x[i];
    __nv_bfloat16 h = __float2bfloat16(v);
    hi[i] = h;
    lo[i] = __float2bfloat16(v - __bfloat162float(h));
}

// ---------------------------------------------------------------------------
// batched transpose + split with zero padding: W[1024,N] -> hi/lo [Npad,1024]
// ---------------------------------------------------------------------------
struct TsCfg {
    const float* W;
    __nv_bfloat16* hi;
    __nv_bfloat16* lo;
    int N;
    int Npad;
};
struct TsCfg7 { TsCfg c[7]; };

__global__ void tsplit7_kernel(TsCfg7 p)
{
    TsCfg cfg = p.c[blockIdx.z];
    const int n0 = blockIdx.x * 32, k0 = blockIdx.y * 32;
    if (n0 >= cfg.Npad) return;
    const int tx = threadIdx.x, ty = threadIdx.y;

    if (n0 >= cfg.N) {
#pragma unroll
        for (int i = 0; i < 4; i++) {
            size_t o = (size_t)(n0 + ty + i * 8) * 1024 + k0 + tx;
            cfg.hi[o] = __float2bfloat16(0.f);
            cfg.lo[o] = __float2bfloat16(0.f);
        }
        return;
    }

    __shared__ float t[32][33];
#pragma unroll
    for (int i = 0; i < 4; i++)
        t[ty + i * 8][tx] = cfg.W[(size_t)(k0 + ty + i * 8) * cfg.N + n0 + tx];
    __syncthreads();
#pragma unroll
    for (int i = 0; i < 4; i++) {
        float v = t[tx][ty + i * 8];
        __nv_bfloat16 h = __float2bfloat16(v);
        size_t o = (size_t)(n0 + ty + i * 8) * 1024 + k0 + tx;
        cfg.hi[o] = h;
        cfg.lo[o] = __float2bfloat16(v - __bfloat162float(h));
    }
}

// ---------------------------------------------------------------------------
// HMMA GEMM, cp.async 2-stage pipelined, up to 6 batched configs.
// ---------------------------------------------------------------------------
#define KPAD   72
#define GARR   (128 * KPAD * 2)
#define GSTAGE (4 * GARR)

struct GemmCfg {
    const __nv_bfloat16 *Ahi, *Alo, *Bhi, *Blo;
    float* C;
    int N;
    int Npad;
};
struct GemmCfg6 { GemmCfg c[6]; };

__global__ __launch_bounds__(256) void tc_gemm_kernel(GemmCfg6 p)
{
    GemmCfg cfg = p.c[blockIdx.z];
    const int n0 = blockIdx.x * 128;
    if (n0 >= cfg.Npad) return;

    extern __shared__ char smem[];
    const uint32_t smem_base = smem_u32(smem);

    const int tid = threadIdx.x;
    const int wid = tid >> 5;
    const int lid = tid & 31;
    const int m0 = blockIdx.y * 128;
    const int wm = (wid & 3) * 32;
    const int wn = (wid >> 2) * 64;
    const int gr = lid >> 2;
    const int gc = (lid & 3) * 2;

    const char* pAhi = reinterpret_cast<const char*>(cfg.Ahi);
    const char* pAlo = reinterpret_cast<const char*>(cfg.Alo);
    const char* pBhi = reinterpret_cast<const char*>(cfg.Bhi);
    const char* pBlo = reinterpret_cast<const char*>(cfg.Blo);

    int cr[4], cc[4];
    uint32_t sdst[4];
#pragma unroll
    for (int i = 0; i < 4; i++) {
        int idx = tid + i * 256;
        cr[i] = idx >> 3;
        cc[i] = idx & 7;
        sdst[i] = (uint32_t)(cr[i] * (KPAD * 2) + cc[i] * 16);
    }

    auto issue = [&](int kc, int st) {
        uint32_t s0a = smem_base + st * GSTAGE;
#pragma unroll
        for (int i = 0; i < 4; i++) {
            size_t ga = 2 * ((size_t)(m0 + cr[i]) * 1024 + kc * 64 + cc[i] * 8);
            CP_ASYNC16(s0a + sdst[i],            pAhi + ga);
            CP_ASYNC16(s0a + GARR + sdst[i],     pAlo + ga);
            size_t gb = 2 * ((size_t)(n0 + cr[i]) * 1024 + kc * 64 + cc[i] * 8);
            CP_ASYNC16(s0a + 2 * GARR + sdst[i], pBhi + gb);
            CP_ASYNC16(s0a + 3 * GARR + sdst[i], pBlo + gb);
        }
        CP_COMMIT();
    };

    float acc[2][8][4];
#pragma unroll
    for (int mf = 0; mf < 2; mf++)
#pragma unroll
        for (int nf = 0; nf < 8; nf++)
#pragma unroll
            for (int e = 0; e < 4; e++) acc[mf][nf][e] = 0.f;

    issue(0, 0);

    for (int kc = 0; kc < 16; kc++) {
        const int st = kc & 1;
        if (kc + 1 < 16) { issue(kc + 1, st ^ 1); CP_WAIT1(); }
        else             { CP_WAIT0(); }
        __syncthreads();

        const uint32_t* uAhi = reinterpret_cast<const uint32_t*>(smem + st * GSTAGE);
        const uint32_t* uAlo = reinterpret_cast<const uint32_t*>(smem + st * GSTAGE + GARR);
        const uint32_t* uBhi = reinterpret_cast<const uint32_t*>(smem + st * GSTAGE + 2 * GARR);
        const uint32_t* uBlo = reinterpret_cast<const uint32_t*>(smem + st * GSTAGE + 3 * GARR);

#pragma unroll
        for (int ks = 0; ks < 4; ks++) {
            const int k0 = ks * 16;
            uint32_t ah[2][4], al[2][4];
#pragma unroll
            for (int mf = 0; mf < 2; mf++) {
                int r0 = wm + mf * 16 + gr;
                int base0 = (r0 * KPAD + k0 + gc) >> 1;
                int base1 = ((r0 + 8) * KPAD + k0 + gc) >> 1;
                ah[mf][0] = uAhi[base0];     al[mf][0] = uAlo[base0];
                ah[mf][1] = uAhi[base1];     al[mf][1] = uAlo[base1];
                ah[mf][2] = uAhi[base0 + 4]; al[mf][2] = uAlo[base0 + 4];
                ah[mf][3] = uAhi[base1 + 4]; al[mf][3] = uAlo[base1 + 4];
            }
            uint32_t bhf[8][2], blf[8][2];
#pragma unroll
            for (int nf = 0; nf < 8; nf++) {
                int r = wn + nf * 8 + gr;
                int base = (r * KPAD + k0 + gc) >> 1;
                bhf[nf][0] = uBhi[base];     blf[nf][0] = uBlo[base];
                bhf[nf][1] = uBhi[base + 4]; blf[nf][1] = uBlo[base + 4];
            }
#pragma unroll
            for (int mf = 0; mf < 2; mf++)
#pragma unroll
                for (int nf = 0; nf < 8; nf++) {
                    mma16816(acc[mf][nf], ah[mf][0], ah[mf][1], ah[mf][2], ah[mf][3],
                             bhf[nf][0], bhf[nf][1]);
                    mma16816(acc[mf][nf], ah[mf][0], ah[mf][1], ah[mf][2], ah[mf][3],
                             blf[nf][0], blf[nf][1]);
                    mma16816(acc[mf][nf], al[mf][0], al[mf][1], al[mf][2], al[mf][3],
                             bhf[nf][0], bhf[nf][1]);
                }
        }
        __syncthreads();
    }

#pragma unroll
    for (int mf = 0; mf < 2; mf++) {
        int r0 = m0 + wm + mf * 16 + gr;
        int r1 = r0 + 8;
#pragma unroll
        for (int nf = 0; nf < 8; nf++) {
            int col = n0 + wn + nf * 8 + gc;
            if (col < cfg.N) {
                *reinterpret_cast<float2*>(&cfg.C[(size_t)r0 * cfg.N + col]) =
                    make_float2(acc[mf][nf][0], acc[mf][nf][1]);
                *reinterpret_cast<float2*>(&cfg.C[(size_t)r1 * cfg.N + col]) =
                    make_float2(acc[mf][nf][2], acc[mf][nf][3]);
            }
        }
    }
}

// ---------------------------------------------------------------------------
// fused RoPE + rank contraction for q AND k (z selects), table-driven.
// -> bf16 hi/lo [bh][s][dk]
// ---------------------------------------------------------------------------
__global__ void contract_rope2_kernel(
    const float* __restrict__ Aq, const float* __restrict__ Bq,
    __nv_bfloat16* __restrict__ qhi, __nv_bfloat16* __restrict__ qlo,
    const float* __restrict__ Ak, const float* __restrict__ Bk,
    __nv_bfloat16* __restrict__ khi, __nv_bfloat16* __restrict__ klo)
{
    const float* Am; const float* Bm;
    __nv_bfloat16 *hi, *lo;
    int R; float scale;
    if (blockIdx.z == 0) {
        Am = Aq; Bm = Bq; hi = qhi; lo = qlo; R = QRANK; scale = 1.0f / (QRANK * DK);
    } else {
        Am = Ak; Bm = Bk; hi = khi; lo = klo; R = RANK; scale = 1.0f / RANK;
    }

    int idx = blockIdx.x * blockDim.x + threadIdx.x;
    if (idx >= NTOK * HEADS * DK) return;
    int d = idx & (DK - 1);
    int h = (idx >> 6) & (HEADS - 1);
    int t = idx >> 10;

    int i = d & 31;
    int s = t & (SEQ - 1);
    float2 rt = g_rope[(s << 5) + i];
    float cs = rt.x, sn = rt.y;

    const float* a = Am + (size_t)t * (HEADS * R) + h * R;
    const float* b = Bm + (size_t)t * R * DK;
    float sum = 0.f;
    const bool lohalf = (d < 32);
#pragma unroll 6
    for (int r = 0; r < R; r++) {
        float x1 = b[r * DK + i];
        float x2 = b[r * DK + 32 + i];
        float rv = lohalf ? (x1 * cs + x2 * sn) : (-x1 * sn + x2 * cs);
        sum += a[r] * rv;
    }
    sum *= scale;

    int bb = t >> 11;
    size_t o = (((size_t)(bb * HEADS + h)) * SEQ + s) * DK + d;
    __nv_bfloat16 hv = __float2bfloat16(sum);
    hi[o] = hv;
    lo[o] = __float2bfloat16(sum - __bfloat162float(hv));
}

// ---------------------------------------------------------------------------
// fused V contraction + transpose + split -> V^T hi/lo [bh][dk][S]
// ---------------------------------------------------------------------------
__global__ void fvt_kernel(const float* __restrict__ Am,
                           const float* __restrict__ Bm,
                           __nv_bfloat16* __restrict__ hi,
                           __nv_bfloat16* __restrict__ lo)
{
    __shared__ float vt[32][33];
    const int s0 = blockIdx.x * 32, d0 = blockIdx.y * 32;
    const int bh = blockIdx.z;
    const int b = bh >> 4, h = bh & 15;
    const int tx = threadIdx.x, ty = threadIdx.y;

#pragma unroll
    for (int i = 0; i < 4; i++) {
        int ss = ty + i * 8;
        int t = b * SEQ + s0 + ss;
        const float* a = Am + (size_t)t * (HEADS * RANK) + h * RANK;
        const float* bp = Bm + (size_t)t * RANK * DK + d0 + tx;
        vt[tx][ss] = (a[0] * bp[0] + a[1] * bp[DK]) * 0.5f;
    }
    __syncthreads();

#pragma unroll
    for (int i = 0; i < 4; i++) {
        int dd = ty + i * 8;
        float v = vt[dd][tx];
        __nv_bfloat16 hv = __float2bfloat16(v);
        size_t o = ((size_t)bh * DK + d0 + dd) * SEQ + s0 + tx;
        hi[o] = hv;
        lo[o] = __float2bfloat16(v - __bfloat162float(hv));
    }
}

// ---------------------------------------------------------------------------
// HMMA causal flash attention, FQ=128 (8 warps), cp.async 2-stage.
// ---------------------------------------------------------------------------
#define FPAD   72
#define FARR   (64 * FPAD * 2)
#define FSTAGE (4 * FARR)

__global__ __launch_bounds__(256) void flash_mma_kernel(
    const __nv_bfloat16* __restrict__ Qhi, const __nv_bfloat16* __restrict__ Qlo,
    const __nv_bfloat16* __restrict__ Khi, const __nv_bfloat16* __restrict__ Klo,
    const __nv_bfloat16* __restrict__ Vthi, const __nv_bfloat16* __restrict__ Vtlo,
    __nv_bfloat16* __restrict__ Ohi, __nv_bfloat16* __restrict__ Olo)
{
    extern __shared__ char smem[];
    const uint32_t smem_base = smem_u32(smem);

    const int bh = blockIdx.y;
    const int qb = (gridDim.x - 1) - blockIdx.x;
    const int tid = threadIdx.x;
    const int wid = tid >> 5;
    const int lid = tid & 31;
    const int gr = lid >> 2;
    const int gc = lid & 3;
    const int q0 = qb * 128 + wid * 16;

    int cr[2], cc[2];
    uint32_t sdst[2];
#pragma unroll
    for (int i = 0; i < 2; i++) {
        int idx = tid + i * 256;
        cr[i] = idx >> 3;
        cc[i] = idx & 7;
        sdst[i] = (uint32_t)(cr[i] * (FPAD * 2) + cc[i] * 16);
    }

    uint32_t qfh[4][4], qfl[4][4];
#pragma unroll
    for (int ks = 0; ks < 4; ks++)
#pragma unroll
        for (int i = 0; i < 4; i++) {
            int row = q0 + gr + (i & 1) * 8;
            int col = ks * 16 + gc * 2 + (i >> 1) * 8;
            size_t g = ((size_t)bh * SEQ + row) * DK + col;
            qfh[ks][i] = *reinterpret_cast<const uint32_t*>(&Qhi[g]);
            qfl[ks][i] = *reinterpret_cast<const uint32_t*>(&Qlo[g]);
        }

    float accO[8][4];
#pragma unroll
    for (int nf = 0; nf < 8; nf++)
#pragma unroll
        for (int e = 0; e < 4; e++) accO[nf][e] = 0.f;
    float m0 = -INFINITY, m1 = -INFINITY, l0 = 0.f, l1 = 0.f;

    const char* pKhi = reinterpret_cast<const char*>(Khi);
    const char* pKlo = reinterpret_cast<const char*>(Klo);
    const char* pVhi = reinterpret_cast<const char*>(Vthi);
    const char* pVlo = reinterpret_cast<const char*>(Vtlo);

    auto issue = [&](int kt, int st) {
        uint32_t s0a = smem_base + st * FSTAGE;
#pragma unroll
        for (int i = 0; i < 2; i++) {
            size_t gk = 2 * (((size_t)bh * SEQ + kt * 64 + cr[i]) * DK + cc[i] * 8);
            CP_ASYNC16(s0a + sdst[i],            pKhi + gk);
            CP_ASYNC16(s0a + FARR + sdst[i],     pKlo + gk);
            size_t gv = 2 * (((size_t)bh * DK + cr[i]) * SEQ + kt * 64 + cc[i] * 8);
            CP_ASYNC16(s0a + 2 * FARR + sdst[i], pVhi + gv);
            CP_ASYNC16(s0a + 3 * FARR + sdst[i], pVlo + gv);
        }
        CP_COMMIT();
    };

    const int ktmax = 2 * qb + 1;
    issue(0, 0);

    for (int kt = 0; kt <= ktmax; kt++) {
        const int st = kt & 1;
        if (kt < ktmax) { issue(kt + 1, st ^ 1); CP_WAIT1(); }
        else            { CP_WAIT0(); }
        __syncthreads();

        const int kg0 = kt * 64;
        if (kg0 <= q0 + 15) {
            const uint32_t* uKhi = reinterpret_cast<const uint32_t*>(smem + st * FSTAGE);
            const uint32_t* uKlo = reinterpret_cast<const uint32_t*>(smem + st * FSTAGE + FARR);
            const uint32_t* uVhi = reinterpret_cast<const uint32_t*>(smem + st * FSTAGE + 2 * FARR);
            const uint32_t* uVlo = reinterpret_cast<const uint32_t*>(smem + st * FSTAGE + 3 * FARR);

            float sacc[8][4];
#pragma unroll
            for (int nf = 0; nf < 8; nf++)
#pragma unroll
                for (int e = 0; e < 4; e++) sacc[nf][e] = 0.f;

#pragma unroll
            for (int ks = 0; ks < 4; ks++) {
#pragma unroll
                for (int nf = 0; nf < 8; nf++) {
                    int w = (nf * 8 + gr) * 36 + ks * 8 + gc;
                    uint32_t b0 = uKhi[w], b1 = uKhi[w + 4];
                    uint32_t c0 = uKlo[w], c1 = uKlo[w + 4];
                    mma16816(sacc[nf], qfh[ks][0], qfh[ks][1], qfh[ks][2], qfh[ks][3], b0, b1);
                    mma16816(sacc[nf], qfh[ks][0], qfh[ks][1], qfh[ks][2], qfh[ks][3], c0, c1);
                    mma16816(sacc[nf], qfl[ks][0], qfl[ks][1], qfl[ks][2], qfl[ks][3], b0, b1);
                }
            }

            if (kg0 + 63 > q0) {
#pragma unroll
                for (int nf = 0; nf < 8; nf++) {
                    int key = kg0 + nf * 8 + gc * 2;
                    int r0 = q0 + gr, r1 = r0 + 8;
                    if (key > r0)     sacc[nf][0] = -INFINITY;
                    if (key + 1 > r0) sacc[nf][1] = -INFINITY;
                    if (key > r1)     sacc[nf][2] = -INFINITY;
                    if (key + 1 > r1) sacc[nf][3] = -INFINITY;
                }
            }

            float mx0 = -INFINITY, mx1 = -INFINITY;
#pragma unroll
            for (int nf = 0; nf < 8; nf++) {
                mx0 = fmaxf(mx0, fmaxf(sacc[nf][0], sacc[nf][1]));
                mx1 = fmaxf(mx1, fmaxf(sacc[nf][2], sacc[nf][3]));
            }
            mx0 = fmaxf(mx0, __shfl_xor_sync(0xffffffffu, mx0, 1));
            mx0 = fmaxf(mx0, __shfl_xor_sync(0xffffffffu, mx0, 2));
            mx1 = fmaxf(mx1, __shfl_xor_sync(0xffffffffu, mx1, 1));
            mx1 = fmaxf(mx1, __shfl_xor_sync(0xffffffffu, mx1, 2));

            float mn0 = fmaxf(m0, mx0), mn1 = fmaxf(m1, mx1);
            float f0 = __expf(m0 - mn0), f1 = __expf(m1 - mn1);
            m0 = mn0; m1 = mn1;

            float sum0 = 0.f, sum1 = 0.f;
#pragma unroll
            for (int nf = 0; nf < 8; nf++) {
                sacc[nf][0] = __expf(sacc[nf][0] - mn0);
                sacc[nf][1] = __expf(sacc[nf][1] - mn0);
                sacc[nf][2] = __expf(sacc[nf][2] - mn1);
                sacc[nf][3] = __expf(sacc[nf][3] - mn1);
                sum0 += sacc[nf][0] + sacc[nf][1];
                sum1 += sacc[nf][2] + sacc[nf][3];
            }
            sum0 += __shfl_xor_sync(0xffffffffu, sum0, 1);
            sum0 += __shfl_xor_sync(0xffffffffu, sum0, 2);
            sum1 += __shfl_xor_sync(0xffffffffu, sum1, 1);
            sum1 += __shfl_xor_sync(0xffffffffu, sum1, 2);
            l0 = l0 * f0 + sum0;
            l1 = l1 * f1 + sum1;

#pragma unroll
            for (int nf = 0; nf < 8; nf++) {
                accO[nf][0] *= f0; accO[nf][1] *= f0;
                accO[nf][2] *= f1; accO[nf][3] *= f1;
            }

            uint32_t pah[4][4], pal[4][4];
#pragma unroll
            for (int j = 0; j < 4; j++) {
                float p00 = sacc[2 * j][0],     p01 = sacc[2 * j][1];
                float p02 = sacc[2 * j][2],     p03 = sacc[2 * j][3];
                float p10 = sacc[2 * j + 1][0], p11 = sacc[2 * j + 1][1];
                float p12 = sacc[2 * j + 1][2], p13 = sacc[2 * j + 1][3];
                pah[j][0] = packbf2(p00, p01);
                pah[j][1] = packbf2(p02, p03);
                pah[j][2] = packbf2(p10, p11);
                pah[j][3] = packbf2(p12, p13);
                pal[j][0] = packbf2(p00 - __bfloat162float(__float2bfloat16(p00)),
                                    p01 - __bfloat162float(__float2bfloat16(p01)));
                pal[j][1] = packbf2(p02 - __bfloat162float(__float2bfloat16(p02)),
                                    p03 - __bfloat162float(__float2bfloat16(p03)));
                pal[j][2] = packbf2(p10 - __bfloat162float(__float2bfloat16(p10)),
                                    p11 - __bfloat162float(__float2bfloat16(p11)));
                pal[j][3] = packbf2(p12 - __bfloat162float(__float2bfloat16(p12)),
                                    p13 - __bfloat162float(__float2bfloat16(p13)));
            }

#pragma unroll
            for (int ks = 0; ks < 4; ks++) {
#pragma unroll
                for (int nf = 0; nf < 8; nf++) {
                    int w = (nf * 8 + gr) * 36 + ks * 8 + gc;
                    uint32_t v0 = uVhi[w], v1 = uVhi[w + 4];
                    uint32_t u0 = uVlo[w], u1 = uVlo[w + 4];
                    mma16816(accO[nf], pah[ks][0], pah[ks][1], pah[ks][2], pah[ks][3], v0, v1);
                    mma16816(accO[nf], pah[ks][0], pah[ks][1], pah[ks][2], pah[ks][3], u0, u1);
                    mma16816(accO[nf], pal[ks][0], pal[ks][1], pal[ks][2], pal[ks][3], v0, v1);
                }
            }
        }
        __syncthreads();
    }

    const int b = bh >> 4;
    const int h = bh & 15;
    const float inv0 = 1.0f / l0, inv1 = 1.0f / l1;
    const int r0 = q0 + gr, r1 = r0 + 8;
#pragma unroll
    for (int nf = 0; nf < 8; nf++) {
        int col = h * DK + nf * 8 + gc * 2;
        size_t o0 = ((size_t)(b * SEQ) + r0) * DMODEL + col;
        size_t o1 = ((size_t)(b * SEQ) + r1) * DMODEL + col;
        float v00 = accO[nf][0] * inv0, v01 = accO[nf][1] * inv0;
        float v10 = accO[nf][2] * inv1, v11 = accO[nf][3] * inv1;
        *reinterpret_cast<uint32_t*>(&Ohi[o0]) = packbf2(v00, v01);
        *reinterpret_cast<uint32_t*>(&Ohi[o1]) = packbf2(v10, v11);
        *reinterpret_cast<uint32_t*>(&Olo[o0]) =
            packbf2(v00 - __bfloat162float(__float2bfloat16(v00)),
                    v01 - __bfloat162float(__float2bfloat16(v01)));
        *reinterpret_cast<uint32_t*>(&Olo[o1]) =
            packbf2(v10 - __bfloat162float(__float2bfloat16(v10)),
                    v11 - __bfloat162float(__float2bfloat16(v11)));
    }
}

// ---------------------------------------------------------------------------
extern "C" void kernel_launch(void* const* d_in, const int* in_sizes, int n_in,
                              void* d_out, int out_size)
{
    const float* q    = (const float*)d_in[0];
    const float* k    = (const float*)d_in[1];
    const float* v    = (const float*)d_in[2];
    const float* W_Aq = (const float*)d_in[4];
    const float* W_Ak = (const float*)d_in[5];
    const float* W_Av = (const float*)d_in[6];
    const float* W_Bq = (const float*)d_in[7];
    const float* W_Bk = (const float*)d_in[8];
    const float* W_Bv = (const float*)d_in[9];
    const float* Wo   = (const float*)d_in[10];
    float* out = (float*)d_out;

    float* scratch = nullptr;
    cudaGetSymbolAddress((void**)&scratch, g_scratch);
    __nv_bfloat16* bs = nullptr;
    cudaGetSymbolAddress((void**)&bs, g_bf);

    float* sAq = scratch + OFF_AQ;
    float* sAk = scratch + OFF_AK;
    float* sAv = scratch + OFF_AV;
    float* sBq = scratch + OFF_BQ;
    float* sBk = scratch + OFF_BK;
    float* sBv = scratch + OFF_BV;

    const int GEMSMEM = 2 * GSTAGE;
    const int FLSMEM  = 2 * FSTAGE;
    cudaFuncSetAttribute(tc_gemm_kernel,
                         cudaFuncAttributeMaxDynamicSharedMemorySize, GEMSMEM);
    cudaFuncSetAttribute(flash_mma_kernel,
                         cudaFuncAttributeMaxDynamicSharedMemorySize, FLSMEM);

    const int MY = NTOK / 128;   // 32

    // 0) rope table + input splits + weight transpose-splits
    rope_table_kernel<<<(SEQ * 32 + 255) / 256, 256>>>();
    split3_kernel<<<dim3((TOKD + 255) / 256, 1, 3), 256>>>(
        q, k, v, bs + BOFF_QHI, bs + BOFF_QLO, bs + BOFF_KHI, bs + BOFF_KLO,
        bs + BOFF_VHI, bs + BOFF_VLO, TOKD);

    TsCfg7 ts;
    ts.c[0] = { W_Bq, bs + BOFF_WBQ_HI, bs + BOFF_WBQ_LO, 384, 384 };
    ts.c[1] = { W_Bk, bs + BOFF_WBK_HI, bs + BOFF_WBK_LO, 128, 128 };
    ts.c[2] = { W_Bv, bs + BOFF_WBV_HI, bs + BOFF_WBV_LO, 128, 128 };
    ts.c[3] = { Wo,   bs + BOFF_WO_HI,  bs + BOFF_WO_LO,  1024, 1024 };
    ts.c[4] = { W_Aq, bs + BOFF_WAQ_HI, bs + BOFF_WAQ_LO, 96, 128 };
    ts.c[5] = { W_Ak, bs + BOFF_WAK_HI, bs + BOFF_WAK_LO, 32, 128 };
    ts.c[6] = { W_Av, bs + BOFF_WAV_HI, bs + BOFF_WAV_LO, 32, 128 };
    tsplit7_kernel<<<dim3(32, 32, 7), dim3(32, 8)>>>(ts);

    // 1) all 6 projections in one pipelined HMMA launch
    GemmCfg6 gp;
    gp.c[0] = { bs + BOFF_QHI, bs + BOFF_QLO, bs + BOFF_WBQ_HI, bs + BOFF_WBQ_LO, sBq, 384, 384 };
    gp.c[1] = { bs + BOFF_KHI, bs + BOFF_KLO, bs + BOFF_WBK_HI, bs + BOFF_WBK_LO, sBk, 128, 128 };
    gp.c[2] = { bs + BOFF_VHI, bs + BOFF_VLO, bs + BOFF_WBV_HI, bs + BOFF_WBV_LO, sBv, 128, 128 };
    gp.c[3] = { bs + BOFF_QHI, bs + BOFF_QLO, bs + BOFF_WAQ_HI, bs + BOFF_WAQ_LO, sAq, 96, 128 };
    gp.c[4] = { bs + BOFF_KHI, bs + BOFF_KLO, bs + BOFF_WAK_HI, bs + BOFF_WAK_LO, sAk, 32, 128 };
    gp.c[5] = { bs + BOFF_VHI, bs + BOFF_VLO, bs + BOFF_WAV_HI, bs + BOFF_WAV_LO, sAv, 32, 128 };
    tc_gemm_kernel<<<dim3(3, MY, 6), 256, GEMSMEM>>>(gp);

    // 2) fused RoPE + contraction (q & k, one launch) and V contraction+transpose
    {
        int total = NTOK * HEADS * DK;
        contract_rope2_kernel<<<dim3((total + 255) / 256, 1, 2), 256>>>(
            sAq, sBq, bs + BOFF_FQHI, bs + BOFF_FQLO,
            sAk, sBk, bs + BOFF_FKHI, bs + BOFF_FKLO);
        fvt_kernel<<<dim3(SEQ / 32, DK / 32, BH), dim3(32, 8)>>>(
            sAv, sBv, bs + BOFF_FVTHI, bs + BOFF_FVTLO);
    }

    // 3) HMMA causal flash attention (FQ=128)
    flash_mma_kernel<<<dim3(SEQ / 128, BH), 256, FLSMEM>>>(
        bs + BOFF_FQHI, bs + BOFF_FQLO, bs + BOFF_FKHI, bs + BOFF_FKLO,
        bs + BOFF_FVTHI, bs + BOFF_FVTLO, bs + BOFF_OAHI, bs + BOFF_OALO);

    // 4) output projection
    GemmCfg6 go;
    go.c[0] = { bs + BOFF_OAHI, bs + BOFF_OALO, bs + BOFF_WO_HI, bs + BOFF_WO_LO, out, 1024, 1024 };
    go.c[1] = go.c[0]; go.c[2] = go.c[0]; go.c[3] = go.c[0]; go.c[4] = go.c[0]; go.c[5] = go.c[0];
    tc_gemm_kernel<<<dim3(8, MY, 1), 256, GEMSMEM>>>(go);
}